// round 8
// baseline (speedup 1.0000x reference)
#include <cuda_runtime.h>
#include <cuda_fp16.h>
#include <cstdint>

#define B  1024
#define T  100
#define F  300
#define KP 304     /* F padded to 16-multiple */
#define U  512
#define G  2048    /* 4*U */
#define NC 10
#define EPS 1e-3f

// ---- fp16x3 HMMA GEMM config ----
#define TMC 128
#define TNC 128
#define BKC 16
#define LDAH 24                       /* 16 data + 8 pad halfs -> 48B rows */
#define ROWB (LDAH * 2)               /* 48 B */
#define TERMB (TMC * ROWB)            /* 6144 B per operand term tile */
#define STAGEB (4 * TERMB)            /* A0,A1,B0,B1 = 24576 B */
#define NST 3
#define SMEM_H (NST * STAGEB)         /* 73728 B */

// ---------------- device scratch ---------------------------------------------------
__device__ __align__(16) float g_A0[(size_t)B * T * G];   // raw x@W0 (LN folded into cell0)
__device__ __align__(16) __half g_x0[(size_t)B * T * KP], g_x1[(size_t)B * T * KP];
__device__ __align__(16) __half g_W0a[(size_t)G * KP], g_W0b[(size_t)G * KP];
__device__ __align__(16) __half g_R0a[(size_t)G * U],  g_R0b[(size_t)G * U];
__device__ __align__(16) __half g_W1a[(size_t)G * U],  g_W1b[(size_t)G * U];
__device__ __align__(16) __half g_R1a[(size_t)G * U],  g_R1b[(size_t)G * U];
__device__ __align__(16) float g_z0[B * G], g_z1a[B * G], g_z1b[B * G];
__device__ __align__(16) __half g_h0sa[B * U], g_h0sb[B * U];
__device__ __align__(16) __half g_h0ia[B * U], g_h0ib[B * U];
__device__ __align__(16) __half g_h1sa[B * U], g_h1sb[B * U];
__device__ __align__(16) float g_c0[B * U], g_c1[B * U], g_out[B * U];

__device__ __forceinline__ float sigmf(float x) { return 1.0f / (1.0f + expf(-x)); }

__device__ __forceinline__ void split2(float v, __half& h0, __half& h1)
{
    h0 = __float2half_rn(v);
    h1 = __float2half_rn(v - __half2float(h0));
}

__device__ __forceinline__ void cp16(uint32_t dst, const void* src) {
    asm volatile("cp.async.cg.shared.global [%0], [%1], 16;" :: "r"(dst), "l"(src));
}
__device__ __forceinline__ void cp_commit() { asm volatile("cp.async.commit_group;"); }

#define MMA16(acc, a, b) \
    asm volatile( \
        "mma.sync.aligned.m16n8k16.row.col.f32.f16.f16.f32 " \
        "{%0,%1,%2,%3},{%4,%5,%6,%7},{%8,%9},{%0,%1,%2,%3};" \
        : "+f"((acc)[0]), "+f"((acc)[1]), "+f"((acc)[2]), "+f"((acc)[3]) \
        : "r"((a)[0]), "r"((a)[1]), "r"((a)[2]), "r"((a)[3]), \
          "r"((b)[0]), "r"((b)[1]))

#define LDSM4(r, addr) \
    asm volatile("ldmatrix.sync.aligned.m8n8.x4.shared.b16 {%0,%1,%2,%3}, [%4];" \
        : "=r"((r)[0]), "=r"((r)[1]), "=r"((r)[2]), "=r"((r)[3]) : "r"(addr))

// ---------------- fp16x3 HMMA GEMM --------------------------------------------------
// C[M,N] = A[M,K] @ Bt[N,K]^T, fp32 emulated as 2 fp16 terms, 3 pair-MMAs.
struct ProbH { const __half *A0, *A1, *B0, *B1; float* C; };
struct GArgsH { ProbH p[3]; };

__global__ __launch_bounds__(256, 2) void gemm_f16x3(GArgsH ga, int N, int K)
{
    extern __shared__ char smem[];
    const uint32_t sb0 = (uint32_t)__cvta_generic_to_shared(smem);

    const ProbH pr = ga.p[blockIdx.z];
    const int tid  = threadIdx.x;
    const int lane = tid & 31;
    const int wid  = tid >> 5;
    const int wm   = wid >> 2;       // 0..1  (64 rows)
    const int wn   = wid & 3;        // 0..3  (32 cols)
    const int m0   = blockIdx.y * TMC;
    const int n0   = blockIdx.x * TNC;
    const int grp  = lane >> 2;      // 0..7
    const int tg   = lane & 3;       // 0..3

    // per-lane ldmatrix offsets (x4 tile decomposition)
    const int lm = lane >> 3, lr = lane & 7;
    const uint32_t aoff = (uint32_t)((((lm & 1) * 8) + lr) * ROWB + (lm >> 1) * 16);
    const uint32_t boff = (uint32_t)((((lm >> 1) * 8) + lr) * ROWB + (lm & 1) * 16);

    // copy one BK=16 chunk (A terms + B terms) into stage buffer; 1 chunk/thread/term
    const int crow = tid >> 1;        // 0..127
    const int cgq  = tid & 1;         // 16B granule in 32B row
    auto issue = [&](int buf, int k0) {
        const uint32_t sb = sb0 + (uint32_t)buf * STAGEB;
        const uint32_t doff = (uint32_t)(crow * ROWB + cgq * 16);
        const size_t soff = (size_t)crow * K + k0 + cgq * 8;
        cp16(sb + 0 * TERMB + doff, pr.A0 + (size_t)m0 * K + soff);
        cp16(sb + 1 * TERMB + doff, pr.A1 + (size_t)m0 * K + soff);
        cp16(sb + 2 * TERMB + doff, pr.B0 + (size_t)n0 * K + soff);
        cp16(sb + 3 * TERMB + doff, pr.B1 + (size_t)n0 * K + soff);
        cp_commit();
    };

    float acc[4][4][4];
#pragma unroll
    for (int i = 0; i < 4; i++)
#pragma unroll
        for (int j = 0; j < 4; j++)
#pragma unroll
            for (int k = 0; k < 4; k++) acc[i][j][k] = 0.f;

    const int NIT = K / BKC;
    issue(0, 0);
    issue(1, BKC);

    int st = 0;          // buffer of current compute stage
    int st2 = 2;         // buffer for stage it+2
    for (int it = 0; it < NIT; ++it) {
        if (it + 1 < NIT) asm volatile("cp.async.wait_group 1;");
        else              asm volatile("cp.async.wait_group 0;");
        __syncthreads();
        if (it + 2 < NIT) {
            issue(st2, (it + 2) * BKC);
            st2 = (st2 == 2) ? 0 : st2 + 1;
        }

        const uint32_t sst = sb0 + (uint32_t)st * STAGEB;
        st = (st == 2) ? 0 : st + 1;
        const uint32_t aBase = sst + (uint32_t)((wm * 64) * ROWB) + aoff;
        const uint32_t bBase = sst + 2 * TERMB + (uint32_t)((wn * 32) * ROWB) + boff;

        uint32_t a0f[4][4], a1f[4][4], b0t[2][4], b1t[2][4];
#pragma unroll
        for (int im = 0; im < 4; im++) {
            const uint32_t ab = aBase + (uint32_t)(im * 16 * ROWB);
            LDSM4(a0f[im], ab);
            LDSM4(a1f[im], ab + TERMB);
        }
#pragma unroll
        for (int jp = 0; jp < 2; jp++) {
            const uint32_t bb = bBase + (uint32_t)(jp * 16 * ROWB);
            LDSM4(b0t[jp], bb);
            LDSM4(b1t[jp], bb + TERMB);
        }
#pragma unroll
        for (int im = 0; im < 4; im++)
#pragma unroll
            for (int jn = 0; jn < 4; jn++) {
                const uint32_t* b0p = &b0t[jn >> 1][(jn & 1) * 2];
                const uint32_t* b1p = &b1t[jn >> 1][(jn & 1) * 2];
                MMA16(acc[im][jn], a1f[im], b0p);   // lo*hi
                MMA16(acc[im][jn], a0f[im], b1p);   // hi*lo
                MMA16(acc[im][jn], a0f[im], b0p);   // hi*hi
            }
    }

    // epilogue
#pragma unroll
    for (int im = 0; im < 4; im++) {
        const int row0 = m0 + wm * 64 + im * 16 + grp;
#pragma unroll
        for (int jn = 0; jn < 4; jn++) {
            const int col = n0 + wn * 32 + jn * 8 + tg * 2;
            *(float2*)(pr.C + (size_t)row0 * N + col)       = make_float2(acc[im][jn][0], acc[im][jn][1]);
            *(float2*)(pr.C + (size_t)(row0 + 8) * N + col) = make_float2(acc[im][jn][2], acc[im][jn][3]);
        }
    }
}

// ---------------- one-time prep ------------------------------------------------------
__global__ void wsplit2_t(const float* __restrict__ W, __half* __restrict__ t0,
                          __half* __restrict__ t1, int Kd, int N, int Ksrc)
{
    const size_t i = (size_t)blockIdx.x * 256 + threadIdx.x;
    if (i < (size_t)N * Kd) {
        const int n = (int)(i / Kd), k = (int)(i % Kd);
        const float v = (k < Ksrc) ? W[(size_t)k * N + n] : 0.f;
        __half h0, h1;
        split2(v, h0, h1);
        t0[i] = h0; t1[i] = h1;
    }
}

__global__ void xsplit2(const float* __restrict__ x, __half* __restrict__ t0,
                        __half* __restrict__ t1)
{
    const size_t i = (size_t)blockIdx.x * 256 + threadIdx.x;
    if (i < (size_t)B * T * KP) {
        const size_t r = i / KP;
        const int c = (int)(i % KP);
        const float v = (c < F) ? x[r * F + c] : 0.f;
        __half h0, h1;
        split2(v, h0, h1);
        t0[i] = h0; t1[i] = h1;
    }
}

__global__ void init_kernel()
{
    const size_t i = (size_t)blockIdx.x * 256 + threadIdx.x;
    if (i < (size_t)B * G) g_z0[i] = 0.f;
    if (i < (size_t)B * U) {
        const __half z = __float2half_rn(0.f);
        g_h0sa[i] = z; g_h0sb[i] = z;
        g_h1sa[i] = z; g_h1sb[i] = z;
        g_c0[i] = 0.f; g_c1[i] = 0.f; g_out[i] = 0.f;
    }
}

// ---------------- unified cell body ----------------------------------------------------
// z = LN(za)*gza + bza  +  LN(zb)*gzb + bzb  +  bias ; gates; c' = LN_c; h' = sig(o)tanh(c')
// layer==0: za=g_z0 row, zb=g_A0 row(t); writes h0i always, h0s/c0 masked.
// layer==1: za=g_z1b row, zb=g_z1a row;  writes h1s/c1/out masked.
__device__ void cell_body(int layer, int b, int t,
                          const float* __restrict__ gza, const float* __restrict__ bza,
                          const float* __restrict__ gzb, const float* __restrict__ bzb,
                          const float* __restrict__ sg,  const float* __restrict__ sb,
                          const float* __restrict__ bias, const int* __restrict__ mask)
{
    const int tid = threadIdx.x, lane = tid & 31, w = tid >> 5;
    const float* za = (layer == 0) ? (g_z0 + (size_t)b * G)
                                   : (g_z1b + (size_t)b * G);
    const float* zb = (layer == 0) ? (g_A0 + (size_t)((size_t)b * T + t) * G)
                                   : (g_z1a + (size_t)b * G);
    __shared__ float sh1[4][8];
    __shared__ float bc1[4];

    float va[2][4], vb[2][4];
    float s1 = 0.f, p1 = 0.f, s2 = 0.f, p2 = 0.f;
#pragma unroll
    for (int q = 0; q < 2; q++) {
        const int u = tid + q * 256;
#pragma unroll
        for (int gg = 0; gg < 4; gg++) {
            const float x1 = za[gg * U + u];
            const float x2 = zb[gg * U + u];
            va[q][gg] = x1; vb[q][gg] = x2;
            s1 += x1; p1 += x1 * x1; s2 += x2; p2 += x2 * x2;
        }
    }
#pragma unroll
    for (int o = 16; o > 0; o >>= 1) {
        s1 += __shfl_xor_sync(0xffffffffu, s1, o);
        p1 += __shfl_xor_sync(0xffffffffu, p1, o);
        s2 += __shfl_xor_sync(0xffffffffu, s2, o);
        p2 += __shfl_xor_sync(0xffffffffu, p2, o);
    }
    if (lane == 0) { sh1[0][w] = s1; sh1[1][w] = p1; sh1[2][w] = s2; sh1[3][w] = p2; }
    __syncthreads();
    if (tid == 0) {
        float S1 = 0.f, P1 = 0.f, S2 = 0.f, P2 = 0.f;
#pragma unroll
        for (int i = 0; i < 8; i++) { S1 += sh1[0][i]; P1 += sh1[1][i]; S2 += sh1[2][i]; P2 += sh1[3][i]; }
        const float m1 = S1 / (float)G, m2 = S2 / (float)G;
        bc1[0] = m1; bc1[1] = rsqrtf(P1 / (float)G - m1 * m1 + EPS);
        bc1[2] = m2; bc1[3] = rsqrtf(P2 / (float)G - m2 * m2 + EPS);
    }
    __syncthreads();
    const float m1 = bc1[0], r1 = bc1[1], m2 = bc1[2], r2 = bc1[3];

    float* cold = (layer == 0) ? g_c0 : g_c1;
    float cn[2], zo[2];
    float s3 = 0.f, p3 = 0.f;
#pragma unroll
    for (int q = 0; q < 2; q++) {
        const int u = tid + q * 256;
        float zg4[4];
#pragma unroll
        for (int gg = 0; gg < 4; gg++) {
            const int j = gg * U + u;
            zg4[gg] = (va[q][gg] - m1) * r1 * gza[j] + bza[j]
                    + (vb[q][gg] - m2) * r2 * gzb[j] + bzb[j] + bias[j];
        }
        const float c = cold[(size_t)b * U + u];
        const float v = sigmf(zg4[1]) * c + sigmf(zg4[0]) * tanhf(zg4[2]);
        cn[q] = v; zo[q] = zg4[3]; s3 += v; p3 += v * v;
    }
#pragma unroll
    for (int o = 16; o > 0; o >>= 1) {
        s3 += __shfl_xor_sync(0xffffffffu, s3, o);
        p3 += __shfl_xor_sync(0xffffffffu, p3, o);
    }
    __syncthreads();
    if (lane == 0) { sh1[0][w] = s3; sh1[1][w] = p3; }
    __syncthreads();
    if (tid == 0) {
        float S = 0.f, P = 0.f;
#pragma unroll
        for (int i = 0; i < 8; i++) { S += sh1[0][i]; P += sh1[1][i]; }
        const float m = S / (float)U;
        bc1[0] = m;
        bc1[1] = rsqrtf(P / (float)U - m * m + EPS);
    }
    __syncthreads();
    const float mc = bc1[0], rc = bc1[1];
    const int msk = mask[b * T + t];
#pragma unroll
    for (int q = 0; q < 2; q++) {
        const int u = tid + q * 256;
        const float cl = (cn[q] - mc) * rc * sg[u] + sb[u];
        const float hn = sigmf(zo[q]) * tanhf(cl);
        __half h0, h1;
        split2(hn, h0, h1);
        if (layer == 0) {
            g_h0ia[(size_t)b * U + u] = h0;
            g_h0ib[(size_t)b * U + u] = h1;
            if (msk) {
                g_h0sa[(size_t)b * U + u] = h0;
                g_h0sb[(size_t)b * U + u] = h1;
                g_c0  [(size_t)b * U + u] = cl;
            }
        } else {
            if (msk) {
                g_h1sa[(size_t)b * U + u] = h0;
                g_h1sb[(size_t)b * U + u] = h1;
                g_c1 [(size_t)b * U + u] = cl;
                g_out[(size_t)b * U + u] = hn;
            }
        }
    }
}

__global__ __launch_bounds__(256) void cell0_kernel(
    const float* rg, const float* rb, const float* kg, const float* kb,
    const float* sg, const float* sb, const float* bias,
    const int* mask, int t)
{
    cell_body(0, blockIdx.x, t, rg, rb, kg, kb, sg, sb, bias, mask);
}

__global__ __launch_bounds__(256) void cell1_kernel(
    const float* kg, const float* kb, const float* rg, const float* rb,
    const float* sg, const float* sb, const float* bias,
    const int* mask, int t)
{
    cell_body(1, blockIdx.x, t, rg, rb, kg, kb, sg, sb, bias, mask);
}

// fused: blocks [0,B) do cell1(t); blocks [B,2B) do cell0(t+1)
__global__ __launch_bounds__(256) void fused_cell_kernel(
    const float* rg0, const float* rb0, const float* kg0, const float* kb0,
    const float* sg0, const float* sb0, const float* b0,
    const float* kg1, const float* kb1, const float* rg1, const float* rb1,
    const float* sg1, const float* sb1, const float* b1,
    const int* mask, int t)
{
    if (blockIdx.x < B)
        cell_body(1, blockIdx.x, t, rg1, rb1, kg1, kb1, sg1, sb1, b1, mask);
    else
        cell_body(0, blockIdx.x - B, t + 1, rg0, rb0, kg0, kb0, sg0, sb0, b0, mask);
}

// ---------------- dense + softmax -----------------------------------------------------
__global__ __launch_bounds__(256) void dense_kernel(const float* __restrict__ Wd,
                                                    const float* __restrict__ bd,
                                                    float* __restrict__ out)
{
    const int b = blockIdx.x, tid = threadIdx.x, lane = tid & 31, w = tid >> 5;
    float p[NC];
#pragma unroll
    for (int c = 0; c < NC; c++) p[c] = 0.f;
    for (int u = tid; u < U; u += 256) {
        const float h = g_out[(size_t)b * U + u];
#pragma unroll
        for (int c = 0; c < NC; c++) p[c] += h * Wd[u * NC + c];
    }
    __shared__ float sh[NC][8];
#pragma unroll
    for (int c = 0; c < NC; c++) {
        float v = p[c];
#pragma unroll
        for (int o = 16; o > 0; o >>= 1) v += __shfl_xor_sync(0xffffffffu, v, o);
        if (lane == 0) sh[c][w] = v;
    }
    __syncthreads();
    if (tid == 0) {
        float lg[NC];
        float mx = -1e30f;
#pragma unroll
        for (int c = 0; c < NC; c++) {
            float l = bd[c];
#pragma unroll
            for (int i = 0; i < 8; i++) l += sh[c][i];
            lg[c] = l;
            mx = fmaxf(mx, l);
        }
        float sum = 0.f;
#pragma unroll
        for (int c = 0; c < NC; c++) { lg[c] = expf(lg[c] - mx); sum += lg[c]; }
        const float inv = 1.f / sum;
#pragma unroll
        for (int c = 0; c < NC; c++) out[b * NC + c] = lg[c] * inv;
    }
}

// ---------------- launch ---------------------------------------------------------------
extern "C" void kernel_launch(void* const* d_in, const int* in_sizes, int n_in,
                              void* d_out, int out_size)
{
    const float* x    = (const float*)d_in[0];
    const int*   mask = (const int*)  d_in[1];
    const float* W0   = (const float*)d_in[2];
    const float* R0   = (const float*)d_in[3];
    const float* b0   = (const float*)d_in[4];
    const float* kg0  = (const float*)d_in[5];
    const float* kb0  = (const float*)d_in[6];
    const float* rg0  = (const float*)d_in[7];
    const float* rb0  = (const float*)d_in[8];
    const float* sg0  = (const float*)d_in[9];
    const float* sb0  = (const float*)d_in[10];
    const float* W1   = (const float*)d_in[11];
    const float* R1   = (const float*)d_in[12];
    const float* b1   = (const float*)d_in[13];
    const float* kg1  = (const float*)d_in[14];
    const float* kb1  = (const float*)d_in[15];
    const float* rg1  = (const float*)d_in[16];
    const float* rb1  = (const float*)d_in[17];
    const float* sg1  = (const float*)d_in[18];
    const float* sb1  = (const float*)d_in[19];
    const float* Wd   = (const float*)d_in[20];
    const float* bd   = (const float*)d_in[21];
    float* out = (float*)d_out;

    float *A0p, *z0p, *z1ap, *z1bp;
    __half *x0, *x1, *W0a, *W0b, *R0a, *R0b, *W1a, *W1b, *R1a, *R1b;
    __half *h0sa, *h0sb, *h0ia, *h0ib, *h1sa, *h1sb;
    cudaGetSymbolAddress((void**)&A0p,  g_A0);
    cudaGetSymbolAddress((void**)&z0p,  g_z0);
    cudaGetSymbolAddress((void**)&z1ap, g_z1a);
    cudaGetSymbolAddress((void**)&z1bp, g_z1b);
    cudaGetSymbolAddress((void**)&x0,   g_x0);
    cudaGetSymbolAddress((void**)&x1,   g_x1);
    cudaGetSymbolAddress((void**)&W0a,  g_W0a);
    cudaGetSymbolAddress((void**)&W0b,  g_W0b);
    cudaGetSymbolAddress((void**)&R0a,  g_R0a);
    cudaGetSymbolAddress((void**)&R0b,  g_R0b);
    cudaGetSymbolAddress((void**)&W1a,  g_W1a);
    cudaGetSymbolAddress((void**)&W1b,  g_W1b);
    cudaGetSymbolAddress((void**)&R1a,  g_R1a);
    cudaGetSymbolAddress((void**)&R1b,  g_R1b);
    cudaGetSymbolAddress((void**)&h0sa, g_h0sa);
    cudaGetSymbolAddress((void**)&h0sb, g_h0sb);
    cudaGetSymbolAddress((void**)&h0ia, g_h0ia);
    cudaGetSymbolAddress((void**)&h0ib, g_h0ib);
    cudaGetSymbolAddress((void**)&h1sa, g_h1sa);
    cudaGetSymbolAddress((void**)&h1sb, g_h1sb);

    cudaFuncSetAttribute(gemm_f16x3, cudaFuncAttributeMaxDynamicSharedMemorySize, SMEM_H);

    // one-time prep
    const size_t nW0 = (size_t)G * KP;
    const size_t nRW = (size_t)G * U;
    const size_t nXT = (size_t)B * T * KP;
    init_kernel<<<(B * G + 255) / 256, 256>>>();
    wsplit2_t<<<(unsigned)((nW0 + 255) / 256), 256>>>(W0, W0a, W0b, KP, G, F);
    wsplit2_t<<<(unsigned)((nRW + 255) / 256), 256>>>(R0, R0a, R0b, U, G, U);
    wsplit2_t<<<(unsigned)((nRW + 255) / 256), 256>>>(W1, W1a, W1b, U, G, U);
    wsplit2_t<<<(unsigned)((nRW + 255) / 256), 256>>>(R1, R1a, R1b, U, G, U);
    xsplit2<<<(unsigned)((nXT + 255) / 256), 256>>>(x, x0, x1);

    // precompute A0 = x @ W0 (raw; LN folded into cell0)
    {
        GArgsH a = {};
        a.p[0] = { x0, x1, W0a, W0b, A0p };
        gemm_f16x3<<<dim3(G / TNC, (B * T) / TMC, 1), 256, SMEM_H>>>(a, G, KP);
    }

    // t = 0 prolog (z0(0) == 0)
    cell0_kernel<<<B, 256>>>(rg0, rb0, kg0, kb0, sg0, sb0, b0, mask, 0);

    for (int t = 0; t < T - 1; t++) {
        GArgsH a = {};
        a.p[0] = { h0ia, h0ib, W1a, W1b, z1ap };   // z1a(t)
        a.p[1] = { h1sa, h1sb, R1a, R1b, z1bp };   // z1b(t)
        a.p[2] = { h0sa, h0sb, R0a, R0b, z0p  };   // z0(t+1)
        gemm_f16x3<<<dim3(G / TNC, B / TMC, 3), 256, SMEM_H>>>(a, G, U);
        fused_cell_kernel<<<2 * B, 256>>>(rg0, rb0, kg0, kb0, sg0, sb0, b0,
                                          kg1, kb1, rg1, rb1, sg1, sb1, b1, mask, t);
    }

    // t = T-1 epilog
    {
        GArgsH a = {};
        a.p[0] = { h0ia, h0ib, W1a, W1b, z1ap };
        a.p[1] = { h1sa, h1sb, R1a, R1b, z1bp };
        gemm_f16x3<<<dim3(G / TNC, B / TMC, 2), 256, SMEM_H>>>(a, G, U);
        cell1_kernel<<<B, 256>>>(kg1, kb1, rg1, rb1, sg1, sb1, b1, mask, T - 1);
    }

    dense_kernel<<<B, 256>>>(Wd, bd, out);
}

// round 9
// speedup vs baseline: 1.1167x; 1.1167x over previous
#include <cuda_runtime.h>
#include <cuda_fp16.h>
#include <cstdint>

#define B  1024
#define T  100
#define F  300
#define KP 320     /* F padded to 32-multiple */
#define U  512
#define G  2048    /* 4*U */
#define NC 10
#define EPS 1e-3f

// ---- fp16x3 HMMA GEMM config (round-7 proven config) ----
#define TMC 128
#define TNC 128
#define BKC 32
#define LDAH 40                       /* padded fp16 stride (conflict-free) */
#define ROWB (LDAH * 2)               /* 80 B row stride */
#define TERMB (TMC * ROWB)            /* 10240 B per term tile */
#define STAGEB (4 * TERMB)            /* A0,A1,B0,B1 = 40960 B */
#define SMEM_H (2 * STAGEB)           /* 81920 B */

// ---------------- device scratch ---------------------------------------------------
__device__ __align__(16) float g_A0[(size_t)B * T * G];   // raw x@W0 (LN folded into cell0)
__device__ __align__(16) __half g_x0[(size_t)B * T * KP], g_x1[(size_t)B * T * KP];
__device__ __align__(16) __half g_W0a[(size_t)G * KP], g_W0b[(size_t)G * KP];
__device__ __align__(16) __half g_R0a[(size_t)G * U],  g_R0b[(size_t)G * U];
__device__ __align__(16) __half g_W1a[(size_t)G * U],  g_W1b[(size_t)G * U];
__device__ __align__(16) __half g_R1a[(size_t)G * U],  g_R1b[(size_t)G * U];
__device__ __align__(16) float g_z0[B * G], g_z1a[B * G], g_z1b[B * G];
__device__ __align__(16) __half g_h0sa[B * U], g_h0sb[B * U];
__device__ __align__(16) __half g_h0ia[B * U], g_h0ib[B * U];
__device__ __align__(16) __half g_h1sa[B * U], g_h1sb[B * U];
__device__ __align__(16) float g_c0[B * U], g_c1[B * U], g_out[B * U];

__device__ __forceinline__ float sigmf(float x) { return 1.0f / (1.0f + expf(-x)); }

__device__ __forceinline__ void split2(float v, __half& h0, __half& h1)
{
    h0 = __float2half_rn(v);
    h1 = __float2half_rn(v - __half2float(h0));
}

__device__ __forceinline__ void cp16(uint32_t dst, const void* src) {
    asm volatile("cp.async.cg.shared.global [%0], [%1], 16;" :: "r"(dst), "l"(src));
}
__device__ __forceinline__ void cp_commit() { asm volatile("cp.async.commit_group;"); }
__device__ __forceinline__ void cp_wait0()  { asm volatile("cp.async.wait_group 0;"); }

#define MMA16(acc, a, b) \
    asm volatile( \
        "mma.sync.aligned.m16n8k16.row.col.f32.f16.f16.f32 " \
        "{%0,%1,%2,%3},{%4,%5,%6,%7},{%8,%9},{%0,%1,%2,%3};" \
        : "+f"((acc)[0]), "+f"((acc)[1]), "+f"((acc)[2]), "+f"((acc)[3]) \
        : "r"((a)[0]), "r"((a)[1]), "r"((a)[2]), "r"((a)[3]), \
          "r"((b)[0]), "r"((b)[1]))

#define LDSM4(r, addr) \
    asm volatile("ldmatrix.sync.aligned.m8n8.x4.shared.b16 {%0,%1,%2,%3}, [%4];" \
        : "=r"((r)[0]), "=r"((r)[1]), "=r"((r)[2]), "=r"((r)[3]) : "r"(addr))

// ---------------- fp16x3 HMMA GEMM --------------------------------------------------
// C[M,N] = A[M,K] @ Bt[N,K]^T, fp32 emulated as 2 fp16 terms, 3 pair-MMAs.
struct ProbH { const __half *A0, *A1, *B0, *B1; float* C; };
struct GArgsH { ProbH p[3]; };

__global__ __launch_bounds__(256, 2) void gemm_f16x3(GArgsH ga, int N, int K)
{
    extern __shared__ char smem[];
    const uint32_t sb0 = (uint32_t)__cvta_generic_to_shared(smem);

    const ProbH pr = ga.p[blockIdx.z];
    const int tid  = threadIdx.x;
    const int lane = tid & 31;
    const int wid  = tid >> 5;
    const int wm   = wid >> 2;       // 0..1  (64 rows)
    const int wn   = wid & 3;        // 0..3  (32 cols)
    const int m0   = blockIdx.y * TMC;
    const int n0   = blockIdx.x * TNC;
    const int grp  = lane >> 2;      // 0..7
    const int tg   = lane & 3;       // 0..3

    // per-lane ldmatrix offsets (x4 tile decomposition)
    const int lm = lane >> 3, lr = lane & 7;
    const uint32_t aoff = (uint32_t)((((lm & 1) * 8) + lr) * ROWB + (lm >> 1) * 16);
    const uint32_t boff = (uint32_t)((((lm >> 1) * 8) + lr) * ROWB + (lm & 1) * 16);

    // copy one BK=32 chunk (A terms + B terms) into stage buffer
    auto issue = [&](int stage, int k0) {
        const uint32_t sb = sb0 + (uint32_t)stage * STAGEB;
        const __half* srcs[4] = { pr.A0, pr.A1, pr.B0, pr.B1 };
        const int r0s[4] = { m0, m0, n0, n0 };
#pragma unroll
        for (int t = 0; t < 4; t++) {
#pragma unroll
            for (int i = 0; i < 2; i++) {
                const int idx = tid + i * 256;        // 0..511
                const int r = idx >> 2, gq = idx & 3; // row, 16B granule
                cp16(sb + (uint32_t)(t * TERMB + r * ROWB + gq * 16),
                     srcs[t] + (size_t)(r0s[t] + r) * K + k0 + gq * 8);
            }
        }
        cp_commit();
    };

    float acc[4][4][4];
#pragma unroll
    for (int i = 0; i < 4; i++)
#pragma unroll
        for (int j = 0; j < 4; j++)
#pragma unroll
            for (int k = 0; k < 4; k++) acc[i][j][k] = 0.f;

    const int NIT = K / BKC;
    issue(0, 0);

    for (int it = 0; it < NIT; ++it) {
        cp_wait0();
        __syncthreads();
        if (it + 1 < NIT) issue((it + 1) & 1, (it + 1) * BKC);

        const uint32_t sst = sb0 + (uint32_t)(it & 1) * STAGEB;
        const uint32_t aBase = sst + (uint32_t)((wm * 64) * ROWB) + aoff;
        const uint32_t bBase = sst + 2 * TERMB + (uint32_t)((wn * 32) * ROWB) + boff;

#pragma unroll
        for (int kk = 0; kk < 2; kk++) {
            uint32_t a0f[4][4], a1f[4][4], b0t[2][4], b1t[2][4];
#pragma unroll
            for (int im = 0; im < 4; im++) {
                const uint32_t ab = aBase + (uint32_t)(im * 16 * ROWB + kk * 32);
                LDSM4(a0f[im], ab);
                LDSM4(a1f[im], ab + TERMB);
            }
#pragma unroll
            for (int jp = 0; jp < 2; jp++) {
                const uint32_t bb = bBase + (uint32_t)(jp * 16 * ROWB + kk * 32);
                LDSM4(b0t[jp], bb);
                LDSM4(b1t[jp], bb + TERMB);
            }
#pragma unroll
            for (int im = 0; im < 4; im++)
#pragma unroll
                for (int jn = 0; jn < 4; jn++) {
                    const uint32_t* b0p = &b0t[jn >> 1][(jn & 1) * 2];
                    const uint32_t* b1p = &b1t[jn >> 1][(jn & 1) * 2];
                    MMA16(acc[im][jn], a1f[im], b0p);   // lo*hi
                    MMA16(acc[im][jn], a0f[im], b1p);   // hi*lo
                    MMA16(acc[im][jn], a0f[im], b0p);   // hi*hi
                }
        }
    }

    // epilogue
#pragma unroll
    for (int im = 0; im < 4; im++) {
        const int row0 = m0 + wm * 64 + im * 16 + grp;
#pragma unroll
        for (int jn = 0; jn < 4; jn++) {
            const int col = n0 + wn * 32 + jn * 8 + tg * 2;
            *(float2*)(pr.C + (size_t)row0 * N + col)       = make_float2(acc[im][jn][0], acc[im][jn][1]);
            *(float2*)(pr.C + (size_t)(row0 + 8) * N + col) = make_float2(acc[im][jn][2], acc[im][jn][3]);
        }
    }
}

// ---------------- one-time prep ------------------------------------------------------
__global__ void wsplit2_t(const float* __restrict__ W, __half* __restrict__ t0,
                          __half* __restrict__ t1, int Kd, int N, int Ksrc)
{
    const size_t i = (size_t)blockIdx.x * 256 + threadIdx.x;
    if (i < (size_t)N * Kd) {
        const int n = (int)(i / Kd), k = (int)(i % Kd);
        const float v = (k < Ksrc) ? W[(size_t)k * N + n] : 0.f;
        __half h0, h1;
        split2(v, h0, h1);
        t0[i] = h0; t1[i] = h1;
    }
}

__global__ void xsplit2(const float* __restrict__ x, __half* __restrict__ t0,
                        __half* __restrict__ t1)
{
    const size_t i = (size_t)blockIdx.x * 256 + threadIdx.x;
    if (i < (size_t)B * T * KP) {
        const size_t r = i / KP;
        const int c = (int)(i % KP);
        const float v = (c < F) ? x[r * F + c] : 0.f;
        __half h0, h1;
        split2(v, h0, h1);
        t0[i] = h0; t1[i] = h1;
    }
}

__global__ void init_kernel()
{
    const size_t i = (size_t)blockIdx.x * 256 + threadIdx.x;
    if (i < (size_t)B * G) g_z0[i] = 0.f;
    if (i < (size_t)B * U) {
        const __half z = __float2half_rn(0.f);
        g_h0sa[i] = z; g_h0sb[i] = z;
        g_h1sa[i] = z; g_h1sb[i] = z;
        g_c0[i] = 0.f; g_c1[i] = 0.f; g_out[i] = 0.f;
    }
}

// ---------------- unified cell body ----------------------------------------------------
// z = LN(za)*gza + bza  +  LN(zb)*gzb + bzb  +  bias ; gates; c' = LN_c; h' = sig(o)tanh(c')
// layer==0: za=g_z0 row, zb=g_A0 row(t); writes h0i always, h0s/c0 masked.
// layer==1: za=g_z1b row, zb=g_z1a row;  writes h1s/c1/out masked.
__device__ void cell_body(int layer, int b, int t,
                          const float* __restrict__ gza, const float* __restrict__ bza,
                          const float* __restrict__ gzb, const float* __restrict__ bzb,
                          const float* __restrict__ sg,  const float* __restrict__ sb,
                          const float* __restrict__ bias, const int* __restrict__ mask)
{
    const int tid = threadIdx.x, lane = tid & 31, w = tid >> 5;
    const float* za = (layer == 0) ? (g_z0 + (size_t)b * G)
                                   : (g_z1b + (size_t)b * G);
    const float* zb = (layer == 0) ? (g_A0 + (size_t)((size_t)b * T + t) * G)
                                   : (g_z1a + (size_t)b * G);
    __shared__ float sh1[4][8];
    __shared__ float bc1[4];

    float va[2][4], vb[2][4];
    float s1 = 0.f, p1 = 0.f, s2 = 0.f, p2 = 0.f;
#pragma unroll
    for (int q = 0; q < 2; q++) {
        const int u = tid + q * 256;
#pragma unroll
        for (int gg = 0; gg < 4; gg++) {
            const float x1 = za[gg * U + u];
            const float x2 = zb[gg * U + u];
            va[q][gg] = x1; vb[q][gg] = x2;
            s1 += x1; p1 += x1 * x1; s2 += x2; p2 += x2 * x2;
        }
    }
#pragma unroll
    for (int o = 16; o > 0; o >>= 1) {
        s1 += __shfl_xor_sync(0xffffffffu, s1, o);
        p1 += __shfl_xor_sync(0xffffffffu, p1, o);
        s2 += __shfl_xor_sync(0xffffffffu, s2, o);
        p2 += __shfl_xor_sync(0xffffffffu, p2, o);
    }
    if (lane == 0) { sh1[0][w] = s1; sh1[1][w] = p1; sh1[2][w] = s2; sh1[3][w] = p2; }
    __syncthreads();
    if (tid == 0) {
        float S1 = 0.f, P1 = 0.f, S2 = 0.f, P2 = 0.f;
#pragma unroll
        for (int i = 0; i < 8; i++) { S1 += sh1[0][i]; P1 += sh1[1][i]; S2 += sh1[2][i]; P2 += sh1[3][i]; }
        const float m1 = S1 / (float)G, m2 = S2 / (float)G;
        bc1[0] = m1; bc1[1] = rsqrtf(P1 / (float)G - m1 * m1 + EPS);
        bc1[2] = m2; bc1[3] = rsqrtf(P2 / (float)G - m2 * m2 + EPS);
    }
    __syncthreads();
    const float m1 = bc1[0], r1 = bc1[1], m2 = bc1[2], r2 = bc1[3];

    float* cold = (layer == 0) ? g_c0 : g_c1;
    float cn[2], zo[2];
    float s3 = 0.f, p3 = 0.f;
#pragma unroll
    for (int q = 0; q < 2; q++) {
        const int u = tid + q * 256;
        float zg4[4];
#pragma unroll
        for (int gg = 0; gg < 4; gg++) {
            const int j = gg * U + u;
            zg4[gg] = (va[q][gg] - m1) * r1 * gza[j] + bza[j]
                    + (vb[q][gg] - m2) * r2 * gzb[j] + bzb[j] + bias[j];
        }
        const float c = cold[(size_t)b * U + u];
        const float v = sigmf(zg4[1]) * c + sigmf(zg4[0]) * tanhf(zg4[2]);
        cn[q] = v; zo[q] = zg4[3]; s3 += v; p3 += v * v;
    }
#pragma unroll
    for (int o = 16; o > 0; o >>= 1) {
        s3 += __shfl_xor_sync(0xffffffffu, s3, o);
        p3 += __shfl_xor_sync(0xffffffffu, p3, o);
    }
    __syncthreads();
    if (lane == 0) { sh1[0][w] = s3; sh1[1][w] = p3; }
    __syncthreads();
    if (tid == 0) {
        float S = 0.f, P = 0.f;
#pragma unroll
        for (int i = 0; i < 8; i++) { S += sh1[0][i]; P += sh1[1][i]; }
        const float m = S / (float)U;
        bc1[0] = m;
        bc1[1] = rsqrtf(P / (float)U - m * m + EPS);
    }
    __syncthreads();
    const float mc = bc1[0], rc = bc1[1];
    const int msk = mask[b * T + t];
#pragma unroll
    for (int q = 0; q < 2; q++) {
        const int u = tid + q * 256;
        const float cl = (cn[q] - mc) * rc * sg[u] + sb[u];
        const float hn = sigmf(zo[q]) * tanhf(cl);
        __half h0, h1;
        split2(hn, h0, h1);
        if (layer == 0) {
            g_h0ia[(size_t)b * U + u] = h0;
            g_h0ib[(size_t)b * U + u] = h1;
            if (msk) {
                g_h0sa[(size_t)b * U + u] = h0;
                g_h0sb[(size_t)b * U + u] = h1;
                g_c0  [(size_t)b * U + u] = cl;
            }
        } else {
            if (msk) {
                g_h1sa[(size_t)b * U + u] = h0;
                g_h1sb[(size_t)b * U + u] = h1;
                g_c1 [(size_t)b * U + u] = cl;
                g_out[(size_t)b * U + u] = hn;
            }
        }
    }
}

__global__ __launch_bounds__(256) void cell0_kernel(
    const float* rg, const float* rb, const float* kg, const float* kb,
    const float* sg, const float* sb, const float* bias,
    const int* mask, int t)
{
    cell_body(0, blockIdx.x, t, rg, rb, kg, kb, sg, sb, bias, mask);
}

__global__ __launch_bounds__(256) void cell1_kernel(
    const float* kg, const float* kb, const float* rg, const float* rb,
    const float* sg, const float* sb, const float* bias,
    const int* mask, int t)
{
    cell_body(1, blockIdx.x, t, rg, rb, kg, kb, sg, sb, bias, mask);
}

// fused: blocks [0,B) do cell1(t); blocks [B,2B) do cell0(t+1)
__global__ __launch_bounds__(256) void fused_cell_kernel(
    const float* rg0, const float* rb0, const float* kg0, const float* kb0,
    const float* sg0, const float* sb0, const float* b0,
    const float* kg1, const float* kb1, const float* rg1, const float* rb1,
    const float* sg1, const float* sb1, const float* b1,
    const int* mask, int t)
{
    if (blockIdx.x < B)
        cell_body(1, blockIdx.x, t, rg1, rb1, kg1, kb1, sg1, sb1, b1, mask);
    else
        cell_body(0, blockIdx.x - B, t + 1, rg0, rb0, kg0, kb0, sg0, sb0, b0, mask);
}

// ---------------- dense + softmax -----------------------------------------------------
__global__ __launch_bounds__(256) void dense_kernel(const float* __restrict__ Wd,
                                                    const float* __restrict__ bd,
                                                    float* __restrict__ out)
{
    const int b = blockIdx.x, tid = threadIdx.x, lane = tid & 31, w = tid >> 5;
    float p[NC];
#pragma unroll
    for (int c = 0; c < NC; c++) p[c] = 0.f;
    for (int u = tid; u < U; u += 256) {
        const float h = g_out[(size_t)b * U + u];
#pragma unroll
        for (int c = 0; c < NC; c++) p[c] += h * Wd[u * NC + c];
    }
    __shared__ float sh[NC][8];
#pragma unroll
    for (int c = 0; c < NC; c++) {
        float v = p[c];
#pragma unroll
        for (int o = 16; o > 0; o >>= 1) v += __shfl_xor_sync(0xffffffffu, v, o);
        if (lane == 0) sh[c][w] = v;
    }
    __syncthreads();
    if (tid == 0) {
        float lg[NC];
        float mx = -1e30f;
#pragma unroll
        for (int c = 0; c < NC; c++) {
            float l = bd[c];
#pragma unroll
            for (int i = 0; i < 8; i++) l += sh[c][i];
            lg[c] = l;
            mx = fmaxf(mx, l);
        }
        float sum = 0.f;
#pragma unroll
        for (int c = 0; c < NC; c++) { lg[c] = expf(lg[c] - mx); sum += lg[c]; }
        const float inv = 1.f / sum;
#pragma unroll
        for (int c = 0; c < NC; c++) out[b * NC + c] = lg[c] * inv;
    }
}

// ---------------- launch ---------------------------------------------------------------
extern "C" void kernel_launch(void* const* d_in, const int* in_sizes, int n_in,
                              void* d_out, int out_size)
{
    const float* x    = (const float*)d_in[0];
    const int*   mask = (const int*)  d_in[1];
    const float* W0   = (const float*)d_in[2];
    const float* R0   = (const float*)d_in[3];
    const float* b0   = (const float*)d_in[4];
    const float* kg0  = (const float*)d_in[5];
    const float* kb0  = (const float*)d_in[6];
    const float* rg0  = (const float*)d_in[7];
    const float* rb0  = (const float*)d_in[8];
    const float* sg0  = (const float*)d_in[9];
    const float* sb0  = (const float*)d_in[10];
    const float* W1   = (const float*)d_in[11];
    const float* R1   = (const float*)d_in[12];
    const float* b1   = (const float*)d_in[13];
    const float* kg1  = (const float*)d_in[14];
    const float* kb1  = (const float*)d_in[15];
    const float* rg1  = (const float*)d_in[16];
    const float* rb1  = (const float*)d_in[17];
    const float* sg1  = (const float*)d_in[18];
    const float* sb1  = (const float*)d_in[19];
    const float* Wd   = (const float*)d_in[20];
    const float* bd   = (const float*)d_in[21];
    float* out = (float*)d_out;

    float *A0p, *z0p, *z1ap, *z1bp;
    __half *x0, *x1, *W0a, *W0b, *R0a, *R0b, *W1a, *W1b, *R1a, *R1b;
    __half *h0sa, *h0sb, *h0ia, *h0ib, *h1sa, *h1sb;
    cudaGetSymbolAddress((void**)&A0p,  g_A0);
    cudaGetSymbolAddress((void**)&z0p,  g_z0);
    cudaGetSymbolAddress((void**)&z1ap, g_z1a);
    cudaGetSymbolAddress((void**)&z1bp, g_z1b);
    cudaGetSymbolAddress((void**)&x0,   g_x0);
    cudaGetSymbolAddress((void**)&x1,   g_x1);
    cudaGetSymbolAddress((void**)&W0a,  g_W0a);
    cudaGetSymbolAddress((void**)&W0b,  g_W0b);
    cudaGetSymbolAddress((void**)&R0a,  g_R0a);
    cudaGetSymbolAddress((void**)&R0b,  g_R0b);
    cudaGetSymbolAddress((void**)&W1a,  g_W1a);
    cudaGetSymbolAddress((void**)&W1b,  g_W1b);
    cudaGetSymbolAddress((void**)&R1a,  g_R1a);
    cudaGetSymbolAddress((void**)&R1b,  g_R1b);
    cudaGetSymbolAddress((void**)&h0sa, g_h0sa);
    cudaGetSymbolAddress((void**)&h0sb, g_h0sb);
    cudaGetSymbolAddress((void**)&h0ia, g_h0ia);
    cudaGetSymbolAddress((void**)&h0ib, g_h0ib);
    cudaGetSymbolAddress((void**)&h1sa, g_h1sa);
    cudaGetSymbolAddress((void**)&h1sb, g_h1sb);

    cudaFuncSetAttribute(gemm_f16x3, cudaFuncAttributeMaxDynamicSharedMemorySize, SMEM_H);

    // one-time prep
    const size_t nW0 = (size_t)G * KP;
    const size_t nRW = (size_t)G * U;
    const size_t nXT = (size_t)B * T * KP;
    init_kernel<<<(B * G + 255) / 256, 256>>>();
    wsplit2_t<<<(unsigned)((nW0 + 255) / 256), 256>>>(W0, W0a, W0b, KP, G, F);
    wsplit2_t<<<(unsigned)((nRW + 255) / 256), 256>>>(R0, R0a, R0b, U, G, U);
    wsplit2_t<<<(unsigned)((nRW + 255) / 256), 256>>>(W1, W1a, W1b, U, G, U);
    wsplit2_t<<<(unsigned)((nRW + 255) / 256), 256>>>(R1, R1a, R1b, U, G, U);
    xsplit2<<<(unsigned)((nXT + 255) / 256), 256>>>(x, x0, x1);

    // precompute A0 = x @ W0 (raw; LN folded into cell0)
    {
        GArgsH a = {};
        a.p[0] = { x0, x1, W0a, W0b, A0p };
        gemm_f16x3<<<dim3(G / TNC, (B * T) / TMC, 1), 256, SMEM_H>>>(a, G, KP);
    }

    // t = 0 prolog (z0(0) == 0)
    cell0_kernel<<<B, 256>>>(rg0, rb0, kg0, kb0, sg0, sb0, b0, mask, 0);

    for (int t = 0; t < T - 1; t++) {
        GArgsH a = {};
        a.p[0] = { h0ia, h0ib, W1a, W1b, z1ap };   // z1a(t)
        a.p[1] = { h1sa, h1sb, R1a, R1b, z1bp };   // z1b(t)
        a.p[2] = { h0sa, h0sb, R0a, R0b, z0p  };   // z0(t+1)
        gemm_f16x3<<<dim3(G / TNC, B / TMC, 3), 256, SMEM_H>>>(a, G, U);
        fused_cell_kernel<<<2 * B, 256>>>(rg0, rb0, kg0, kb0, sg0, sb0, b0,
                                          kg1, kb1, rg1, rb1, sg1, sb1, b1, mask, t);
    }

    // t = T-1 epilog
    {
        GArgsH a = {};
        a.p[0] = { h0ia, h0ib, W1a, W1b, z1ap };
        a.p[1] = { h1sa, h1sb, R1a, R1b, z1bp };
        gemm_f16x3<<<dim3(G / TNC, B / TMC, 2), 256, SMEM_H>>>(a, G, U);
        cell1_kernel<<<B, 256>>>(kg1, kb1, rg1, rb1, sg1, sb1, b1, mask, T - 1);
    }

    dense_kernel<<<B, 256>>>(Wd, bd, out);
}

// round 10
// speedup vs baseline: 1.4829x; 1.3279x over previous
#include <cuda_runtime.h>
#include <cuda_fp16.h>
#include <cstdint>

#define B  1024
#define T  100
#define F  300
#define KP 320     /* F padded to 32-multiple */
#define U  512
#define G  2048    /* 4*U */
#define NC 10
#define EPS 1e-3f

// ---- fp16x3 HMMA GEMM config (proven round-7 config) ----
#define TMC 128
#define TNC 128
#define BKC 32
#define LDAH 40                       /* padded fp16 stride (conflict-free) */
#define ROWB (LDAH * 2)               /* 80 B row stride */
#define TERMB (TMC * ROWB)            /* 10240 B per term tile */
#define STAGEB (4 * TERMB)            /* A0,A1,B0,B1 = 40960 B */
#define SMEM_H (2 * STAGEB)           /* 81920 B */

// ---------------- device scratch ---------------------------------------------------
// all batch-indexed arrays live in PERMUTED row order (sorted by len desc)
__device__ __align__(16) float g_A0[(size_t)B * T * G];   // raw x@W0, permuted rows
__device__ __align__(16) __half g_x0[(size_t)B * T * KP], g_x1[(size_t)B * T * KP];
__device__ __align__(16) __half g_W0a[(size_t)G * KP], g_W0b[(size_t)G * KP];
__device__ __align__(16) __half g_R0a[(size_t)G * U],  g_R0b[(size_t)G * U];
__device__ __align__(16) __half g_W1a[(size_t)G * U],  g_W1b[(size_t)G * U];
__device__ __align__(16) __half g_R1a[(size_t)G * U],  g_R1b[(size_t)G * U];
__device__ __align__(16) float g_z0[B * G], g_z1a[B * G], g_z1b[B * G];
__device__ __align__(16) __half g_h0sa[B * U], g_h0sb[B * U];
__device__ __align__(16) __half g_h0ia[B * U], g_h0ib[B * U];
__device__ __align__(16) __half g_h1sa[B * U], g_h1sb[B * U];
__device__ __align__(16) float g_c0[B * U], g_c1[B * U], g_out[B * U];
__device__ int g_perm[B];      // permuted p -> original b
__device__ int g_plen[B];      // len of permuted row p (descending)
__device__ int g_cnt[T + 1];   // cnt[t] = #rows with len > t (active at step t)

__device__ __forceinline__ float sigmf(float x) { return 1.0f / (1.0f + expf(-x)); }

__device__ __forceinline__ void split2(float v, __half& h0, __half& h1)
{
    h0 = __float2half_rn(v);
    h1 = __float2half_rn(v - __half2float(h0));
}

__device__ __forceinline__ void cp16(uint32_t dst, const void* src) {
    asm volatile("cp.async.cg.shared.global [%0], [%1], 16;" :: "r"(dst), "l"(src));
}
__device__ __forceinline__ void cp_commit() { asm volatile("cp.async.commit_group;"); }
__device__ __forceinline__ void cp_wait0()  { asm volatile("cp.async.wait_group 0;"); }

#define MMA16(acc, a, b) \
    asm volatile( \
        "mma.sync.aligned.m16n8k16.row.col.f32.f16.f16.f32 " \
        "{%0,%1,%2,%3},{%4,%5,%6,%7},{%8,%9},{%0,%1,%2,%3};" \
        : "+f"((acc)[0]), "+f"((acc)[1]), "+f"((acc)[2]), "+f"((acc)[3]) \
        : "r"((a)[0]), "r"((a)[1]), "r"((a)[2]), "r"((a)[3]), \
          "r"((b)[0]), "r"((b)[1]))

#define LDSM4(r, addr) \
    asm volatile("ldmatrix.sync.aligned.m8n8.x4.shared.b16 {%0,%1,%2,%3}, [%4];" \
        : "=r"((r)[0]), "=r"((r)[1]), "=r"((r)[2]), "=r"((r)[3]) : "r"(addr))

// ---------------- fp16x3 HMMA GEMM --------------------------------------------------
// C[M,N] = A[M,K] @ Bt[N,K]^T, fp32 emulated as 2 fp16 terms, 3 pair-MMAs.
// actp: if non-null, CTAs whose row tile starts at/above *actp exit immediately
// (monotone mask: stale rows of C are exactly correct).
struct ProbH { const __half *A0, *A1, *B0, *B1; float* C; };
struct GArgsH { ProbH p[3]; };

__global__ __launch_bounds__(256, 2) void gemm_f16x3(GArgsH ga, int N, int K,
                                                     const int* actp)
{
    const int m0 = blockIdx.y * TMC;
    if (actp != nullptr && m0 >= *actp) return;

    extern __shared__ char smem[];
    const uint32_t sb0 = (uint32_t)__cvta_generic_to_shared(smem);

    const ProbH pr = ga.p[blockIdx.z];
    const int tid  = threadIdx.x;
    const int lane = tid & 31;
    const int wid  = tid >> 5;
    const int wm   = wid >> 2;       // 0..1  (64 rows)
    const int wn   = wid & 3;        // 0..3  (32 cols)
    const int n0   = blockIdx.x * TNC;
    const int grp  = lane >> 2;      // 0..7
    const int tg   = lane & 3;       // 0..3

    // per-lane ldmatrix offsets (x4 tile decomposition)
    const int lm = lane >> 3, lr = lane & 7;
    const uint32_t aoff = (uint32_t)((((lm & 1) * 8) + lr) * ROWB + (lm >> 1) * 16);
    const uint32_t boff = (uint32_t)((((lm >> 1) * 8) + lr) * ROWB + (lm & 1) * 16);

    // copy one BK=32 chunk (A terms + B terms) into stage buffer
    auto issue = [&](int stage, int k0) {
        const uint32_t sb = sb0 + (uint32_t)stage * STAGEB;
        const __half* srcs[4] = { pr.A0, pr.A1, pr.B0, pr.B1 };
        const int r0s[4] = { m0, m0, n0, n0 };
#pragma unroll
        for (int t = 0; t < 4; t++) {
#pragma unroll
            for (int i = 0; i < 2; i++) {
                const int idx = tid + i * 256;        // 0..511
                const int r = idx >> 2, gq = idx & 3; // row, 16B granule
                cp16(sb + (uint32_t)(t * TERMB + r * ROWB + gq * 16),
                     srcs[t] + (size_t)(r0s[t] + r) * K + k0 + gq * 8);
            }
        }
        cp_commit();
    };

    float acc[4][4][4];
#pragma unroll
    for (int i = 0; i < 4; i++)
#pragma unroll
        for (int j = 0; j < 4; j++)
#pragma unroll
            for (int k = 0; k < 4; k++) acc[i][j][k] = 0.f;

    const int NIT = K / BKC;
    issue(0, 0);

    for (int it = 0; it < NIT; ++it) {
        cp_wait0();
        __syncthreads();
        if (it + 1 < NIT) issue((it + 1) & 1, (it + 1) * BKC);

        const uint32_t sst = sb0 + (uint32_t)(it & 1) * STAGEB;
        const uint32_t aBase = sst + (uint32_t)((wm * 64) * ROWB) + aoff;
        const uint32_t bBase = sst + 2 * TERMB + (uint32_t)((wn * 32) * ROWB) + boff;

#pragma unroll
        for (int kk = 0; kk < 2; kk++) {
            uint32_t a0f[4][4], a1f[4][4], b0t[2][4], b1t[2][4];
#pragma unroll
            for (int im = 0; im < 4; im++) {
                const uint32_t ab = aBase + (uint32_t)(im * 16 * ROWB + kk * 32);
                LDSM4(a0f[im], ab);
                LDSM4(a1f[im], ab + TERMB);
            }
#pragma unroll
            for (int jp = 0; jp < 2; jp++) {
                const uint32_t bb = bBase + (uint32_t)(jp * 16 * ROWB + kk * 32);
                LDSM4(b0t[jp], bb);
                LDSM4(b1t[jp], bb + TERMB);
            }
#pragma unroll
            for (int im = 0; im < 4; im++)
#pragma unroll
                for (int jn = 0; jn < 4; jn++) {
                    const uint32_t* b0p = &b0t[jn >> 1][(jn & 1) * 2];
                    const uint32_t* b1p = &b1t[jn >> 1][(jn & 1) * 2];
                    MMA16(acc[im][jn], a1f[im], b0p);   // lo*hi
                    MMA16(acc[im][jn], a0f[im], b1p);   // hi*lo
                    MMA16(acc[im][jn], a0f[im], b0p);   // hi*hi
                }
        }
    }

    // epilogue
#pragma unroll
    for (int im = 0; im < 4; im++) {
        const int row0 = m0 + wm * 64 + im * 16 + grp;
#pragma unroll
        for (int jn = 0; jn < 4; jn++) {
            const int col = n0 + wn * 32 + jn * 8 + tg * 2;
            *(float2*)(pr.C + (size_t)row0 * N + col)       = make_float2(acc[im][jn][0], acc[im][jn][1]);
            *(float2*)(pr.C + (size_t)(row0 + 8) * N + col) = make_float2(acc[im][jn][2], acc[im][jn][3]);
        }
    }
}

// ---------------- one-time prep ------------------------------------------------------
// rank-sort rows by len desc (deterministic; tie-break original index asc)
__global__ void sort_kernel(const int* __restrict__ mask)
{
    __shared__ int len[B];
    const int b = threadIdx.x;
    int l = 0;
    for (int t = 0; t < T; t++) l += mask[b * T + t];
    len[b] = l;
    __syncthreads();
    int rank = 0;
    for (int j = 0; j < B; j++) {
        const int lj = len[j];
        rank += (lj > l) || (lj == l && j < b);
    }
    g_perm[rank] = b;
    g_plen[rank] = l;
}

__global__ void cnt_kernel()
{
    const int t = threadIdx.x;
    if (t <= T) {
        int c = 0;
        for (int p = 0; p < B; p++) c += (g_plen[p] > t);
        g_cnt[t] = c;
    }
}

__global__ void wsplit2_t(const float* __restrict__ W, __half* __restrict__ t0,
                          __half* __restrict__ t1, int Kd, int N, int Ksrc)
{
    const size_t i = (size_t)blockIdx.x * 256 + threadIdx.x;
    if (i < (size_t)N * Kd) {
        const int n = (int)(i / Kd), k = (int)(i % Kd);
        const float v = (k < Ksrc) ? W[(size_t)k * N + n] : 0.f;
        __half h0, h1;
        split2(v, h0, h1);
        t0[i] = h0; t1[i] = h1;
    }
}

// x rows gathered through perm: permuted row p <- original row g_perm[p]
__global__ void xsplit2(const float* __restrict__ x, __half* __restrict__ t0,
                        __half* __restrict__ t1)
{
    const size_t i = (size_t)blockIdx.x * 256 + threadIdx.x;
    if (i < (size_t)B * T * KP) {
        const size_t r = i / KP;       // permuted (p, t) flat index
        const int c = (int)(i % KP);
        const int p = (int)(r / T), t = (int)(r % T);
        const float v = (c < F) ? x[((size_t)g_perm[p] * T + t) * F + c] : 0.f;
        __half h0, h1;
        split2(v, h0, h1);
        t0[i] = h0; t1[i] = h1;
    }
}

__global__ void init_kernel()
{
    const size_t i = (size_t)blockIdx.x * 256 + threadIdx.x;
    if (i < (size_t)B * G) g_z0[i] = 0.f;
    if (i < (size_t)B * U) {
        const __half z = __float2half_rn(0.f);
        g_h0sa[i] = z; g_h0sb[i] = z;
        g_h1sa[i] = z; g_h1sb[i] = z;
        g_c0[i] = 0.f; g_c1[i] = 0.f; g_out[i] = 0.f;
    }
}

// ---------------- unified cell body ----------------------------------------------------
// layer==0: za=g_z0 row, zb=g_A0 row(t);  layer==1: za=g_z1b row, zb=g_z1a row.
// Early-exits when row inactive (t >= plen[b]); surviving blocks write unconditionally.
__device__ void cell_body(int layer, int b, int t,
                          const float* __restrict__ gza, const float* __restrict__ bza,
                          const float* __restrict__ gzb, const float* __restrict__ bzb,
                          const float* __restrict__ sg,  const float* __restrict__ sb,
                          const float* __restrict__ bias)
{
    if (t >= g_plen[b]) return;   // uniform per block (b = blockIdx-derived)

    const int tid = threadIdx.x, lane = tid & 31, w = tid >> 5;
    const float* za = (layer == 0) ? (g_z0 + (size_t)b * G)
                                   : (g_z1b + (size_t)b * G);
    const float* zb = (layer == 0) ? (g_A0 + (size_t)((size_t)b * T + t) * G)
                                   : (g_z1a + (size_t)b * G);
    __shared__ float sh1[4][8];
    __shared__ float bc1[4];

    float va[2][4], vb[2][4];
    float s1 = 0.f, p1 = 0.f, s2 = 0.f, p2 = 0.f;
#pragma unroll
    for (int q = 0; q < 2; q++) {
        const int u = tid + q * 256;
#pragma unroll
        for (int gg = 0; gg < 4; gg++) {
            const float x1 = za[gg * U + u];
            const float x2 = zb[gg * U + u];
            va[q][gg] = x1; vb[q][gg] = x2;
            s1 += x1; p1 += x1 * x1; s2 += x2; p2 += x2 * x2;
        }
    }
#pragma unroll
    for (int o = 16; o > 0; o >>= 1) {
        s1 += __shfl_xor_sync(0xffffffffu, s1, o);
        p1 += __shfl_xor_sync(0xffffffffu, p1, o);
        s2 += __shfl_xor_sync(0xffffffffu, s2, o);
        p2 += __shfl_xor_sync(0xffffffffu, p2, o);
    }
    if (lane == 0) { sh1[0][w] = s1; sh1[1][w] = p1; sh1[2][w] = s2; sh1[3][w] = p2; }
    __syncthreads();
    if (tid == 0) {
        float S1 = 0.f, P1 = 0.f, S2 = 0.f, P2 = 0.f;
#pragma unroll
        for (int i = 0; i < 8; i++) { S1 += sh1[0][i]; P1 += sh1[1][i]; S2 += sh1[2][i]; P2 += sh1[3][i]; }
        const float m1 = S1 / (float)G, m2 = S2 / (float)G;
        bc1[0] = m1; bc1[1] = rsqrtf(P1 / (float)G - m1 * m1 + EPS);
        bc1[2] = m2; bc1[3] = rsqrtf(P2 / (float)G - m2 * m2 + EPS);
    }
    __syncthreads();
    const float m1 = bc1[0], r1 = bc1[1], m2 = bc1[2], r2 = bc1[3];

    float* cold = (layer == 0) ? g_c0 : g_c1;
    float cn[2], zo[2];
    float s3 = 0.f, p3 = 0.f;
#pragma unroll
    for (int q = 0; q < 2; q++) {
        const int u = tid + q * 256;
        float zg4[4];
#pragma unroll
        for (int gg = 0; gg < 4; gg++) {
            const int j = gg * U + u;
            zg4[gg] = (va[q][gg] - m1) * r1 * gza[j] + bza[j]
                    + (vb[q][gg] - m2) * r2 * gzb[j] + bzb[j] + bias[j];
        }
        const float c = cold[(size_t)b * U + u];
        const float v = sigmf(zg4[1]) * c + sigmf(zg4[0]) * tanhf(zg4[2]);
        cn[q] = v; zo[q] = zg4[3]; s3 += v; p3 += v * v;
    }
#pragma unroll
    for (int o = 16; o > 0; o >>= 1) {
        s3 += __shfl_xor_sync(0xffffffffu, s3, o);
        p3 += __shfl_xor_sync(0xffffffffu, p3, o);
    }
    __syncthreads();
    if (lane == 0) { sh1[0][w] = s3; sh1[1][w] = p3; }
    __syncthreads();
    if (tid == 0) {
        float S = 0.f, P = 0.f;
#pragma unroll
        for (int i = 0; i < 8; i++) { S += sh1[0][i]; P += sh1[1][i]; }
        const float m = S / (float)U;
        bc1[0] = m;
        bc1[1] = rsqrtf(P / (float)U - m * m + EPS);
    }
    __syncthreads();
    const float mc = bc1[0], rc = bc1[1];
#pragma unroll
    for (int q = 0; q < 2; q++) {
        const int u = tid + q * 256;
        const float cl = (cn[q] - mc) * rc * sg[u] + sb[u];
        const float hn = sigmf(zo[q]) * tanhf(cl);
        __half h0, h1;
        split2(hn, h0, h1);
        if (layer == 0) {
            // active row (mask==1): state and input-to-layer1 both update
            g_h0ia[(size_t)b * U + u] = h0;
            g_h0ib[(size_t)b * U + u] = h1;
            g_h0sa[(size_t)b * U + u] = h0;
            g_h0sb[(size_t)b * U + u] = h1;
            g_c0  [(size_t)b * U + u] = cl;
        } else {
            g_h1sa[(size_t)b * U + u] = h0;
            g_h1sb[(size_t)b * U + u] = h1;
            g_c1 [(size_t)b * U + u] = cl;
            g_out[(size_t)b * U + u] = hn;
        }
    }
}

__global__ __launch_bounds__(256) void cell0_kernel(
    const float* rg, const float* rb, const float* kg, const float* kb,
    const float* sg, const float* sb, const float* bias, int t)
{
    cell_body(0, blockIdx.x, t, rg, rb, kg, kb, sg, sb, bias);
}

__global__ __launch_bounds__(256) void cell1_kernel(
    const float* kg, const float* kb, const float* rg, const float* rb,
    const float* sg, const float* sb, const float* bias, int t)
{
    cell_body(1, blockIdx.x, t, rg, rb, kg, kb, sg, sb, bias);
}

// fused: blocks [0,B) do cell1(t); blocks [B,2B) do cell0(t+1)
__global__ __launch_bounds__(256) void fused_cell_kernel(
    const float* rg0, const float* rb0, const float* kg0, const float* kb0,
    const float* sg0, const float* sb0, const float* b0,
    const float* kg1, const float* kb1, const float* rg1, const float* rb1,
    const float* sg1, const float* sb1, const float* b1, int t)
{
    if (blockIdx.x < B)
        cell_body(1, blockIdx.x, t, rg1, rb1, kg1, kb1, sg1, sb1, b1);
    else
        cell_body(0, blockIdx.x - B, t + 1, rg0, rb0, kg0, kb0, sg0, sb0, b0);
}

// ---------------- dense + softmax (scatter through perm) ------------------------------
__global__ __launch_bounds__(256) void dense_kernel(const float* __restrict__ Wd,
                                                    const float* __restrict__ bd,
                                                    float* __restrict__ out)
{
    const int b = blockIdx.x, tid = threadIdx.x, lane = tid & 31, w = tid >> 5;
    float p[NC];
#pragma unroll
    for (int c = 0; c < NC; c++) p[c] = 0.f;
    for (int u = tid; u < U; u += 256) {
        const float h = g_out[(size_t)b * U + u];
#pragma unroll
        for (int c = 0; c < NC; c++) p[c] += h * Wd[u * NC + c];
    }
    __shared__ float sh[NC][8];
#pragma unroll
    for (int c = 0; c < NC; c++) {
        float v = p[c];
#pragma unroll
        for (int o = 16; o > 0; o >>= 1) v += __shfl_xor_sync(0xffffffffu, v, o);
        if (lane == 0) sh[c][w] = v;
    }
    __syncthreads();
    if (tid == 0) {
        const int ob = g_perm[b];
        float lg[NC];
        float mx = -1e30f;
#pragma unroll
        for (int c = 0; c < NC; c++) {
            float l = bd[c];
#pragma unroll
            for (int i = 0; i < 8; i++) l += sh[c][i];
            lg[c] = l;
            mx = fmaxf(mx, l);
        }
        float sum = 0.f;
#pragma unroll
        for (int c = 0; c < NC; c++) { lg[c] = expf(lg[c] - mx); sum += lg[c]; }
        const float inv = 1.f / sum;
#pragma unroll
        for (int c = 0; c < NC; c++) out[ob * NC + c] = lg[c] * inv;
    }
}

// ---------------- launch ---------------------------------------------------------------
extern "C" void kernel_launch(void* const* d_in, const int* in_sizes, int n_in,
                              void* d_out, int out_size)
{
    const float* x    = (const float*)d_in[0];
    const int*   mask = (const int*)  d_in[1];
    const float* W0   = (const float*)d_in[2];
    const float* R0   = (const float*)d_in[3];
    const float* b0   = (const float*)d_in[4];
    const float* kg0  = (const float*)d_in[5];
    const float* kb0  = (const float*)d_in[6];
    const float* rg0  = (const float*)d_in[7];
    const float* rb0  = (const float*)d_in[8];
    const float* sg0  = (const float*)d_in[9];
    const float* sb0  = (const float*)d_in[10];
    const float* W1   = (const float*)d_in[11];
    const float* R1   = (const float*)d_in[12];
    const float* b1   = (const float*)d_in[13];
    const float* kg1  = (const float*)d_in[14];
    const float* kb1  = (const float*)d_in[15];
    const float* rg1  = (const float*)d_in[16];
    const float* rb1  = (const float*)d_in[17];
    const float* sg1  = (const float*)d_in[18];
    const float* sb1  = (const float*)d_in[19];
    const float* Wd   = (const float*)d_in[20];
    const float* bd   = (const float*)d_in[21];
    float* out = (float*)d_out;

    float *A0p, *z0p, *z1ap, *z1bp;
    __half *x0, *x1, *W0a, *W0b, *R0a, *R0b, *W1a, *W1b, *R1a, *R1b;
    __half *h0sa, *h0sb, *h0ia, *h0ib, *h1sa, *h1sb;
    int *cntp;
    cudaGetSymbolAddress((void**)&A0p,  g_A0);
    cudaGetSymbolAddress((void**)&z0p,  g_z0);
    cudaGetSymbolAddress((void**)&z1ap, g_z1a);
    cudaGetSymbolAddress((void**)&z1bp, g_z1b);
    cudaGetSymbolAddress((void**)&x0,   g_x0);
    cudaGetSymbolAddress((void**)&x1,   g_x1);
    cudaGetSymbolAddress((void**)&W0a,  g_W0a);
    cudaGetSymbolAddress((void**)&W0b,  g_W0b);
    cudaGetSymbolAddress((void**)&R0a,  g_R0a);
    cudaGetSymbolAddress((void**)&R0b,  g_R0b);
    cudaGetSymbolAddress((void**)&W1a,  g_W1a);
    cudaGetSymbolAddress((void**)&W1b,  g_W1b);
    cudaGetSymbolAddress((void**)&R1a,  g_R1a);
    cudaGetSymbolAddress((void**)&R1b,  g_R1b);
    cudaGetSymbolAddress((void**)&h0sa, g_h0sa);
    cudaGetSymbolAddress((void**)&h0sb, g_h0sb);
    cudaGetSymbolAddress((void**)&h0ia, g_h0ia);
    cudaGetSymbolAddress((void**)&h0ib, g_h0ib);
    cudaGetSymbolAddress((void**)&h1sa, g_h1sa);
    cudaGetSymbolAddress((void**)&h1sb, g_h1sb);
    cudaGetSymbolAddress((void**)&cntp, g_cnt);

    cudaFuncSetAttribute(gemm_f16x3, cudaFuncAttributeMaxDynamicSharedMemorySize, SMEM_H);

    // one-time prep
    const size_t nW0 = (size_t)G * KP;
    const size_t nRW = (size_t)G * U;
    const size_t nXT = (size_t)B * T * KP;
    init_kernel<<<(B * G + 255) / 256, 256>>>();
    sort_kernel<<<1, B>>>(mask);
    cnt_kernel<<<1, 128>>>();
    wsplit2_t<<<(unsigned)((nW0 + 255) / 256), 256>>>(W0, W0a, W0b, KP, G, F);
    wsplit2_t<<<(unsigned)((nRW + 255) / 256), 256>>>(R0, R0a, R0b, U, G, U);
    wsplit2_t<<<(unsigned)((nRW + 255) / 256), 256>>>(W1, W1a, W1b, U, G, U);
    wsplit2_t<<<(unsigned)((nRW + 255) / 256), 256>>>(R1, R1a, R1b, U, G, U);
    xsplit2<<<(unsigned)((nXT + 255) / 256), 256>>>(x, x0, x1);

    // precompute A0 = x @ W0 (raw; LN folded into cell0), permuted rows, full M
    {
        GArgsH a = {};
        a.p[0] = { x0, x1, W0a, W0b, A0p };
        gemm_f16x3<<<dim3(G / TNC, (B * T) / TMC, 1), 256, SMEM_H>>>(a, G, KP, nullptr);
    }

    // t = 0 prolog (z0(0) == 0; all rows active at t=0 since len >= 1)
    cell0_kernel<<<B, 256>>>(rg0, rb0, kg0, kb0, sg0, sb0, b0, 0);

    for (int t = 0; t < T - 1; t++) {
        GArgsH a = {};
        a.p[0] = { h0ia, h0ib, W1a, W1b, z1ap };   // z1a(t)
        a.p[1] = { h1sa, h1sb, R1a, R1b, z1bp };   // z1b(t)
        a.p[2] = { h0sa, h0sb, R0a, R0b, z0p  };   // z0(t+1)
        gemm_f16x3<<<dim3(G / TNC, B / TMC, 3), 256, SMEM_H>>>(a, G, U, cntp + t);
        fused_cell_kernel<<<2 * B, 256>>>(rg0, rb0, kg0, kb0, sg0, sb0, b0,
                                          kg1, kb1, rg1, rb1, sg1, sb1, b1, t);
    }

    // t = T-1 epilog
    {
        GArgsH a = {};
        a.p[0] = { h0ia, h0ib, W1a, W1b, z1ap };
        a.p[1] = { h1sa, h1sb, R1a, R1b, z1bp };
        gemm_f16x3<<<dim3(G / TNC, B / TMC, 2), 256, SMEM_H>>>(a, G, U, cntp + (T - 1));
        cell1_kernel<<<B, 256>>>(kg1, kb1, rg1, rb1, sg1, sb1, b1, T - 1);
    }

    dense_kernel<<<B, 256>>>(Wd, bd, out);
}

// round 11
// speedup vs baseline: 1.5803x; 1.0657x over previous
#include <cuda_runtime.h>
#include <cuda_fp16.h>
#include <cstdint>

#define B  1024
#define T  100
#define F  300
#define KP 320     /* F padded to 32-multiple */
#define U  512
#define G  2048    /* 4*U */
#define NC 10
#define EPS 1e-3f

// ---- fp16x3 HMMA GEMM config (proven round-7 config) ----
#define TMC 128
#define TNC 128
#define BKC 32
#define LDAH 40                       /* padded fp16 stride (conflict-free) */
#define ROWB (LDAH * 2)               /* 80 B row stride */
#define TERMB (TMC * ROWB)            /* 10240 B per term tile */
#define STAGEB (4 * TERMB)            /* A0,A1,B0,B1 = 40960 B */
#define SMEM_H (2 * STAGEB)           /* 81920 B */
#define NTILEA ((B * T) / TMC)        /* 800 precompute row-tiles */

// ---------------- device scratch ---------------------------------------------------
// batch-indexed arrays live in PERMUTED row order (sorted by len desc)
// A0 and x-splits live in [t*B + p] row order (tile == single t)
__device__ __align__(16) float g_A0[(size_t)B * T * G];
__device__ __align__(16) __half g_x0[(size_t)B * T * KP], g_x1[(size_t)B * T * KP];
__device__ __align__(16) __half g_W0a[(size_t)G * KP], g_W0b[(size_t)G * KP];
__device__ __align__(16) __half g_R0a[(size_t)G * U],  g_R0b[(size_t)G * U];
__device__ __align__(16) __half g_W1a[(size_t)G * U],  g_W1b[(size_t)G * U];
__device__ __align__(16) __half g_R1a[(size_t)G * U],  g_R1b[(size_t)G * U];
__device__ __align__(16) float g_z0[B * G], g_z1a[B * G], g_z1b[B * G];
__device__ __align__(16) __half g_h0sa[B * U], g_h0sb[B * U];
__device__ __align__(16) __half g_h1sa[B * U], g_h1sb[B * U];
__device__ __align__(16) float g_c0[B * U], g_c1[B * U], g_out[B * U];
__device__ int g_perm[B];        // permuted p -> original b
__device__ int g_plen[B];        // len of permuted row p (descending)
__device__ int g_cnt[T + 1];     // cnt[t] = #rows with len > t
__device__ int g_actA[NTILEA];   // precompute tile flags

__device__ __forceinline__ float sigmf(float x) { return 1.0f / (1.0f + expf(-x)); }

__device__ __forceinline__ void split2(float v, __half& h0, __half& h1)
{
    h0 = __float2half_rn(v);
    h1 = __float2half_rn(v - __half2float(h0));
}

__device__ __forceinline__ void cp16(uint32_t dst, const void* src) {
    asm volatile("cp.async.cg.shared.global [%0], [%1], 16;" :: "r"(dst), "l"(src));
}
__device__ __forceinline__ void cp_commit() { asm volatile("cp.async.commit_group;"); }
__device__ __forceinline__ void cp_wait0()  { asm volatile("cp.async.wait_group 0;"); }

#define MMA16(acc, a, b) \
    asm volatile( \
        "mma.sync.aligned.m16n8k16.row.col.f32.f16.f16.f32 " \
        "{%0,%1,%2,%3},{%4,%5,%6,%7},{%8,%9},{%0,%1,%2,%3};" \
        : "+f"((acc)[0]), "+f"((acc)[1]), "+f"((acc)[2]), "+f"((acc)[3]) \
        : "r"((a)[0]), "r"((a)[1]), "r"((a)[2]), "r"((a)[3]), \
          "r"((b)[0]), "r"((b)[1]))

#define LDSM4(r, addr) \
    asm volatile("ldmatrix.sync.aligned.m8n8.x4.shared.b16 {%0,%1,%2,%3}, [%4];" \
        : "=r"((r)[0]), "=r"((r)[1]), "=r"((r)[2]), "=r"((r)[3]) : "r"(addr))

// ---------------- fp16x3 HMMA GEMM --------------------------------------------------
// C[M,N] = A[M,K] @ Bt[N,K]^T, fp32 emulated as 2 fp16 terms, 3 pair-MMAs.
// cntp : scalar active-row bound (exit if m0 >= *cntp)     — loop GEMMs
// tilef: per-row-tile flags (exit if !tilef[blockIdx.y])   — precompute
struct ProbH { const __half *A0, *A1, *B0, *B1; float* C; };
struct GArgsH { ProbH p[3]; };

__global__ __launch_bounds__(256, 2) void gemm_f16x3(GArgsH ga, int N, int K,
                                                     const int* cntp, const int* tilef)
{
    const int m0 = blockIdx.y * TMC;
    if (cntp != nullptr && m0 >= *cntp) return;
    if (tilef != nullptr && tilef[blockIdx.y] == 0) return;

    extern __shared__ char smem[];
    const uint32_t sb0 = (uint32_t)__cvta_generic_to_shared(smem);

    const ProbH pr = ga.p[blockIdx.z];
    const int tid  = threadIdx.x;
    const int lane = tid & 31;
    const int wid  = tid >> 5;
    const int wm   = wid >> 2;       // 0..1  (64 rows)
    const int wn   = wid & 3;        // 0..3  (32 cols)
    const int n0   = blockIdx.x * TNC;
    const int grp  = lane >> 2;      // 0..7
    const int tg   = lane & 3;       // 0..3

    // per-lane ldmatrix offsets (x4 tile decomposition)
    const int lm = lane >> 3, lr = lane & 7;
    const uint32_t aoff = (uint32_t)((((lm & 1) * 8) + lr) * ROWB + (lm >> 1) * 16);
    const uint32_t boff = (uint32_t)((((lm >> 1) * 8) + lr) * ROWB + (lm & 1) * 16);

    // copy one BK=32 chunk (A terms + B terms) into stage buffer
    auto issue = [&](int stage, int k0) {
        const uint32_t sb = sb0 + (uint32_t)stage * STAGEB;
        const __half* srcs[4] = { pr.A0, pr.A1, pr.B0, pr.B1 };
        const int r0s[4] = { m0, m0, n0, n0 };
#pragma unroll
        for (int t = 0; t < 4; t++) {
#pragma unroll
            for (int i = 0; i < 2; i++) {
                const int idx = tid + i * 256;        // 0..511
                const int r = idx >> 2, gq = idx & 3; // row, 16B granule
                cp16(sb + (uint32_t)(t * TERMB + r * ROWB + gq * 16),
                     srcs[t] + (size_t)(r0s[t] + r) * K + k0 + gq * 8);
            }
        }
        cp_commit();
    };

    float acc[4][4][4];
#pragma unroll
    for (int i = 0; i < 4; i++)
#pragma unroll
        for (int j = 0; j < 4; j++)
#pragma unroll
            for (int k = 0; k < 4; k++) acc[i][j][k] = 0.f;

    const int NIT = K / BKC;
    issue(0, 0);

    for (int it = 0; it < NIT; ++it) {
        cp_wait0();
        __syncthreads();
        if (it + 1 < NIT) issue((it + 1) & 1, (it + 1) * BKC);

        const uint32_t sst = sb0 + (uint32_t)(it & 1) * STAGEB;
        const uint32_t aBase = sst + (uint32_t)((wm * 64) * ROWB) + aoff;
        const uint32_t bBase = sst + 2 * TERMB + (uint32_t)((wn * 32) * ROWB) + boff;

#pragma unroll
        for (int kk = 0; kk < 2; kk++) {
            uint32_t a0f[4][4], a1f[4][4], b0t[2][4], b1t[2][4];
#pragma unroll
            for (int im = 0; im < 4; im++) {
                const uint32_t ab = aBase + (uint32_t)(im * 16 * ROWB + kk * 32);
                LDSM4(a0f[im], ab);
                LDSM4(a1f[im], ab + TERMB);
            }
#pragma unroll
            for (int jp = 0; jp < 2; jp++) {
                const uint32_t bb = bBase + (uint32_t)(jp * 16 * ROWB + kk * 32);
                LDSM4(b0t[jp], bb);
                LDSM4(b1t[jp], bb + TERMB);
            }
#pragma unroll
            for (int im = 0; im < 4; im++)
#pragma unroll
                for (int jn = 0; jn < 4; jn++) {
                    const uint32_t* b0p = &b0t[jn >> 1][(jn & 1) * 2];
                    const uint32_t* b1p = &b1t[jn >> 1][(jn & 1) * 2];
                    MMA16(acc[im][jn], a1f[im], b0p);   // lo*hi
                    MMA16(acc[im][jn], a0f[im], b1p);   // hi*lo
                    MMA16(acc[im][jn], a0f[im], b0p);   // hi*hi
                }
        }
    }

    // epilogue
#pragma unroll
    for (int im = 0; im < 4; im++) {
        const int row0 = m0 + wm * 64 + im * 16 + grp;
#pragma unroll
        for (int jn = 0; jn < 4; jn++) {
            const int col = n0 + wn * 32 + jn * 8 + tg * 2;
            *(float2*)(pr.C + (size_t)row0 * N + col)       = make_float2(acc[im][jn][0], acc[im][jn][1]);
            *(float2*)(pr.C + (size_t)(row0 + 8) * N + col) = make_float2(acc[im][jn][2], acc[im][jn][3]);
        }
    }
}

// ---------------- one-time prep ------------------------------------------------------
// rank-sort rows by len desc (deterministic; tie-break original index asc)
__global__ void sort_kernel(const int* __restrict__ mask)
{
    __shared__ int len[B];
    const int b = threadIdx.x;
    int l = 0;
    for (int t = 0; t < T; t++) l += mask[b * T + t];
    len[b] = l;
    __syncthreads();
    int rank = 0;
    for (int j = 0; j < B; j++) {
        const int lj = len[j];
        rank += (lj > l) || (lj == l && j < b);
    }
    g_perm[rank] = b;
    g_plen[rank] = l;
}

// cnt[t] and per-precompute-tile activity flags
__global__ void cnt_kernel()
{
    const int tid = threadIdx.x;   // 1024 threads
    if (tid <= T) {
        int c = 0;
        for (int p = 0; p < B; p++) c += (g_plen[p] > tid);
        g_cnt[tid] = c;
    }
    __syncthreads();
    if (tid < NTILEA) {
        const int t  = tid >> 3;           // B/TMC = 8 tiles per t
        const int pb = tid & 7;
        g_actA[tid] = (pb * TMC < g_cnt[t]) ? 1 : 0;
    }
}

__global__ void wsplit2_t(const float* __restrict__ W, __half* __restrict__ t0,
                          __half* __restrict__ t1, int Kd, int N, int Ksrc)
{
    const size_t i = (size_t)blockIdx.x * 256 + threadIdx.x;
    if (i < (size_t)N * Kd) {
        const int n = (int)(i / Kd), k = (int)(i % Kd);
        const float v = (k < Ksrc) ? W[(size_t)k * N + n] : 0.f;
        __half h0, h1;
        split2(v, h0, h1);
        t0[i] = h0; t1[i] = h1;
    }
}

// x: gathered through perm, relaid to [t*B + p] rows
__global__ void xsplit2(const float* __restrict__ x, __half* __restrict__ t0,
                        __half* __restrict__ t1)
{
    const size_t i = (size_t)blockIdx.x * 256 + threadIdx.x;
    if (i < (size_t)B * T * KP) {
        const size_t r = i / KP;       // flat [t*B + p]
        const int c = (int)(i % KP);
        const int t = (int)(r / B), p = (int)(r % B);
        const float v = (c < F) ? x[((size_t)g_perm[p] * T + t) * F + c] : 0.f;
        __half h0, h1;
        split2(v, h0, h1);
        t0[i] = h0; t1[i] = h1;
    }
}

__global__ void init_kernel()
{
    const size_t i = (size_t)blockIdx.x * 256 + threadIdx.x;
    if (i < (size_t)B * G) g_z0[i] = 0.f;
    if (i < (size_t)B * U) {
        const __half z = __float2half_rn(0.f);
        g_h0sa[i] = z; g_h0sb[i] = z;
        g_h1sa[i] = z; g_h1sb[i] = z;
        g_c0[i] = 0.f; g_c1[i] = 0.f; g_out[i] = 0.f;
    }
}

// ---------------- unified cell body ----------------------------------------------------
// layer==0: za=g_z0 row, zb=g_A0[t*B+b];  layer==1: za=g_z1b row, zb=g_z1a row.
// Early-exits when row inactive (t >= plen[b]); surviving blocks write unconditionally.
__device__ void cell_body(int layer, int b, int t,
                          const float* __restrict__ gza, const float* __restrict__ bza,
                          const float* __restrict__ gzb, const float* __restrict__ bzb,
                          const float* __restrict__ sg,  const float* __restrict__ sb,
                          const float* __restrict__ bias)
{
    if (t >= g_plen[b]) return;   // uniform per block

    const int tid = threadIdx.x, lane = tid & 31, w = tid >> 5;
    const float* za = (layer == 0) ? (g_z0 + (size_t)b * G)
                                   : (g_z1b + (size_t)b * G);
    const float* zb = (layer == 0) ? (g_A0 + ((size_t)t * B + b) * G)
                                   : (g_z1a + (size_t)b * G);
    __shared__ float sh1[4][8];
    __shared__ float bc1[4];

    float va[2][4], vb[2][4];
    float s1 = 0.f, p1 = 0.f, s2 = 0.f, p2 = 0.f;
#pragma unroll
    for (int q = 0; q < 2; q++) {
        const int u = tid + q * 256;
#pragma unroll
        for (int gg = 0; gg < 4; gg++) {
            const float x1 = za[gg * U + u];
            const float x2 = zb[gg * U + u];
            va[q][gg] = x1; vb[q][gg] = x2;
            s1 += x1; p1 += x1 * x1; s2 += x2; p2 += x2 * x2;
        }
    }
#pragma unroll
    for (int o = 16; o > 0; o >>= 1) {
        s1 += __shfl_xor_sync(0xffffffffu, s1, o);
        p1 += __shfl_xor_sync(0xffffffffu, p1, o);
        s2 += __shfl_xor_sync(0xffffffffu, s2, o);
        p2 += __shfl_xor_sync(0xffffffffu, p2, o);
    }
    if (lane == 0) { sh1[0][w] = s1; sh1[1][w] = p1; sh1[2][w] = s2; sh1[3][w] = p2; }
    __syncthreads();
    if (tid == 0) {
        float S1 = 0.f, P1 = 0.f, S2 = 0.f, P2 = 0.f;
#pragma unroll
        for (int i = 0; i < 8; i++) { S1 += sh1[0][i]; P1 += sh1[1][i]; S2 += sh1[2][i]; P2 += sh1[3][i]; }
        const float m1 = S1 / (float)G, m2 = S2 / (float)G;
        bc1[0] = m1; bc1[1] = rsqrtf(P1 / (float)G - m1 * m1 + EPS);
        bc1[2] = m2; bc1[3] = rsqrtf(P2 / (float)G - m2 * m2 + EPS);
    }
    __syncthreads();
    const float m1 = bc1[0], r1 = bc1[1], m2 = bc1[2], r2 = bc1[3];

    float* cold = (layer == 0) ? g_c0 : g_c1;
    float cn[2], zo[2];
    float s3 = 0.f, p3 = 0.f;
#pragma unroll
    for (int q = 0; q < 2; q++) {
        const int u = tid + q * 256;
        float zg4[4];
#pragma unroll
        for (int gg = 0; gg < 4; gg++) {
            const int j = gg * U + u;
            zg4[gg] = (va[q][gg] - m1) * r1 * gza[j] + bza[j]
                    + (vb[q][gg] - m2) * r2 * gzb[j] + bzb[j] + bias[j];
        }
        const float c = cold[(size_t)b * U + u];
        const float v = sigmf(zg4[1]) * c + sigmf(zg4[0]) * tanhf(zg4[2]);
        cn[q] = v; zo[q] = zg4[3]; s3 += v; p3 += v * v;
    }
#pragma unroll
    for (int o = 16; o > 0; o >>= 1) {
        s3 += __shfl_xor_sync(0xffffffffu, s3, o);
        p3 += __shfl_xor_sync(0xffffffffu, p3, o);
    }
    __syncthreads();
    if (lane == 0) { sh1[0][w] = s3; sh1[1][w] = p3; }
    __syncthreads();
    if (tid == 0) {
        float S = 0.f, P = 0.f;
#pragma unroll
        for (int i = 0; i < 8; i++) { S += sh1[0][i]; P += sh1[1][i]; }
        const float m = S / (float)U;
        bc1[0] = m;
        bc1[1] = rsqrtf(P / (float)U - m * m + EPS);
    }
    __syncthreads();
    const float mc = bc1[0], rc = bc1[1];
#pragma unroll
    for (int q = 0; q < 2; q++) {
        const int u = tid + q * 256;
        const float cl = (cn[q] - mc) * rc * sg[u] + sb[u];
        const float hn = sigmf(zo[q]) * tanhf(cl);
        __half h0, h1;
        split2(hn, h0, h1);
        if (layer == 0) {
            g_h0sa[(size_t)b * U + u] = h0;
            g_h0sb[(size_t)b * U + u] = h1;
            g_c0  [(size_t)b * U + u] = cl;
        } else {
            g_h1sa[(size_t)b * U + u] = h0;
            g_h1sb[(size_t)b * U + u] = h1;
            g_c1 [(size_t)b * U + u] = cl;
            g_out[(size_t)b * U + u] = hn;
        }
    }
}

__global__ __launch_bounds__(256) void cell0_kernel(
    const float* rg, const float* rb, const float* kg, const float* kb,
    const float* sg, const float* sb, const float* bias, int t)
{
    cell_body(0, blockIdx.x, t, rg, rb, kg, kb, sg, sb, bias);
}

__global__ __launch_bounds__(256) void cell1_kernel(
    const float* kg, const float* kb, const float* rg, const float* rb,
    const float* sg, const float* sb, const float* bias, int t)
{
    cell_body(1, blockIdx.x, t, rg, rb, kg, kb, sg, sb, bias);
}

// fused: blocks [0,B) do cell1(t); blocks [B,2B) do cell0(t+1)
__global__ __launch_bounds__(256) void fused_cell_kernel(
    const float* rg0, const float* rb0, const float* kg0, const float* kb0,
    const float* sg0, const float* sb0, const float* b0,
    const float* kg1, const float* kb1, const float* rg1, const float* rb1,
    const float* sg1, const float* sb1, const float* b1, int t)
{
    if (blockIdx.x < B)
        cell_body(1, blockIdx.x, t, rg1, rb1, kg1, kb1, sg1, sb1, b1);
    else
        cell_body(0, blockIdx.x - B, t + 1, rg0, rb0, kg0, kb0, sg0, sb0, b0);
}

// ---------------- dense + softmax (scatter through perm) ------------------------------
__global__ __launch_bounds__(256) void dense_kernel(const float* __restrict__ Wd,
                                                    const float* __restrict__ bd,
                                                    float* __restrict__ out)
{
    const int b = blockIdx.x, tid = threadIdx.x, lane = tid & 31, w = tid >> 5;
    float p[NC];
#pragma unroll
    for (int c = 0; c < NC; c++) p[c] = 0.f;
    for (int u = tid; u < U; u += 256) {
        const float h = g_out[(size_t)b * U + u];
#pragma unroll
        for (int c = 0; c < NC; c++) p[c] += h * Wd[u * NC + c];
    }
    __shared__ float sh[NC][8];
#pragma unroll
    for (int c = 0; c < NC; c++) {
        float v = p[c];
#pragma unroll
        for (int o = 16; o > 0; o >>= 1) v += __shfl_xor_sync(0xffffffffu, v, o);
        if (lane == 0) sh[c][w] = v;
    }
    __syncthreads();
    if (tid == 0) {
        const int ob = g_perm[b];
        float lg[NC];
        float mx = -1e30f;
#pragma unroll
        for (int c = 0; c < NC; c++) {
            float l = bd[c];
#pragma unroll
            for (int i = 0; i < 8; i++) l += sh[c][i];
            lg[c] = l;
            mx = fmaxf(mx, l);
        }
        float sum = 0.f;
#pragma unroll
        for (int c = 0; c < NC; c++) { lg[c] = expf(lg[c] - mx); sum += lg[c]; }
        const float inv = 1.f / sum;
#pragma unroll
        for (int c = 0; c < NC; c++) out[ob * NC + c] = lg[c] * inv;
    }
}

// ---------------- launch ---------------------------------------------------------------
extern "C" void kernel_launch(void* const* d_in, const int* in_sizes, int n_in,
                              void* d_out, int out_size)
{
    const float* x    = (const float*)d_in[0];
    const int*   mask = (const int*)  d_in[1];
    const float* W0   = (const float*)d_in[2];
    const float* R0   = (const float*)d_in[3];
    const float* b0   = (const float*)d_in[4];
    const float* kg0  = (const float*)d_in[5];
    const float* kb0  = (const float*)d_in[6];
    const float* rg0  = (const float*)d_in[7];
    const float* rb0  = (const float*)d_in[8];
    const float* sg0  = (const float*)d_in[9];
    const float* sb0  = (const float*)d_in[10];
    const float* W1   = (const float*)d_in[11];
    const float* R1   = (const float*)d_in[12];
    const float* b1   = (const float*)d_in[13];
    const float* kg1  = (const float*)d_in[14];
    const float* kb1  = (const float*)d_in[15];
    const float* rg1  = (const float*)d_in[16];
    const float* rb1  = (const float*)d_in[17];
    const float* sg1  = (const float*)d_in[18];
    const float* sb1  = (const float*)d_in[19];
    const float* Wd   = (const float*)d_in[20];
    const float* bd   = (const float*)d_in[21];
    float* out = (float*)d_out;

    float *A0p, *z0p, *z1ap, *z1bp;
    __half *x0, *x1, *W0a, *W0b, *R0a, *R0b, *W1a, *W1b, *R1a, *R1b;
    __half *h0sa, *h0sb, *h1sa, *h1sb;
    int *cntp, *actAp;
    cudaGetSymbolAddress((void**)&A0p,  g_A0);
    cudaGetSymbolAddress((void**)&z0p,  g_z0);
    cudaGetSymbolAddress((void**)&z1ap, g_z1a);
    cudaGetSymbolAddress((void**)&z1bp, g_z1b);
    cudaGetSymbolAddress((void**)&x0,   g_x0);
    cudaGetSymbolAddress((void**)&x1,   g_x1);
    cudaGetSymbolAddress((void**)&W0a,  g_W0a);
    cudaGetSymbolAddress((void**)&W0b,  g_W0b);
    cudaGetSymbolAddress((void**)&R0a,  g_R0a);
    cudaGetSymbolAddress((void**)&R0b,  g_R0b);
    cudaGetSymbolAddress((void**)&W1a,  g_W1a);
    cudaGetSymbolAddress((void**)&W1b,  g_W1b);
    cudaGetSymbolAddress((void**)&R1a,  g_R1a);
    cudaGetSymbolAddress((void**)&R1b,  g_R1b);
    cudaGetSymbolAddress((void**)&h0sa, g_h0sa);
    cudaGetSymbolAddress((void**)&h0sb, g_h0sb);
    cudaGetSymbolAddress((void**)&h1sa, g_h1sa);
    cudaGetSymbolAddress((void**)&h1sb, g_h1sb);
    cudaGetSymbolAddress((void**)&cntp, g_cnt);
    cudaGetSymbolAddress((void**)&actAp, g_actA);

    cudaFuncSetAttribute(gemm_f16x3, cudaFuncAttributeMaxDynamicSharedMemorySize, SMEM_H);

    // one-time prep
    const size_t nW0 = (size_t)G * KP;
    const size_t nRW = (size_t)G * U;
    const size_t nXT = (size_t)B * T * KP;
    init_kernel<<<(B * G + 255) / 256, 256>>>();
    sort_kernel<<<1, B>>>(mask);
    cnt_kernel<<<1, 1024>>>();
    wsplit2_t<<<(unsigned)((nW0 + 255) / 256), 256>>>(W0, W0a, W0b, KP, G, F);
    wsplit2_t<<<(unsigned)((nRW + 255) / 256), 256>>>(R0, R0a, R0b, U, G, U);
    wsplit2_t<<<(unsigned)((nRW + 255) / 256), 256>>>(W1, W1a, W1b, U, G, U);
    wsplit2_t<<<(unsigned)((nRW + 255) / 256), 256>>>(R1, R1a, R1b, U, G, U);
    xsplit2<<<(unsigned)((nXT + 255) / 256), 256>>>(x, x0, x1);

    // precompute A0 = x @ W0 (raw; LN folded into cell0), [t*B+p] rows, tile-skipped
    {
        GArgsH a = {};
        a.p[0] = { x0, x1, W0a, W0b, A0p };
        gemm_f16x3<<<dim3(G / TNC, NTILEA, 1), 256, SMEM_H>>>(a, G, KP, nullptr, actAp);
    }

    // t = 0 prolog (z0(0) == 0; all rows active at t=0 since len >= 1)
    cell0_kernel<<<B, 256>>>(rg0, rb0, kg0, kb0, sg0, sb0, b0, 0);

    for (int t = 0; t < T - 1; t++) {
        GArgsH a = {};
        a.p[0] = { h0sa, h0sb, W1a, W1b, z1ap };   // z1a(t)  (h0i == h0s)
        a.p[1] = { h1sa, h1sb, R1a, R1b, z1bp };   // z1b(t)
        a.p[2] = { h0sa, h0sb, R0a, R0b, z0p  };   // z0(t+1)
        gemm_f16x3<<<dim3(G / TNC, B / TMC, 3), 256, SMEM_H>>>(a, G, U, cntp + t, nullptr);
        fused_cell_kernel<<<2 * B, 256>>>(rg0, rb0, kg0, kb0, sg0, sb0, b0,
                                          kg1, kb1, rg1, rb1, sg1, sb1, b1, t);
    }

    // t = T-1 epilog
    {
        GArgsH a = {};
        a.p[0] = { h0sa, h0sb, W1a, W1b, z1ap };
        a.p[1] = { h1sa, h1sb, R1a, R1b, z1bp };
        gemm_f16x3<<<dim3(G / TNC, B / TMC, 2), 256, SMEM_H>>>(a, G, U, cntp + (T - 1), nullptr);
        cell1_kernel<<<B, 256>>>(kg1, kb1, rg1, rb1, sg1, sb1, b1, T - 1);
    }

    dense_kernel<<<B, 256>>>(Wd, bd, out);
}

// round 13
// speedup vs baseline: 1.7202x; 1.0885x over previous
#include <cuda_runtime.h>
#include <cuda_fp16.h>
#include <cstdint>

#define B  1024
#define T  100
#define F  300
#define KP 320     /* F padded to 32-multiple */
#define U  512
#define G  2048    /* 4*U */
#define NC 10
#define EPS 1e-3f

// ---- fp16x3 HMMA GEMM config: fine 64x64 tiles for SM load balance ----
#define TMC 64
#define TNC 64
#define BKC 32
#define LDAH 40                       /* padded fp16 stride (conflict-free) */
#define ROWB (LDAH * 2)               /* 80 B row stride */
#define TERMB (TMC * ROWB)            /* 5120 B per operand term tile */
#define STAGEB (4 * TERMB)            /* A0,A1,B0,B1 = 20480 B */
#define SMEM_H (2 * STAGEB)           /* 40960 B */
#define NTILEA ((B * T) / TMC)        /* 1600 precompute row-tiles */

// ---------------- device scratch ---------------------------------------------------
// batch-indexed arrays live in PERMUTED row order (sorted by len desc)
// A0 and x-splits live in [t*B + p] row order (tile == single t)
__device__ __align__(16) float g_A0[(size_t)B * T * G];
__device__ __align__(16) __half g_x0[(size_t)B * T * KP], g_x1[(size_t)B * T * KP];
__device__ __align__(16) __half g_W0a[(size_t)G * KP], g_W0b[(size_t)G * KP];
__device__ __align__(16) __half g_R0a[(size_t)G * U],  g_R0b[(size_t)G * U];
__device__ __align__(16) __half g_W1a[(size_t)G * U],  g_W1b[(size_t)G * U];
__device__ __align__(16) __half g_R1a[(size_t)G * U],  g_R1b[(size_t)G * U];
__device__ __align__(16) float g_z0[B * G], g_z1a[B * G], g_z1b[B * G];
__device__ __align__(16) __half g_h0sa[B * U], g_h0sb[B * U];
__device__ __align__(16) __half g_h1sa[B * U], g_h1sb[B * U];
__device__ __align__(16) float g_c0[B * U], g_c1[B * U], g_out[B * U];
__device__ int g_perm[B];        // permuted p -> original b
__device__ int g_plen[B];        // len of permuted row p (descending)
__device__ int g_cnt[T + 1];     // cnt[t] = #rows with len > t
__device__ int g_actA[NTILEA];   // precompute tile flags

__device__ __forceinline__ float sigmf(float x) { return 1.0f / (1.0f + expf(-x)); }

__device__ __forceinline__ void split2(float v, __half& h0, __half& h1)
{
    h0 = __float2half_rn(v);
    h1 = __float2half_rn(v - __half2float(h0));
}

__device__ __forceinline__ void cp16(uint32_t dst, const void* src) {
    asm volatile("cp.async.cg.shared.global [%0], [%1], 16;" :: "r"(dst), "l"(src));
}
__device__ __forceinline__ void cp_commit() { asm volatile("cp.async.commit_group;"); }
__device__ __forceinline__ void cp_wait0()  { asm volatile("cp.async.wait_group 0;"); }

#define MMA16(acc, a, b) \
    asm volatile( \
        "mma.sync.aligned.m16n8k16.row.col.f32.f16.f16.f32 " \
        "{%0,%1,%2,%3},{%4,%5,%6,%7},{%8,%9},{%0,%1,%2,%3};" \
        : "+f"((acc)[0]), "+f"((acc)[1]), "+f"((acc)[2]), "+f"((acc)[3]) \
        : "r"((a)[0]), "r"((a)[1]), "r"((a)[2]), "r"((a)[3]), \
          "r"((b)[0]), "r"((b)[1]))

#define LDSM4(r, addr) \
    asm volatile("ldmatrix.sync.aligned.m8n8.x4.shared.b16 {%0,%1,%2,%3}, [%4];" \
        : "=r"((r)[0]), "=r"((r)[1]), "=r"((r)[2]), "=r"((r)[3]) : "r"(addr))

// ---------------- fp16x3 HMMA GEMM --------------------------------------------------
// C[M,N] = A[M,K] @ Bt[N,K]^T, fp32 emulated as 2 fp16 terms, 3 pair-MMAs.
// cntp : scalar active-row bound (exit if m0 >= *cntp)     — loop GEMMs
// tilef: per-row-tile flags (exit if !tilef[blockIdx.y])   — precompute
struct ProbH { const __half *A0, *A1, *B0, *B1; float* C; };
struct GArgsH { ProbH p[3]; };

__global__ __launch_bounds__(128, 5) void gemm_f16x3(GArgsH ga, int N, int K,
                                                     const int* cntp, const int* tilef)
{
    const int m0 = blockIdx.y * TMC;
    if (cntp != nullptr && m0 >= *cntp) return;
    if (tilef != nullptr && tilef[blockIdx.y] == 0) return;

    extern __shared__ char smem[];
    const uint32_t sb0 = (uint32_t)__cvta_generic_to_shared(smem);

    const ProbH pr = ga.p[blockIdx.z];
    const int tid  = threadIdx.x;
    const int lane = tid & 31;
    const int wid  = tid >> 5;       // 0..3
    const int wm   = wid >> 1;       // 0..1  (32 rows each)
    const int wn   = wid & 1;        // 0..1  (32 cols each)
    const int n0   = blockIdx.x * TNC;
    const int grp  = lane >> 2;      // 0..7
    const int tg   = lane & 3;       // 0..3

    // per-lane ldmatrix offsets (x4 tile decomposition)
    const int lm = lane >> 3, lr = lane & 7;
    const uint32_t aoff = (uint32_t)((((lm & 1) * 8) + lr) * ROWB + (lm >> 1) * 16);
    const uint32_t boff = (uint32_t)((((lm >> 1) * 8) + lr) * ROWB + (lm & 1) * 16);

    // copy one BK=32 chunk: per term 64 rows x 4 granules(16B) = 256 slots,
    // 128 threads x 2 iterations.
    auto issue = [&](int stage, int k0) {
        const uint32_t sb = sb0 + (uint32_t)stage * STAGEB;
#pragma unroll
        for (int i = 0; i < 2; i++) {
            const int idx = tid + i * 128;        // 0..255
            const int r = idx >> 2, g = idx & 3;  // row, 16B granule
            const uint32_t doff = (uint32_t)(r * ROWB + g * 16);
            const size_t soffA = (size_t)(m0 + r) * K + k0 + g * 8;
            const size_t soffB = (size_t)(n0 + r) * K + k0 + g * 8;
            cp16(sb + 0 * TERMB + doff, pr.A0 + soffA);
            cp16(sb + 1 * TERMB + doff, pr.A1 + soffA);
            cp16(sb + 2 * TERMB + doff, pr.B0 + soffB);
            cp16(sb + 3 * TERMB + doff, pr.B1 + soffB);
        }
        cp_commit();
    };

    float acc[2][4][4];
#pragma unroll
    for (int i = 0; i < 2; i++)
#pragma unroll
        for (int j = 0; j < 4; j++)
#pragma unroll
            for (int k = 0; k < 4; k++) acc[i][j][k] = 0.f;

    const int NIT = K / BKC;
    issue(0, 0);

    for (int it = 0; it < NIT; ++it) {
        cp_wait0();
        __syncthreads();
        if (it + 1 < NIT) issue((it + 1) & 1, (it + 1) * BKC);

        const uint32_t sst = sb0 + (uint32_t)(it & 1) * STAGEB;
        const uint32_t aBase = sst + (uint32_t)((wm * 32) * ROWB) + aoff;
        const uint32_t bBase = sst + 2 * TERMB + (uint32_t)((wn * 32) * ROWB) + boff;

#pragma unroll
        for (int kk = 0; kk < 2; kk++) {
            uint32_t a0f[2][4], a1f[2][4], b0t[2][4], b1t[2][4];
#pragma unroll
            for (int im = 0; im < 2; im++) {
                const uint32_t ab = aBase + (uint32_t)(im * 16 * ROWB + kk * 32);
                LDSM4(a0f[im], ab);
                LDSM4(a1f[im], ab + TERMB);
            }
#pragma unroll
            for (int jp = 0; jp < 2; jp++) {
                const uint32_t bb = bBase + (uint32_t)(jp * 16 * ROWB + kk * 32);
                LDSM4(b0t[jp], bb);
                LDSM4(b1t[jp], bb + TERMB);
            }
#pragma unroll
            for (int im = 0; im < 2; im++)
#pragma unroll
                for (int jn = 0; jn < 4; jn++) {
                    const uint32_t* b0p = &b0t[jn >> 1][(jn & 1) * 2];
                    const uint32_t* b1p = &b1t[jn >> 1][(jn & 1) * 2];
                    MMA16(acc[im][jn], a1f[im], b0p);   // lo*hi
                    MMA16(acc[im][jn], a0f[im], b1p);   // hi*lo
                    MMA16(acc[im][jn], a0f[im], b0p);   // hi*hi
                }
        }
    }

    // epilogue
#pragma unroll
    for (int im = 0; im < 2; im++) {
        const int row0 = m0 + wm * 32 + im * 16 + grp;
#pragma unroll
        for (int jn = 0; jn < 4; jn++) {
            const int col = n0 + wn * 32 + jn * 8 + tg * 2;
            *(float2*)(pr.C + (size_t)row0 * N + col)       = make_float2(acc[im][jn][0], acc[im][jn][1]);
            *(float2*)(pr.C + (size_t)(row0 + 8) * N + col) = make_float2(acc[im][jn][2], acc[im][jn][3]);
        }
    }
}

// ---------------- one-time prep ------------------------------------------------------
// rank-sort rows by len desc (deterministic; tie-break original index asc)
__global__ void sort_kernel(const int* __restrict__ mask)
{
    __shared__ int len[B];
    const int b = threadIdx.x;
    int l = 0;
    for (int t = 0; t < T; t++) l += mask[b * T + t];
    len[b] = l;
    __syncthreads();
    int rank = 0;
    for (int j = 0; j < B; j++) {
        const int lj = len[j];
        rank += (lj > l) || (lj == l && j < b);
    }
    g_perm[rank] = b;
    g_plen[rank] = l;
}

// cnt[t] and per-precompute-tile activity flags
__global__ void cnt_kernel()
{
    const int tid = threadIdx.x;   // 1024 threads
    if (tid <= T) {
        int c = 0;
        for (int p = 0; p < B; p++) c += (g_plen[p] > tid);
        g_cnt[tid] = c;
    }
    __syncthreads();
    for (int i = tid; i < NTILEA; i += 1024) {
        const int t  = i >> 4;            // B/TMC = 16 tiles per t
        const int pb = i & 15;
        g_actA[i] = (pb * TMC < g_cnt[t]) ? 1 : 0;
    }
}

__global__ void wsplit2_t(const float* __restrict__ W, __half* __restrict__ t0,
                          __half* __restrict__ t1, int Kd, int N, int Ksrc)
{
    const size_t i = (size_t)blockIdx.x * 256 + threadIdx.x;
    if (i < (size_t)N * Kd) {
        const int n = (int)(i / Kd), k = (int)(i % Kd);
        const float v = (k < Ksrc) ? W[(size_t)k * N + n] : 0.f;
        __half h0, h1;
        split2(v, h0, h1);
        t0[i] = h0; t1[i] = h1;
    }
}

// x: gathered through perm, relaid to [t*B + p] rows
__global__ void xsplit2(const float* __restrict__ x, __half* __restrict__ t0,
                        __half* __restrict__ t1)
{
    const size_t i = (size_t)blockIdx.x * 256 + threadIdx.x;
    if (i < (size_t)B * T * KP) {
        const size_t r = i / KP;       // flat [t*B + p]
        const int c = (int)(i % KP);
        const int t = (int)(r / B), p = (int)(r % B);
        const float v = (c < F) ? x[((size_t)g_perm[p] * T + t) * F + c] : 0.f;
        __half h0, h1;
        split2(v, h0, h1);
        t0[i] = h0; t1[i] = h1;
    }
}

__global__ void init_kernel()
{
    const size_t i = (size_t)blockIdx.x * 256 + threadIdx.x;
    if (i < (size_t)B * G) g_z0[i] = 0.f;
    if (i < (size_t)B * U) {
        const __half z = __float2half_rn(0.f);
        g_h0sa[i] = z; g_h0sb[i] = z;
        g_h1sa[i] = z; g_h1sb[i] = z;
        g_c0[i] = 0.f; g_c1[i] = 0.f; g_out[i] = 0.f;
    }
}

// ---------------- unified cell body ----------------------------------------------------
// layer==0: za=g_z0 row, zb=g_A0[t*B+b];  layer==1: za=g_z1b row, zb=g_z1a row.
// Early-exits when row inactive (t >= plen[b]); surviving blocks write unconditionally.
__device__ void cell_body(int layer, int b, int t,
                          const float* __restrict__ gza, const float* __restrict__ bza,
                          const float* __restrict__ gzb, const float* __restrict__ bzb,
                          const float* __restrict__ sg,  const float* __restrict__ sb,
                          const float* __restrict__ bias)
{
    if (t >= g_plen[b]) return;   // uniform per block

    const int tid = threadIdx.x, lane = tid & 31, w = tid >> 5;
    const float* za = (layer == 0) ? (g_z0 + (size_t)b * G)
                                   : (g_z1b + (size_t)b * G);
    const float* zb = (layer == 0) ? (g_A0 + ((size_t)t * B + b) * G)
                                   : (g_z1a + (size_t)b * G);
    __shared__ float sh1[4][8];
    __shared__ float bc1[4];

    float va[2][4], vb[2][4];
    float s1 = 0.f, p1 = 0.f, s2 = 0.f, p2 = 0.f;
#pragma unroll
    for (int q = 0; q < 2; q++) {
        const int u = tid + q * 256;
#pragma unroll
        for (int gg = 0; gg < 4; gg++) {
            const float x1 = za[gg * U + u];
            const float x2 = zb[gg * U + u];
            va[q][gg] = x1; vb[q][gg] = x2;
            s1 += x1; p1 += x1 * x1; s2 += x2; p2 += x2 * x2;
        }
    }
#pragma unroll
    for (int o = 16; o > 0; o >>= 1) {
        s1 += __shfl_xor_sync(0xffffffffu, s1, o);
        p1 += __shfl_xor_sync(0xffffffffu, p1, o);
        s2 += __shfl_xor_sync(0xffffffffu, s2, o);
        p2 += __shfl_xor_sync(0xffffffffu, p2, o);
    }
    if (lane == 0) { sh1[0][w] = s1; sh1[1][w] = p1; sh1[2][w] = s2; sh1[3][w] = p2; }
    __syncthreads();
    if (tid == 0) {
        float S1 = 0.f, P1 = 0.f, S2 = 0.f, P2 = 0.f;
#pragma unroll
        for (int i = 0; i < 8; i++) { S1 += sh1[0][i]; P1 += sh1[1][i]; S2 += sh1[2][i]; P2 += sh1[3][i]; }
        const float m1 = S1 / (float)G, m2 = S2 / (float)G;
        bc1[0] = m1; bc1[1] = rsqrtf(P1 / (float)G - m1 * m1 + EPS);
        bc1[2] = m2; bc1[3] = rsqrtf(P2 / (float)G - m2 * m2 + EPS);
    }
    __syncthreads();
    const float m1 = bc1[0], r1 = bc1[1], m2 = bc1[2], r2 = bc1[3];

    float* cold = (layer == 0) ? g_c0 : g_c1;
    float cn[2], zo[2];
    float s3 = 0.f, p3 = 0.f;
#pragma unroll
    for (int q = 0; q < 2; q++) {
        const int u = tid + q * 256;
        float zg4[4];
#pragma unroll
        for (int gg = 0; gg < 4; gg++) {
            const int j = gg * U + u;
            zg4[gg] = (va[q][gg] - m1) * r1 * gza[j] + bza[j]
                    + (vb[q][gg] - m2) * r2 * gzb[j] + bzb[j] + bias[j];
        }
        const float c = cold[(size_t)b * U + u];
        const float v = sigmf(zg4[1]) * c + sigmf(zg4[0]) * tanhf(zg4[2]);
        cn[q] = v; zo[q] = zg4[3]; s3 += v; p3 += v * v;
    }
#pragma unroll
    for (int o = 16; o > 0; o >>= 1) {
        s3 += __shfl_xor_sync(0xffffffffu, s3, o);
        p3 += __shfl_xor_sync(0xffffffffu, p3, o);
    }
    __syncthreads();
    if (lane == 0) { sh1[0][w] = s3; sh1[1][w] = p3; }
    __syncthreads();
    if (tid == 0) {
        float S = 0.f, P = 0.f;
#pragma unroll
        for (int i = 0; i < 8; i++) { S += sh1[0][i]; P += sh1[1][i]; }
        const float m = S / (float)U;
        bc1[0] = m;
        bc1[1] = rsqrtf(P / (float)U - m * m + EPS);
    }
    __syncthreads();
    const float mc = bc1[0], rc = bc1[1];
#pragma unroll
    for (int q = 0; q < 2; q++) {
        const int u = tid + q * 256;
        const float cl = (cn[q] - mc) * rc * sg[u] + sb[u];
        const float hn = sigmf(zo[q]) * tanhf(cl);
        __half h0, h1;
        split2(hn, h0, h1);
        if (layer == 0) {
            g_h0sa[(size_t)b * U + u] = h0;
            g_h0sb[(size_t)b * U + u] = h1;
            g_c0  [(size_t)b * U + u] = cl;
        } else {
            g_h1sa[(size_t)b * U + u] = h0;
            g_h1sb[(size_t)b * U + u] = h1;
            g_c1 [(size_t)b * U + u] = cl;
            g_out[(size_t)b * U + u] = hn;
        }
    }
}

__global__ __launch_bounds__(256) void cell0_kernel(
    const float* rg, const float* rb, const float* kg, const float* kb,
    const float* sg, const float* sb, const float* bias, int t)
{
    cell_body(0, blockIdx.x, t, rg, rb, kg, kb, sg, sb, bias);
}

__global__ __launch_bounds__(256) void cell1_kernel(
    const float* kg, const float* kb, const float* rg, const float* rb,
    const float* sg, const float* sb, const float* bias, int t)
{
    cell_body(1, blockIdx.x, t, rg, rb, kg, kb, sg, sb, bias);
}

// fused: blocks [0,B) do cell1(t); blocks [B,2B) do cell0(t+1)
__global__ __launch_bounds__(256) void fused_cell_kernel(
    const float* rg0, const float* rb0, const float* kg0, const float* kb0,
    const float* sg0, const float* sb0, const float* b0,
    const float* kg1, const float* kb1, const float* rg1, const float* rb1,
    const float* sg1, const float* sb1, const float* b1, int t)
{
    if (blockIdx.x < B)
        cell_body(1, blockIdx.x, t, rg1, rb1, kg1, kb1, sg1, sb1, b1);
    else
        cell_body(0, blockIdx.x - B, t + 1, rg0, rb0, kg0, kb0, sg0, sb0, b0);
}

// ---------------- dense + softmax (scatter through perm) ------------------------------
__global__ __launch_bounds__(256) void dense_kernel(const float* __restrict__ Wd,
                                                    const float* __restrict__ bd,
                                                    float* __restrict__ out)
{
    const int b = blockIdx.x, tid = threadIdx.x, lane = tid & 31, w = tid >> 5;
    float p[NC];
#pragma unroll
    for (int c = 0; c < NC; c++) p[c] = 0.f;
    for (int u = tid; u < U; u += 256) {
        const float h = g_out[(size_t)b * U + u];
#pragma unroll
        for (int c = 0; c < NC; c++) p[c] += h * Wd[u * NC + c];
    }
    __shared__ float sh[NC][8];
#pragma unroll
    for (int c = 0; c < NC; c++) {
        float v = p[c];
#pragma unroll
        for (int o = 16; o > 0; o >>= 1) v += __shfl_xor_sync(0xffffffffu, v, o);
        if (lane == 0) sh[c][w] = v;
    }
    __syncthreads();
    if (tid == 0) {
        const int ob = g_perm[b];
        float lg[NC];
        float mx = -1e30f;
#pragma unroll
        for (int c = 0; c < NC; c++) {
            float l = bd[c];
#pragma unroll
            for (int i = 0; i < 8; i++) l += sh[c][i];
            lg[c] = l;
            mx = fmaxf(mx, l);
        }
        float sum = 0.f;
#pragma unroll
        for (int c = 0; c < NC; c++) { lg[c] = expf(lg[c] - mx); sum += lg[c]; }
        const float inv = 1.f / sum;
#pragma unroll
        for (int c = 0; c < NC; c++) out[ob * NC + c] = lg[c] * inv;
    }
}

// ---------------- launch ---------------------------------------------------------------
extern "C" void kernel_launch(void* const* d_in, const int* in_sizes, int n_in,
                              void* d_out, int out_size)
{
    const float* x    = (const float*)d_in[0];
    const int*   mask = (const int*)  d_in[1];
    const float* W0   = (const float*)d_in[2];
    const float* R0   = (const float*)d_in[3];
    const float* b0   = (const float*)d_in[4];
    const float* kg0  = (const float*)d_in[5];
    const float* kb0  = (const float*)d_in[6];
    const float* rg0  = (const float*)d_in[7];
    const float* rb0  = (const float*)d_in[8];
    const float* sg0  = (const float*)d_in[9];
    const float* sb0  = (const float*)d_in[10];
    const float* W1   = (const float*)d_in[11];
    const float* R1   = (const float*)d_in[12];
    const float* b1   = (const float*)d_in[13];
    const float* kg1  = (const float*)d_in[14];
    const float* kb1  = (const float*)d_in[15];
    const float* rg1  = (const float*)d_in[16];
    const float* rb1  = (const float*)d_in[17];
    const float* sg1  = (const float*)d_in[18];
    const float* sb1  = (const float*)d_in[19];
    const float* Wd   = (const float*)d_in[20];
    const float* bd   = (const float*)d_in[21];
    float* out = (float*)d_out;

    float *A0p, *z0p, *z1ap, *z1bp;
    __half *x0, *x1, *W0a, *W0b, *R0a, *R0b, *W1a, *W1b, *R1a, *R1b;
    __half *h0sa, *h0sb, *h1sa, *h1sb;
    int *cntp, *actAp;
    cudaGetSymbolAddress((void**)&A0p,  g_A0);
    cudaGetSymbolAddress((void**)&z0p,  g_z0);
    cudaGetSymbolAddress((void**)&z1ap, g_z1a);
    cudaGetSymbolAddress((void**)&z1bp, g_z1b);
    cudaGetSymbolAddress((void**)&x0,   g_x0);
    cudaGetSymbolAddress((void**)&x1,   g_x1);
    cudaGetSymbolAddress((void**)&W0a,  g_W0a);
    cudaGetSymbolAddress((void**)&W0b,  g_W0b);
    cudaGetSymbolAddress((void**)&R0a,  g_R0a);
    cudaGetSymbolAddress((void**)&R0b,  g_R0b);
    cudaGetSymbolAddress((void**)&W1a,  g_W1a);
    cudaGetSymbolAddress((void**)&W1b,  g_W1b);
    cudaGetSymbolAddress((void**)&R1a,  g_R1a);
    cudaGetSymbolAddress((void**)&R1b,  g_R1b);
    cudaGetSymbolAddress((void**)&h0sa, g_h0sa);
    cudaGetSymbolAddress((void**)&h0sb, g_h0sb);
    cudaGetSymbolAddress((void**)&h1sa, g_h1sa);
    cudaGetSymbolAddress((void**)&h1sb, g_h1sb);
    cudaGetSymbolAddress((void**)&cntp, g_cnt);
    cudaGetSymbolAddress((void**)&actAp, g_actA);

    cudaFuncSetAttribute(gemm_f16x3, cudaFuncAttributeMaxDynamicSharedMemorySize, SMEM_H);

    // one-time prep
    const size_t nW0 = (size_t)G * KP;
    const size_t nRW = (size_t)G * U;
    const size_t nXT = (size_t)B * T * KP;
    init_kernel<<<(B * G + 255) / 256, 256>>>();
    sort_kernel<<<1, B>>>(mask);
    cnt_kernel<<<1, 1024>>>();
    wsplit2_t<<<(unsigned)((nW0 + 255) / 256), 256>>>(W0, W0a, W0b, KP, G, F);
    wsplit2_t<<<(unsigned)((nRW + 255) / 256), 256>>>(R0, R0a, R0b, U, G, U);
    wsplit2_t<<<(unsigned)((nRW + 255) / 256), 256>>>(W1, W1a, W1b, U, G, U);
    wsplit2_t<<<(unsigned)((nRW + 255) / 256), 256>>>(R1, R1a, R1b, U, G, U);
    xsplit2<<<(unsigned)((nXT + 255) / 256), 256>>>(x, x0, x1);

    // precompute A0 = x @ W0 (raw; LN folded into cell0), [t*B+p] rows, tile-skipped
    {
        GArgsH a = {};
        a.p[0] = { x0, x1, W0a, W0b, A0p };
        gemm_f16x3<<<dim3(G / TNC, NTILEA, 1), 128, SMEM_H>>>(a, G, KP, nullptr, actAp);
    }

    // t = 0 prolog (z0(0) == 0; all rows active at t=0 since len >= 1)
    cell0_kernel<<<B, 256>>>(rg0, rb0, kg0, kb0, sg0, sb0, b0, 0);

    for (int t = 0; t < T - 1; t++) {
        GArgsH a = {};
        a.p[0] = { h0sa, h0sb, W1a, W1b, z1ap };   // z1a(t)
        a.p[1] = { h1sa, h1sb, R1a, R1b, z1bp };   // z1b(t)
        a.p[2] = { h0sa, h0sb, R0a, R0b, z0p  };   // z0(t+1)
        gemm_f16x3<<<dim3(G / TNC, B / TMC, 3), 128, SMEM_H>>>(a, G, U, cntp + t, nullptr);
        fused_cell_kernel<<<2 * B, 256>>>(rg0, rb0, kg0, kb0, sg0, sb0, b0,
                                          kg1, kb1, rg1, rb1, sg1, sb1, b1, t);
    }

    // t = T-1 epilog
    {
        GArgsH a = {};
        a.p[0] = { h0sa, h0sb, W1a, W1b, z1ap };
        a.p[1] = { h1sa, h1sb, R1a, R1b, z1bp };
        gemm_f16x3<<<dim3(G / TNC, B / TMC, 2), 128, SMEM_H>>>(a, G, U, cntp + (T - 1), nullptr);
        cell1_kernel<<<B, 256>>>(kg1, kb1, rg1, rb1, sg1, sb1, b1, T - 1);
    }

    dense_kernel<<<B, 256>>>(Wd, bd, out);
}

// round 14
// speedup vs baseline: 1.7242x; 1.0023x over previous
#include <cuda_runtime.h>
#include <cuda_fp16.h>
#include <cstdint>

#define B  1024
#define T  100
#define F  300
#define KP 320     /* F padded to 32-multiple */
#define U  512
#define G  2048    /* 4*U */
#define NC 10
#define EPS 1e-3f

// ---- fp16x3 HMMA GEMM config: fine 64x64 tiles for SM load balance ----
#define TMC 64
#define TNC 64
#define BKC 32
#define LDAH 40                       /* padded fp16 stride (conflict-free) */
#define ROWB (LDAH * 2)               /* 80 B row stride */
#define TERMB (TMC * ROWB)            /* 5120 B per operand term tile */
#define STAGEB (4 * TERMB)            /* A0,A1,B0,B1 = 20480 B */
#define SMEM_H (2 * STAGEB)           /* 40960 B */
#define NTILEA ((B * T) / TMC)        /* 1600 precompute row-tiles */
#define NCHUNK 10                     /* precompute chunks (10 timesteps each) */
#define CH_TILES (NTILEA / NCHUNK)    /* 160 row-tiles per chunk */

// ---------------- device scratch ---------------------------------------------------
// batch-indexed arrays live in PERMUTED row order (sorted by len desc)
// A0 and x-splits live in [t*B + p] row order (tile == single t)
__device__ __align__(16) float g_A0[(size_t)B * T * G];
__device__ __align__(16) __half g_x0[(size_t)B * T * KP], g_x1[(size_t)B * T * KP];
__device__ __align__(16) __half g_W0a[(size_t)G * KP], g_W0b[(size_t)G * KP];
__device__ __align__(16) __half g_R0a[(size_t)G * U],  g_R0b[(size_t)G * U];
__device__ __align__(16) __half g_W1a[(size_t)G * U],  g_W1b[(size_t)G * U];
__device__ __align__(16) __half g_R1a[(size_t)G * U],  g_R1b[(size_t)G * U];
__device__ __align__(16) float g_z0[B * G], g_z1a[B * G], g_z1b[B * G];
__device__ __align__(16) __half g_h0sa[B * U], g_h0sb[B * U];
__device__ __align__(16) __half g_h1sa[B * U], g_h1sb[B * U];
__device__ __align__(16) float g_c0[B * U], g_c1[B * U], g_out[B * U];
__device__ int g_perm[B];        // permuted p -> original b
__device__ int g_plen[B];        // len of permuted row p (descending)
__device__ int g_cnt[T + 1];     // cnt[t] = #rows with len > t
__device__ int g_actA[NTILEA];   // precompute tile flags

__device__ __forceinline__ float sigmf(float x) { return 1.0f / (1.0f + expf(-x)); }

__device__ __forceinline__ void split2(float v, __half& h0, __half& h1)
{
    h0 = __float2half_rn(v);
    h1 = __float2half_rn(v - __half2float(h0));
}

__device__ __forceinline__ void cp16(uint32_t dst, const void* src) {
    asm volatile("cp.async.cg.shared.global [%0], [%1], 16;" :: "r"(dst), "l"(src));
}
__device__ __forceinline__ void cp_commit() { asm volatile("cp.async.commit_group;"); }
__device__ __forceinline__ void cp_wait0()  { asm volatile("cp.async.wait_group 0;"); }

#define MMA16(acc, a, b) \
    asm volatile( \
        "mma.sync.aligned.m16n8k16.row.col.f32.f16.f16.f32 " \
        "{%0,%1,%2,%3},{%4,%5,%6,%7},{%8,%9},{%0,%1,%2,%3};" \
        : "+f"((acc)[0]), "+f"((acc)[1]), "+f"((acc)[2]), "+f"((acc)[3]) \
        : "r"((a)[0]), "r"((a)[1]), "r"((a)[2]), "r"((a)[3]), \
          "r"((b)[0]), "r"((b)[1]))

#define LDSM4(r, addr) \
    asm volatile("ldmatrix.sync.aligned.m8n8.x4.shared.b16 {%0,%1,%2,%3}, [%4];" \
        : "=r"((r)[0]), "=r"((r)[1]), "=r"((r)[2]), "=r"((r)[3]) : "r"(addr))

// ---------------- fp16x3 HMMA GEMM --------------------------------------------------
// C[M,N] = A[M,K] @ Bt[N,K]^T, fp32 emulated as 2 fp16 terms, 3 pair-MMAs.
// cntp : scalar active-row bound (exit if m0 >= *cntp)     — loop GEMMs
// tilef: per-row-tile flags (exit if !tilef[ytile])        — precompute
// yoff : row-tile index offset (for chunked precompute launches)
struct ProbH { const __half *A0, *A1, *B0, *B1; float* C; };
struct GArgsH { ProbH p[3]; };

__global__ __launch_bounds__(128, 5) void gemm_f16x3(GArgsH ga, int N, int K,
                                                     const int* cntp, const int* tilef,
                                                     int yoff)
{
    const int ytile = blockIdx.y + yoff;
    const int m0 = ytile * TMC;
    if (cntp != nullptr && m0 >= *cntp) return;
    if (tilef != nullptr && tilef[ytile] == 0) return;

    extern __shared__ char smem[];
    const uint32_t sb0 = (uint32_t)__cvta_generic_to_shared(smem);

    const ProbH pr = ga.p[blockIdx.z];
    const int tid  = threadIdx.x;
    const int lane = tid & 31;
    const int wid  = tid >> 5;       // 0..3
    const int wm   = wid >> 1;       // 0..1  (32 rows each)
    const int wn   = wid & 1;        // 0..1  (32 cols each)
    const int n0   = blockIdx.x * TNC;
    const int grp  = lane >> 2;      // 0..7
    const int tg   = lane & 3;       // 0..3

    // per-lane ldmatrix offsets (x4 tile decomposition)
    const int lm = lane >> 3, lr = lane & 7;
    const uint32_t aoff = (uint32_t)((((lm & 1) * 8) + lr) * ROWB + (lm >> 1) * 16);
    const uint32_t boff = (uint32_t)((((lm >> 1) * 8) + lr) * ROWB + (lm & 1) * 16);

    // copy one BK=32 chunk: per term 64 rows x 4 granules(16B) = 256 slots,
    // 128 threads x 2 iterations.
    auto issue = [&](int stage, int k0) {
        const uint32_t sb = sb0 + (uint32_t)stage * STAGEB;
#pragma unroll
        for (int i = 0; i < 2; i++) {
            const int idx = tid + i * 128;        // 0..255
            const int r = idx >> 2, g = idx & 3;  // row, 16B granule
            const uint32_t doff = (uint32_t)(r * ROWB + g * 16);
            const size_t soffA = (size_t)(m0 + r) * K + k0 + g * 8;
            const size_t soffB = (size_t)(n0 + r) * K + k0 + g * 8;
            cp16(sb + 0 * TERMB + doff, pr.A0 + soffA);
            cp16(sb + 1 * TERMB + doff, pr.A1 + soffA);
            cp16(sb + 2 * TERMB + doff, pr.B0 + soffB);
            cp16(sb + 3 * TERMB + doff, pr.B1 + soffB);
        }
        cp_commit();
    };

    float acc[2][4][4];
#pragma unroll
    for (int i = 0; i < 2; i++)
#pragma unroll
        for (int j = 0; j < 4; j++)
#pragma unroll
            for (int k = 0; k < 4; k++) acc[i][j][k] = 0.f;

    const int NIT = K / BKC;
    issue(0, 0);

    for (int it = 0; it < NIT; ++it) {
        cp_wait0();
        __syncthreads();
        if (it + 1 < NIT) issue((it + 1) & 1, (it + 1) * BKC);

        const uint32_t sst = sb0 + (uint32_t)(it & 1) * STAGEB;
        const uint32_t aBase = sst + (uint32_t)((wm * 32) * ROWB) + aoff;
        const uint32_t bBase = sst + 2 * TERMB + (uint32_t)((wn * 32) * ROWB) + boff;

#pragma unroll
        for (int kk = 0; kk < 2; kk++) {
            uint32_t a0f[2][4], a1f[2][4], b0t[2][4], b1t[2][4];
#pragma unroll
            for (int im = 0; im < 2; im++) {
                const uint32_t ab = aBase + (uint32_t)(im * 16 * ROWB + kk * 32);
                LDSM4(a0f[im], ab);
                LDSM4(a1f[im], ab + TERMB);
            }
#pragma unroll
            for (int jp = 0; jp < 2; jp++) {
                const uint32_t bb = bBase + (uint32_t)(jp * 16 * ROWB + kk * 32);
                LDSM4(b0t[jp], bb);
                LDSM4(b1t[jp], bb + TERMB);
            }
#pragma unroll
            for (int im = 0; im < 2; im++)
#pragma unroll
                for (int jn = 0; jn < 4; jn++) {
                    const uint32_t* b0p = &b0t[jn >> 1][(jn & 1) * 2];
                    const uint32_t* b1p = &b1t[jn >> 1][(jn & 1) * 2];
                    MMA16(acc[im][jn], a1f[im], b0p);   // lo*hi
                    MMA16(acc[im][jn], a0f[im], b1p);   // hi*lo
                    MMA16(acc[im][jn], a0f[im], b0p);   // hi*hi
                }
        }
    }

    // epilogue
#pragma unroll
    for (int im = 0; im < 2; im++) {
        const int row0 = m0 + wm * 32 + im * 16 + grp;
#pragma unroll
        for (int jn = 0; jn < 4; jn++) {
            const int col = n0 + wn * 32 + jn * 8 + tg * 2;
            *(float2*)(pr.C + (size_t)row0 * N + col)       = make_float2(acc[im][jn][0], acc[im][jn][1]);
            *(float2*)(pr.C + (size_t)(row0 + 8) * N + col) = make_float2(acc[im][jn][2], acc[im][jn][3]);
        }
    }
}

// ---------------- one-time prep ------------------------------------------------------
// rank-sort rows by len desc (deterministic; tie-break original index asc)
__global__ void sort_kernel(const int* __restrict__ mask)
{
    __shared__ int len[B];
    const int b = threadIdx.x;
    int l = 0;
    for (int t = 0; t < T; t++) l += mask[b * T + t];
    len[b] = l;
    __syncthreads();
    int rank = 0;
    for (int j = 0; j < B; j++) {
        const int lj = len[j];
        rank += (lj > l) || (lj == l && j < b);
    }
    g_perm[rank] = b;
    g_plen[rank] = l;
}

// cnt[t] and per-precompute-tile activity flags
__global__ void cnt_kernel()
{
    const int tid = threadIdx.x;   // 1024 threads
    if (tid <= T) {
        int c = 0;
        for (int p = 0; p < B; p++) c += (g_plen[p] > tid);
        g_cnt[tid] = c;
    }
    __syncthreads();
    for (int i = tid; i < NTILEA; i += 1024) {
        const int t  = i >> 4;            // B/TMC = 16 tiles per t
        const int pb = i & 15;
        g_actA[i] = (pb * TMC < g_cnt[t]) ? 1 : 0;
    }
}

__global__ void wsplit2_t(const float* __restrict__ W, __half* __restrict__ t0,
                          __half* __restrict__ t1, int Kd, int N, int Ksrc)
{
    const size_t i = (size_t)blockIdx.x * 256 + threadIdx.x;
    if (i < (size_t)N * Kd) {
        const int n = (int)(i / Kd), k = (int)(i % Kd);
        const float v = (k < Ksrc) ? W[(size_t)k * N + n] : 0.f;
        __half h0, h1;
        split2(v, h0, h1);
        t0[i] = h0; t1[i] = h1;
    }
}

// x: gathered through perm, relaid to [t*B + p] rows
__global__ void xsplit2(const float* __restrict__ x, __half* __restrict__ t0,
                        __half* __restrict__ t1)
{
    const size_t i = (size_t)blockIdx.x * 256 + threadIdx.x;
    if (i < (size_t)B * T * KP) {
        const size_t r = i / KP;       // flat [t*B + p]
        const int c = (int)(i % KP);
        const int t = (int)(r / B), p = (int)(r % B);
        const float v = (c < F) ? x[((size_t)g_perm[p] * T + t) * F + c] : 0.f;
        __half h0, h1;
        split2(v, h0, h1);
        t0[i] = h0; t1[i] = h1;
    }
}

__global__ void init_kernel()
{
    const size_t i = (size_t)blockIdx.x * 256 + threadIdx.x;
    if (i < (size_t)B * G) g_z0[i] = 0.f;
    if (i < (size_t)B * U) {
        const __half z = __float2half_rn(0.f);
        g_h0sa[i] = z; g_h0sb[i] = z;
        g_h1sa[i] = z; g_h1sb[i] = z;
        g_c0[i] = 0.f; g_c1[i] = 0.f; g_out[i] = 0.f;
    }
}

// ---------------- unified cell body ----------------------------------------------------
// layer==0: za=g_z0 row, zb=g_A0[t*B+b];  layer==1: za=g_z1b row, zb=g_z1a row.
// Early-exits when row inactive (t >= plen[b]); surviving blocks write unconditionally.
__device__ void cell_body(int layer, int b, int t,
                          const float* __restrict__ gza, const float* __restrict__ bza,
                          const float* __restrict__ gzb, const float* __restrict__ bzb,
                          const float* __restrict__ sg,  const float* __restrict__ sb,
                          const float* __restrict__ bias)
{
    if (t >= g_plen[b]) return;   // uniform per block

    const int tid = threadIdx.x, lane = tid & 31, w = tid >> 5;
    const float* za = (layer == 0) ? (g_z0 + (size_t)b * G)
                                   : (g_z1b + (size_t)b * G);
    const float* zb = (layer == 0) ? (g_A0 + ((size_t)t * B + b) * G)
                                   : (g_z1a + (size_t)b * G);
    __shared__ float sh1[4][8];
    __shared__ float bc1[4];

    float va[2][4], vb[2][4];
    float s1 = 0.f, p1 = 0.f, s2 = 0.f, p2 = 0.f;
#pragma unroll
    for (int q = 0; q < 2; q++) {
        const int u = tid + q * 256;
#pragma unroll
        for (int gg = 0; gg < 4; gg++) {
            const float x1 = za[gg * U + u];
            const float x2 = zb[gg * U + u];
            va[q][gg] = x1; vb[q][gg] = x2;
            s1 += x1; p1 += x1 * x1; s2 += x2; p2 += x2 * x2;
        }
    }
#pragma unroll
    for (int o = 16; o > 0; o >>= 1) {
        s1 += __shfl_xor_sync(0xffffffffu, s1, o);
        p1 += __shfl_xor_sync(0xffffffffu, p1, o);
        s2 += __shfl_xor_sync(0xffffffffu, s2, o);
        p2 += __shfl_xor_sync(0xffffffffu, p2, o);
    }
    if (lane == 0) { sh1[0][w] = s1; sh1[1][w] = p1; sh1[2][w] = s2; sh1[3][w] = p2; }
    __syncthreads();
    if (tid == 0) {
        float S1 = 0.f, P1 = 0.f, S2 = 0.f, P2 = 0.f;
#pragma unroll
        for (int i = 0; i < 8; i++) { S1 += sh1[0][i]; P1 += sh1[1][i]; S2 += sh1[2][i]; P2 += sh1[3][i]; }
        const float m1 = S1 / (float)G, m2 = S2 / (float)G;
        bc1[0] = m1; bc1[1] = rsqrtf(P1 / (float)G - m1 * m1 + EPS);
        bc1[2] = m2; bc1[3] = rsqrtf(P2 / (float)G - m2 * m2 + EPS);
    }
    __syncthreads();
    const float m1 = bc1[0], r1 = bc1[1], m2 = bc1[2], r2 = bc1[3];

    float* cold = (layer == 0) ? g_c0 : g_c1;
    float cn[2], zo[2];
    float s3 = 0.f, p3 = 0.f;
#pragma unroll
    for (int q = 0; q < 2; q++) {
        const int u = tid + q * 256;
        float zg4[4];
#pragma unroll
        for (int gg = 0; gg < 4; gg++) {
            const int j = gg * U + u;
            zg4[gg] = (va[q][gg] - m1) * r1 * gza[j] + bza[j]
                    + (vb[q][gg] - m2) * r2 * gzb[j] + bzb[j] + bias[j];
        }
        const float c = cold[(size_t)b * U + u];
        const float v = sigmf(zg4[1]) * c + sigmf(zg4[0]) * tanhf(zg4[2]);
        cn[q] = v; zo[q] = zg4[3]; s3 += v; p3 += v * v;
    }
#pragma unroll
    for (int o = 16; o > 0; o >>= 1) {
        s3 += __shfl_xor_sync(0xffffffffu, s3, o);
        p3 += __shfl_xor_sync(0xffffffffu, p3, o);
    }
    __syncthreads();
    if (lane == 0) { sh1[0][w] = s3; sh1[1][w] = p3; }
    __syncthreads();
    if (tid == 0) {
        float S = 0.f, P = 0.f;
#pragma unroll
        for (int i = 0; i < 8; i++) { S += sh1[0][i]; P += sh1[1][i]; }
        const float m = S / (float)U;
        bc1[0] = m;
        bc1[1] = rsqrtf(P / (float)U - m * m + EPS);
    }
    __syncthreads();
    const float mc = bc1[0], rc = bc1[1];
#pragma unroll
    for (int q = 0; q < 2; q++) {
        const int u = tid + q * 256;
        const float cl = (cn[q] - mc) * rc * sg[u] + sb[u];
        const float hn = sigmf(zo[q]) * tanhf(cl);
        __half h0, h1;
        split2(hn, h0, h1);
        if (layer == 0) {
            g_h0sa[(size_t)b * U + u] = h0;
            g_h0sb[(size_t)b * U + u] = h1;
            g_c0  [(size_t)b * U + u] = cl;
        } else {
            g_h1sa[(size_t)b * U + u] = h0;
            g_h1sb[(size_t)b * U + u] = h1;
            g_c1 [(size_t)b * U + u] = cl;
            g_out[(size_t)b * U + u] = hn;
        }
    }
}

__global__ __launch_bounds__(256) void cell0_kernel(
    const float* rg, const float* rb, const float* kg, const float* kb,
    const float* sg, const float* sb, const float* bias, int t)
{
    cell_body(0, blockIdx.x, t, rg, rb, kg, kb, sg, sb, bias);
}

__global__ __launch_bounds__(256) void cell1_kernel(
    const float* kg, const float* kb, const float* rg, const float* rb,
    const float* sg, const float* sb, const float* bias, int t)
{
    cell_body(1, blockIdx.x, t, rg, rb, kg, kb, sg, sb, bias);
}

// fused: blocks [0,B) do cell1(t); blocks [B,2B) do cell0(t+1)
__global__ __launch_bounds__(256) void fused_cell_kernel(
    const float* rg0, const float* rb0, const float* kg0, const float* kb0,
    const float* sg0, const float* sb0, const float* b0,
    const float* kg1, const float* kb1, const float* rg1, const float* rb1,
    const float* sg1, const float* sb1, const float* b1, int t)
{
    if (blockIdx.x < B)
        cell_body(1, blockIdx.x, t, rg1, rb1, kg1, kb1, sg1, sb1, b1);
    else
        cell_body(0, blockIdx.x - B, t + 1, rg0, rb0, kg0, kb0, sg0, sb0, b0);
}

// ---------------- dense + softmax (scatter through perm) ------------------------------
__global__ __launch_bounds__(256) void dense_kernel(const float* __restrict__ Wd,
                                                    const float* __restrict__ bd,
                                                    float* __restrict__ out)
{
    const int b = blockIdx.x, tid = threadIdx.x, lane = tid & 31, w = tid >> 5;
    float p[NC];
#pragma unroll
    for (int c = 0; c < NC; c++) p[c] = 0.f;
    for (int u = tid; u < U; u += 256) {
        const float h = g_out[(size_t)b * U + u];
#pragma unroll
        for (int c = 0; c < NC; c++) p[c] += h * Wd[u * NC + c];
    }
    __shared__ float sh[NC][8];
#pragma unroll
    for (int c = 0; c < NC; c++) {
        float v = p[c];
#pragma unroll
        for (int o = 16; o > 0; o >>= 1) v += __shfl_xor_sync(0xffffffffu, v, o);
        if (lane == 0) sh[c][w] = v;
    }
    __syncthreads();
    if (tid == 0) {
        const int ob = g_perm[b];
        float lg[NC];
        float mx = -1e30f;
#pragma unroll
        for (int c = 0; c < NC; c++) {
            float l = bd[c];
#pragma unroll
            for (int i = 0; i < 8; i++) l += sh[c][i];
            lg[c] = l;
            mx = fmaxf(mx, l);
        }
        float sum = 0.f;
#pragma unroll
        for (int c = 0; c < NC; c++) { lg[c] = expf(lg[c] - mx); sum += lg[c]; }
        const float inv = 1.f / sum;
#pragma unroll
        for (int c = 0; c < NC; c++) out[ob * NC + c] = lg[c] * inv;
    }
}

// ---------------- launch ---------------------------------------------------------------
extern "C" void kernel_launch(void* const* d_in, const int* in_sizes, int n_in,
                              void* d_out, int out_size)
{
    const float* x    = (const float*)d_in[0];
    const int*   mask = (const int*)  d_in[1];
    const float* W0   = (const float*)d_in[2];
    const float* b0   = (const float*)d_in[4];
    const float* R0   = (const float*)d_in[3];
    const float* kg0  = (const float*)d_in[5];
    const float* kb0  = (const float*)d_in[6];
    const float* rg0  = (const float*)d_in[7];
    const float* rb0  = (const float*)d_in[8];
    const float* sg0  = (const float*)d_in[9];
    const float* sb0  = (const float*)d_in[10];
    const float* W1   = (const float*)d_in[11];
    const float* R1   = (const float*)d_in[12];
    const float* b1   = (const float*)d_in[13];
    const float* kg1  = (const float*)d_in[14];
    const float* kb1  = (const float*)d_in[15];
    const float* rg1  = (const float*)d_in[16];
    const float* rb1  = (const float*)d_in[17];
    const float* sg1  = (const float*)d_in[18];
    const float* sb1  = (const float*)d_in[19];
    const float* Wd   = (const float*)d_in[20];
    const float* bd   = (const float*)d_in[21];
    float* out = (float*)d_out;

    float *A0p, *z0p, *z1ap, *z1bp;
    __half *x0, *x1, *W0a, *W0b, *R0a, *R0b, *W1a, *W1b, *R1a, *R1b;
    __half *h0sa, *h0sb, *h1sa, *h1sb;
    int *cntp, *actAp;
    cudaGetSymbolAddress((void**)&A0p,  g_A0);
    cudaGetSymbolAddress((void**)&z0p,  g_z0);
    cudaGetSymbolAddress((void**)&z1ap, g_z1a);
    cudaGetSymbolAddress((void**)&z1bp, g_z1b);
    cudaGetSymbolAddress((void**)&x0,   g_x0);
    cudaGetSymbolAddress((void**)&x1,   g_x1);
    cudaGetSymbolAddress((void**)&W0a,  g_W0a);
    cudaGetSymbolAddress((void**)&W0b,  g_W0b);
    cudaGetSymbolAddress((void**)&R0a,  g_R0a);
    cudaGetSymbolAddress((void**)&R0b,  g_R0b);
    cudaGetSymbolAddress((void**)&W1a,  g_W1a);
    cudaGetSymbolAddress((void**)&W1b,  g_W1b);
    cudaGetSymbolAddress((void**)&R1a,  g_R1a);
    cudaGetSymbolAddress((void**)&R1b,  g_R1b);
    cudaGetSymbolAddress((void**)&h0sa, g_h0sa);
    cudaGetSymbolAddress((void**)&h0sb, g_h0sb);
    cudaGetSymbolAddress((void**)&h1sa, g_h1sa);
    cudaGetSymbolAddress((void**)&h1sb, g_h1sb);
    cudaGetSymbolAddress((void**)&cntp, g_cnt);
    cudaGetSymbolAddress((void**)&actAp, g_actA);

    cudaFuncSetAttribute(gemm_f16x3, cudaFuncAttributeMaxDynamicSharedMemorySize, SMEM_H);

    // lazy-init second stream + events (handles only; no device memory)
    static cudaStream_t s2 = nullptr;
    static cudaEvent_t evFork = nullptr;
    static cudaEvent_t evChunk[NCHUNK];
    if (s2 == nullptr) {
        cudaStreamCreateWithFlags(&s2, cudaStreamNonBlocking);
        cudaEventCreateWithFlags(&evFork, cudaEventDisableTiming);
        for (int k = 0; k < NCHUNK; k++)
            cudaEventCreateWithFlags(&evChunk[k], cudaEventDisableTiming);
    }

    // one-time prep (main stream)
    const size_t nW0 = (size_t)G * KP;
    const size_t nRW = (size_t)G * U;
    const size_t nXT = (size_t)B * T * KP;
    init_kernel<<<(B * G + 255) / 256, 256>>>();
    sort_kernel<<<1, B>>>(mask);
    cnt_kernel<<<1, 1024>>>();
    wsplit2_t<<<(unsigned)((nW0 + 255) / 256), 256>>>(W0, W0a, W0b, KP, G, F);
    xsplit2<<<(unsigned)((nXT + 255) / 256), 256>>>(x, x0, x1);

    // fork: precompute A0 chunks on s2 (needs x splits, W0 splits, actA)
    cudaEventRecord(evFork, 0);
    cudaStreamWaitEvent(s2, evFork, 0);
    for (int k = 0; k < NCHUNK; k++) {
        GArgsH a = {};
        a.p[0] = { x0, x1, W0a, W0b, A0p };
        gemm_f16x3<<<dim3(G / TNC, CH_TILES, 1), 128, SMEM_H, s2>>>(
            a, G, KP, nullptr, actAp, k * CH_TILES);
        cudaEventRecord(evChunk[k], s2);
    }

    // remaining weight splits on main stream (overlap with first A0 chunks)
    wsplit2_t<<<(unsigned)((nRW + 255) / 256), 256>>>(R0, R0a, R0b, U, G, U);
    wsplit2_t<<<(unsigned)((nRW + 255) / 256), 256>>>(W1, W1a, W1b, U, G, U);
    wsplit2_t<<<(unsigned)((nRW + 255) / 256), 256>>>(R1, R1a, R1b, U, G, U);

    // t = 0 prolog needs A0 chunk 0
    cudaStreamWaitEvent(0, evChunk[0], 0);
    cell0_kernel<<<B, 256>>>(rg0, rb0, kg0, kb0, sg0, sb0, b0, 0);

    for (int t = 0; t < T - 1; t++) {
        GArgsH a = {};
        a.p[0] = { h0sa, h0sb, W1a, W1b, z1ap };   // z1a(t)
        a.p[1] = { h1sa, h1sb, R1a, R1b, z1bp };   // z1b(t)
        a.p[2] = { h0sa, h0sb, R0a, R0b, z0p  };   // z0(t+1)
        gemm_f16x3<<<dim3(G / TNC, B / TMC, 3), 128, SMEM_H>>>(a, G, U, cntp + t, nullptr, 0);
        // fused cell runs cell0(t+1): ensure A0 chunk (t+1)/10 is ready
        if ((t + 1) % (T / NCHUNK) == 0)
            cudaStreamWaitEvent(0, evChunk[(t + 1) / (T / NCHUNK)], 0);
        fused_cell_kernel<<<2 * B, 256>>>(rg0, rb0, kg0, kb0, sg0, sb0, b0,
                                          kg1, kb1, rg1, rb1, sg1, sb1, b1, t);
    }

    // t = T-1 epilog
    {
        GArgsH a = {};
        a.p[0] = { h0sa, h0sb, W1a, W1b, z1ap };
        a.p[1] = { h1sa, h1sb, R1a, R1b, z1bp };
        gemm_f16x3<<<dim3(G / TNC, B / TMC, 2), 128, SMEM_H>>>(a, G, U, cntp + (T - 1), nullptr, 0);
        cell1_kernel<<<B, 256>>>(kg1, kb1, rg1, rb1, sg1, sb1, b1, T - 1);
    }

    dense_kernel<<<B, 256>>>(Wd, bd, out);
}

// round 15
// speedup vs baseline: 1.8496x; 1.0727x over previous
#include <cuda_runtime.h>
#include <cuda_fp16.h>
#include <cstdint>

#define B  1024
#define T  100
#define F  300
#define KP 320     /* F padded to 32-multiple */
#define U  512
#define G  2048    /* 4*U */
#define NC 10
#define EPS 1e-3f

// ---- fp16x3 HMMA GEMM config: fine 64x64 tiles for SM load balance ----
#define TMC 64
#define TNC 64
#define BKC 32
#define LDAH 40                       /* padded fp16 stride (conflict-free) */
#define ROWB (LDAH * 2)               /* 80 B row stride */
#define TERMB (TMC * ROWB)            /* 5120 B per operand term tile */
#define STAGEB (4 * TERMB)            /* A0,A1,B0,B1 = 20480 B */
#define SMEM_H (2 * STAGEB)           /* 40960 B */
#define NTILEA ((B * T) / TMC)        /* 1600 precompute row-tiles */
#define NCHUNK 10                     /* precompute chunks (10 timesteps each) */
#define CH_TILES (NTILEA / NCHUNK)    /* 160 row-tiles per chunk */

// ---------------- device scratch ---------------------------------------------------
// batch-indexed arrays live in PERMUTED row order (sorted by len desc)
// A0 and x-splits live in [t*B + p] row order (tile == single t)
__device__ __align__(16) float g_A0[(size_t)B * T * G];
__device__ __align__(16) __half g_x0[(size_t)B * T * KP], g_x1[(size_t)B * T * KP];
__device__ __align__(16) __half g_W0a[(size_t)G * KP], g_W0b[(size_t)G * KP];
__device__ __align__(16) __half g_R0a[(size_t)G * U],  g_R0b[(size_t)G * U];
__device__ __align__(16) __half g_W1a[(size_t)G * U],  g_W1b[(size_t)G * U];
__device__ __align__(16) __half g_R1a[(size_t)G * U],  g_R1b[(size_t)G * U];
__device__ __align__(16) float g_z0[B * G], g_z1a[B * G], g_z1b[B * G];
__device__ __align__(16) __half g_h0sa[B * U], g_h0sb[B * U];
__device__ __align__(16) __half g_h1sa[B * U], g_h1sb[B * U];
__device__ __align__(16) float g_c0[B * U], g_c1[B * U], g_out[B * U];
__device__ int g_perm[B];        // permuted p -> original b
__device__ int g_plen[B];        // len of permuted row p (descending)
__device__ int g_cnt[T + 1];     // cnt[t] = #rows with len > t
__device__ int g_actA[NTILEA];   // precompute tile flags

__device__ __forceinline__ float sigmf(float x) { return 1.0f / (1.0f + expf(-x)); }

__device__ __forceinline__ void split2(float v, __half& h0, __half& h1)
{
    h0 = __float2half_rn(v);
    h1 = __float2half_rn(v - __half2float(h0));
}

__device__ __forceinline__ void cp16(uint32_t dst, const void* src) {
    asm volatile("cp.async.cg.shared.global [%0], [%1], 16;" :: "r"(dst), "l"(src));
}
__device__ __forceinline__ void cp_commit() { asm volatile("cp.async.commit_group;"); }
__device__ __forceinline__ void cp_wait0()  { asm volatile("cp.async.wait_group 0;"); }

#define MMA16(acc, a, b) \
    asm volatile( \
        "mma.sync.aligned.m16n8k16.row.col.f32.f16.f16.f32 " \
        "{%0,%1,%2,%3},{%4,%5,%6,%7},{%8,%9},{%0,%1,%2,%3};" \
        : "+f"((acc)[0]), "+f"((acc)[1]), "+f"((acc)[2]), "+f"((acc)[3]) \
        : "r"((a)[0]), "r"((a)[1]), "r"((a)[2]), "r"((a)[3]), \
          "r"((b)[0]), "r"((b)[1]))

#define LDSM4(r, addr) \
    asm volatile("ldmatrix.sync.aligned.m8n8.x4.shared.b16 {%0,%1,%2,%3}, [%4];" \
        : "=r"((r)[0]), "=r"((r)[1]), "=r"((r)[2]), "=r"((r)[3]) : "r"(addr))

// ---------------- fp16x3 HMMA GEMM --------------------------------------------------
// C[M,N] = A[M,K] @ Bt[N,K]^T, fp32 emulated as 2 fp16 terms, 3 pair-MMAs.
// cntp : scalar active-row bound (exit if m0 >= *cntp)     — loop GEMMs
// tilef: per-row-tile flags (exit if !tilef[ytile])        — precompute
// yoff : row-tile index offset (for chunked precompute launches)
struct ProbH { const __half *A0, *A1, *B0, *B1; float* C; };
struct GArgsH { ProbH p[2]; };

__global__ __launch_bounds__(128, 5) void gemm_f16x3(GArgsH ga, int N, int K,
                                                     const int* cntp, const int* tilef,
                                                     int yoff)
{
    const int ytile = blockIdx.y + yoff;
    const int m0 = ytile * TMC;
    if (cntp != nullptr && m0 >= *cntp) return;
    if (tilef != nullptr && tilef[ytile] == 0) return;

    extern __shared__ char smem[];
    const uint32_t sb0 = (uint32_t)__cvta_generic_to_shared(smem);

    const ProbH pr = ga.p[blockIdx.z];
    const int tid  = threadIdx.x;
    const int lane = tid & 31;
    const int wid  = tid >> 5;       // 0..3
    const int wm   = wid >> 1;       // 0..1  (32 rows each)
    const int wn   = wid & 1;        // 0..1  (32 cols each)
    const int n0   = blockIdx.x * TNC;
    const int grp  = lane >> 2;      // 0..7
    const int tg   = lane & 3;       // 0..3

    // per-lane ldmatrix offsets (x4 tile decomposition)
    const int lm = lane >> 3, lr = lane & 7;
    const uint32_t aoff = (uint32_t)((((lm & 1) * 8) + lr) * ROWB + (lm >> 1) * 16);
    const uint32_t boff = (uint32_t)((((lm >> 1) * 8) + lr) * ROWB + (lm & 1) * 16);

    // copy one BK=32 chunk: per term 64 rows x 4 granules(16B) = 256 slots,
    // 128 threads x 2 iterations.
    auto issue = [&](int stage, int k0) {
        const uint32_t sb = sb0 + (uint32_t)stage * STAGEB;
#pragma unroll
        for (int i = 0; i < 2; i++) {
            const int idx = tid + i * 128;        // 0..255
            const int r = idx >> 2, g = idx & 3;  // row, 16B granule
            const uint32_t doff = (uint32_t)(r * ROWB + g * 16);
            const size_t soffA = (size_t)(m0 + r) * K + k0 + g * 8;
            const size_t soffB = (size_t)(n0 + r) * K + k0 + g * 8;
            cp16(sb + 0 * TERMB + doff, pr.A0 + soffA);
            cp16(sb + 1 * TERMB + doff, pr.A1 + soffA);
            cp16(sb + 2 * TERMB + doff, pr.B0 + soffB);
            cp16(sb + 3 * TERMB + doff, pr.B1 + soffB);
        }
        cp_commit();
    };

    float acc[2][4][4];
#pragma unroll
    for (int i = 0; i < 2; i++)
#pragma unroll
        for (int j = 0; j < 4; j++)
#pragma unroll
            for (int k = 0; k < 4; k++) acc[i][j][k] = 0.f;

    const int NIT = K / BKC;
    issue(0, 0);

    for (int it = 0; it < NIT; ++it) {
        cp_wait0();
        __syncthreads();
        if (it + 1 < NIT) issue((it + 1) & 1, (it + 1) * BKC);

        const uint32_t sst = sb0 + (uint32_t)(it & 1) * STAGEB;
        const uint32_t aBase = sst + (uint32_t)((wm * 32) * ROWB) + aoff;
        const uint32_t bBase = sst + 2 * TERMB + (uint32_t)((wn * 32) * ROWB) + boff;

#pragma unroll
        for (int kk = 0; kk < 2; kk++) {
            uint32_t a0f[2][4], a1f[2][4], b0t[2][4], b1t[2][4];
#pragma unroll
            for (int im = 0; im < 2; im++) {
                const uint32_t ab = aBase + (uint32_t)(im * 16 * ROWB + kk * 32);
                LDSM4(a0f[im], ab);
                LDSM4(a1f[im], ab + TERMB);
            }
#pragma unroll
            for (int jp = 0; jp < 2; jp++) {
                const uint32_t bb = bBase + (uint32_t)(jp * 16 * ROWB + kk * 32);
                LDSM4(b0t[jp], bb);
                LDSM4(b1t[jp], bb + TERMB);
            }
#pragma unroll
            for (int im = 0; im < 2; im++)
#pragma unroll
                for (int jn = 0; jn < 4; jn++) {
                    const uint32_t* b0p = &b0t[jn >> 1][(jn & 1) * 2];
                    const uint32_t* b1p = &b1t[jn >> 1][(jn & 1) * 2];
                    MMA16(acc[im][jn], a1f[im], b0p);   // lo*hi
                    MMA16(acc[im][jn], a0f[im], b1p);   // hi*lo
                    MMA16(acc[im][jn], a0f[im], b0p);   // hi*hi
                }
        }
    }

    // epilogue
#pragma unroll
    for (int im = 0; im < 2; im++) {
        const int row0 = m0 + wm * 32 + im * 16 + grp;
#pragma unroll
        for (int jn = 0; jn < 4; jn++) {
            const int col = n0 + wn * 32 + jn * 8 + tg * 2;
            *(float2*)(pr.C + (size_t)row0 * N + col)       = make_float2(acc[im][jn][0], acc[im][jn][1]);
            *(float2*)(pr.C + (size_t)(row0 + 8) * N + col) = make_float2(acc[im][jn][2], acc[im][jn][3]);
        }
    }
}

// ---------------- one-time prep ------------------------------------------------------
// rank-sort rows by len desc (deterministic; tie-break original index asc)
__global__ void sort_kernel(const int* __restrict__ mask)
{
    __shared__ int len[B];
    const int b = threadIdx.x;
    int l = 0;
    for (int t = 0; t < T; t++) l += mask[b * T + t];
    len[b] = l;
    __syncthreads();
    int rank = 0;
    for (int j = 0; j < B; j++) {
        const int lj = len[j];
        rank += (lj > l) || (lj == l && j < b);
    }
    g_perm[rank] = b;
    g_plen[rank] = l;
}

// cnt[t] and per-precompute-tile activity flags
__global__ void cnt_kernel()
{
    const int tid = threadIdx.x;   // 1024 threads
    if (tid <= T) {
        int c = 0;
        for (int p = 0; p < B; p++) c += (g_plen[p] > tid);
        g_cnt[tid] = c;
    }
    __syncthreads();
    for (int i = tid; i < NTILEA; i += 1024) {
        const int t  = i >> 4;            // B/TMC = 16 tiles per t
        const int pb = i & 15;
        g_actA[i] = (pb * TMC < g_cnt[t]) ? 1 : 0;
    }
}

__global__ void wsplit2_t(const float* __restrict__ W, __half* __restrict__ t0,
                          __half* __restrict__ t1, int Kd, int N, int Ksrc)
{
    const size_t i = (size_t)blockIdx.x * 256 + threadIdx.x;
    if (i < (size_t)N * Kd) {
        const int n = (int)(i / Kd), k = (int)(i % Kd);
        const float v = (k < Ksrc) ? W[(size_t)k * N + n] : 0.f;
        __half h0, h1;
        split2(v, h0, h1);
        t0[i] = h0; t1[i] = h1;
    }
}

// x: gathered through perm, relaid to [t*B + p] rows
__global__ void xsplit2(const float* __restrict__ x, __half* __restrict__ t0,
                        __half* __restrict__ t1)
{
    const size_t i = (size_t)blockIdx.x * 256 + threadIdx.x;
    if (i < (size_t)B * T * KP) {
        const size_t r = i / KP;       // flat [t*B + p]
        const int c = (int)(i % KP);
        const int t = (int)(r / B), p = (int)(r % B);
        const float v = (c < F) ? x[((size_t)g_perm[p] * T + t) * F + c] : 0.f;
        __half h0, h1;
        split2(v, h0, h1);
        t0[i] = h0; t1[i] = h1;
    }
}

__global__ void init_kernel()
{
    const size_t i = (size_t)blockIdx.x * 256 + threadIdx.x;
    if (i < (size_t)B * G) g_z0[i] = 0.f;
    if (i < (size_t)B * U) {
        const __half z = __float2half_rn(0.f);
        g_h0sa[i] = z; g_h0sb[i] = z;
        g_h1sa[i] = z; g_h1sb[i] = z;
        g_c0[i] = 0.f; g_c1[i] = 0.f; g_out[i] = 0.f;
    }
}

// ---------------- unified cell body ----------------------------------------------------
// layer==0: za=g_z0 row, zb=g_A0[t*B+b];  layer==1: za=g_z1b row, zb=g_z1a row.
// Early-exits when row inactive (t >= plen[b]); surviving blocks write unconditionally.
__device__ void cell_body(int layer, int b, int t,
                          const float* __restrict__ gza, const float* __restrict__ bza,
                          const float* __restrict__ gzb, const float* __restrict__ bzb,
                          const float* __restrict__ sg,  const float* __restrict__ sb,
                          const float* __restrict__ bias)
{
    if (t >= g_plen[b]) return;   // uniform per block

    const int tid = threadIdx.x, lane = tid & 31, w = tid >> 5;
    const float* za = (layer == 0) ? (g_z0 + (size_t)b * G)
                                   : (g_z1b + (size_t)b * G);
    const float* zb = (layer == 0) ? (g_A0 + ((size_t)t * B + b) * G)
                                   : (g_z1a + (size_t)b * G);
    __shared__ float sh1[4][8];
    __shared__ float bc1[4];

    float va[2][4], vb[2][4];
    float s1 = 0.f, p1 = 0.f, s2 = 0.f, p2 = 0.f;
#pragma unroll
    for (int q = 0; q < 2; q++) {
        const int u = tid + q * 256;
#pragma unroll
        for (int gg = 0; gg < 4; gg++) {
            const float x1 = za[gg * U + u];
            const float x2 = zb[gg * U + u];
            va[q][gg] = x1; vb[q][gg] = x2;
            s1 += x1; p1 += x1 * x1; s2 += x2; p2 += x2 * x2;
        }
    }
#pragma unroll
    for (int o = 16; o > 0; o >>= 1) {
        s1 += __shfl_xor_sync(0xffffffffu, s1, o);
        p1 += __shfl_xor_sync(0xffffffffu, p1, o);
        s2 += __shfl_xor_sync(0xffffffffu, s2, o);
        p2 += __shfl_xor_sync(0xffffffffu, p2, o);
    }
    if (lane == 0) { sh1[0][w] = s1; sh1[1][w] = p1; sh1[2][w] = s2; sh1[3][w] = p2; }
    __syncthreads();
    if (tid == 0) {
        float S1 = 0.f, P1 = 0.f, S2 = 0.f, P2 = 0.f;
#pragma unroll
        for (int i = 0; i < 8; i++) { S1 += sh1[0][i]; P1 += sh1[1][i]; S2 += sh1[2][i]; P2 += sh1[3][i]; }
        const float m1 = S1 / (float)G, m2 = S2 / (float)G;
        bc1[0] = m1; bc1[1] = rsqrtf(P1 / (float)G - m1 * m1 + EPS);
        bc1[2] = m2; bc1[3] = rsqrtf(P2 / (float)G - m2 * m2 + EPS);
    }
    __syncthreads();
    const float m1 = bc1[0], r1 = bc1[1], m2 = bc1[2], r2 = bc1[3];

    float* cold = (layer == 0) ? g_c0 : g_c1;
    float cn[2], zo[2];
    float s3 = 0.f, p3 = 0.f;
#pragma unroll
    for (int q = 0; q < 2; q++) {
        const int u = tid + q * 256;
        float zg4[4];
#pragma unroll
        for (int gg = 0; gg < 4; gg++) {
            const int j = gg * U + u;
            zg4[gg] = (va[q][gg] - m1) * r1 * gza[j] + bza[j]
                    + (vb[q][gg] - m2) * r2 * gzb[j] + bzb[j] + bias[j];
        }
        const float c = cold[(size_t)b * U + u];
        const float v = sigmf(zg4[1]) * c + sigmf(zg4[0]) * tanhf(zg4[2]);
        cn[q] = v; zo[q] = zg4[3]; s3 += v; p3 += v * v;
    }
#pragma unroll
    for (int o = 16; o > 0; o >>= 1) {
        s3 += __shfl_xor_sync(0xffffffffu, s3, o);
        p3 += __shfl_xor_sync(0xffffffffu, p3, o);
    }
    __syncthreads();
    if (lane == 0) { sh1[0][w] = s3; sh1[1][w] = p3; }
    __syncthreads();
    if (tid == 0) {
        float S = 0.f, P = 0.f;
#pragma unroll
        for (int i = 0; i < 8; i++) { S += sh1[0][i]; P += sh1[1][i]; }
        const float m = S / (float)U;
        bc1[0] = m;
        bc1[1] = rsqrtf(P / (float)U - m * m + EPS);
    }
    __syncthreads();
    const float mc = bc1[0], rc = bc1[1];
#pragma unroll
    for (int q = 0; q < 2; q++) {
        const int u = tid + q * 256;
        const float cl = (cn[q] - mc) * rc * sg[u] + sb[u];
        const float hn = sigmf(zo[q]) * tanhf(cl);
        __half h0, h1;
        split2(hn, h0, h1);
        if (layer == 0) {
            g_h0sa[(size_t)b * U + u] = h0;
            g_h0sb[(size_t)b * U + u] = h1;
            g_c0  [(size_t)b * U + u] = cl;
        } else {
            g_h1sa[(size_t)b * U + u] = h0;
            g_h1sb[(size_t)b * U + u] = h1;
            g_c1 [(size_t)b * U + u] = cl;
            g_out[(size_t)b * U + u] = hn;
        }
    }
}

__global__ __launch_bounds__(256) void cell0_kernel(
    const float* rg, const float* rb, const float* kg, const float* kb,
    const float* sg, const float* sb, const float* bias, int t)
{
    cell_body(0, blockIdx.x, t, rg, rb, kg, kb, sg, sb, bias);
}

__global__ __launch_bounds__(256) void cell1_kernel(
    const float* kg, const float* kb, const float* rg, const float* rb,
    const float* sg, const float* sb, const float* bias, int t)
{
    cell_body(1, blockIdx.x, t, rg, rb, kg, kb, sg, sb, bias);
}

// ---------------- dense + softmax (scatter through perm) ------------------------------
__global__ __launch_bounds__(256) void dense_kernel(const float* __restrict__ Wd,
                                                    const float* __restrict__ bd,
                                                    float* __restrict__ out)
{
    const int b = blockIdx.x, tid = threadIdx.x, lane = tid & 31, w = tid >> 5;
    float p[NC];
#pragma unroll
    for (int c = 0; c < NC; c++) p[c] = 0.f;
    for (int u = tid; u < U; u += 256) {
        const float h = g_out[(size_t)b * U + u];
#pragma unroll
        for (int c = 0; c < NC; c++) p[c] += h * Wd[u * NC + c];
    }
    __shared__ float sh[NC][8];
#pragma unroll
    for (int c = 0; c < NC; c++) {
        float v = p[c];
#pragma unroll
        for (int o = 16; o > 0; o >>= 1) v += __shfl_xor_sync(0xffffffffu, v, o);
        if (lane == 0) sh[c][w] = v;
    }
    __syncthreads();
    if (tid == 0) {
        const int ob = g_perm[b];
        float lg[NC];
        float mx = -1e30f;
#pragma unroll
        for (int c = 0; c < NC; c++) {
            float l = bd[c];
#pragma unroll
            for (int i = 0; i < 8; i++) l += sh[c][i];
            lg[c] = l;
            mx = fmaxf(mx, l);
        }
        float sum = 0.f;
#pragma unroll
        for (int c = 0; c < NC; c++) { lg[c] = expf(lg[c] - mx); sum += lg[c]; }
        const float inv = 1.f / sum;
#pragma unroll
        for (int c = 0; c < NC; c++) out[ob * NC + c] = lg[c] * inv;
    }
}

// ---------------- launch ---------------------------------------------------------------
extern "C" void kernel_launch(void* const* d_in, const int* in_sizes, int n_in,
                              void* d_out, int out_size)
{
    const float* x    = (const float*)d_in[0];
    const int*   mask = (const int*)  d_in[1];
    const float* W0   = (const float*)d_in[2];
    const float* R0   = (const float*)d_in[3];
    const float* b0   = (const float*)d_in[4];
    const float* kg0  = (const float*)d_in[5];
    const float* kb0  = (const float*)d_in[6];
    const float* rg0  = (const float*)d_in[7];
    const float* rb0  = (const float*)d_in[8];
    const float* sg0  = (const float*)d_in[9];
    const float* sb0  = (const float*)d_in[10];
    const float* W1   = (const float*)d_in[11];
    const float* R1   = (const float*)d_in[12];
    const float* b1   = (const float*)d_in[13];
    const float* kg1  = (const float*)d_in[14];
    const float* kb1  = (const float*)d_in[15];
    const float* rg1  = (const float*)d_in[16];
    const float* rb1  = (const float*)d_in[17];
    const float* sg1  = (const float*)d_in[18];
    const float* sb1  = (const float*)d_in[19];
    const float* Wd   = (const float*)d_in[20];
    const float* bd   = (const float*)d_in[21];
    float* out = (float*)d_out;

    float *A0p, *z0p, *z1ap, *z1bp;
    __half *x0, *x1, *W0a, *W0b, *R0a, *R0b, *W1a, *W1b, *R1a, *R1b;
    __half *h0sa, *h0sb, *h1sa, *h1sb;
    int *cntp, *actAp;
    cudaGetSymbolAddress((void**)&A0p,  g_A0);
    cudaGetSymbolAddress((void**)&z0p,  g_z0);
    cudaGetSymbolAddress((void**)&z1ap, g_z1a);
    cudaGetSymbolAddress((void**)&z1bp, g_z1b);
    cudaGetSymbolAddress((void**)&x0,   g_x0);
    cudaGetSymbolAddress((void**)&x1,   g_x1);
    cudaGetSymbolAddress((void**)&W0a,  g_W0a);
    cudaGetSymbolAddress((void**)&W0b,  g_W0b);
    cudaGetSymbolAddress((void**)&R0a,  g_R0a);
    cudaGetSymbolAddress((void**)&R0b,  g_R0b);
    cudaGetSymbolAddress((void**)&W1a,  g_W1a);
    cudaGetSymbolAddress((void**)&W1b,  g_W1b);
    cudaGetSymbolAddress((void**)&R1a,  g_R1a);
    cudaGetSymbolAddress((void**)&R1b,  g_R1b);
    cudaGetSymbolAddress((void**)&h0sa, g_h0sa);
    cudaGetSymbolAddress((void**)&h0sb, g_h0sb);
    cudaGetSymbolAddress((void**)&h1sa, g_h1sa);
    cudaGetSymbolAddress((void**)&h1sb, g_h1sb);
    cudaGetSymbolAddress((void**)&cntp, g_cnt);
    cudaGetSymbolAddress((void**)&actAp, g_actA);

    cudaFuncSetAttribute(gemm_f16x3, cudaFuncAttributeMaxDynamicSharedMemorySize, SMEM_H);

    // lazy-init streams + events (handles only; no device memory)
    static cudaStream_t s2 = nullptr, s3 = nullptr;
    static cudaEvent_t evFork = nullptr, evC1 = nullptr;
    static cudaEvent_t evChunk[NCHUNK];
    static cudaEvent_t evC0[T];     // after cell0(t)
    static cudaEvent_t evGB[T];     // after gemmB(t) (read of h0s(t) complete)
    if (s2 == nullptr) {
        cudaStreamCreateWithFlags(&s2, cudaStreamNonBlocking);
        cudaStreamCreateWithFlags(&s3, cudaStreamNonBlocking);
        cudaEventCreateWithFlags(&evFork, cudaEventDisableTiming);
        cudaEventCreateWithFlags(&evC1, cudaEventDisableTiming);
        for (int k = 0; k < NCHUNK; k++)
            cudaEventCreateWithFlags(&evChunk[k], cudaEventDisableTiming);
        for (int t = 0; t < T; t++) {
            cudaEventCreateWithFlags(&evC0[t], cudaEventDisableTiming);
            cudaEventCreateWithFlags(&evGB[t], cudaEventDisableTiming);
        }
    }

    // one-time prep (main stream = layer-0 chain)
    const size_t nW0 = (size_t)G * KP;
    const size_t nRW = (size_t)G * U;
    const size_t nXT = (size_t)B * T * KP;
    init_kernel<<<(B * G + 255) / 256, 256>>>();
    sort_kernel<<<1, B>>>(mask);
    cnt_kernel<<<1, 1024>>>();
    wsplit2_t<<<(unsigned)((nW0 + 255) / 256), 256>>>(W0, W0a, W0b, KP, G, F);
    xsplit2<<<(unsigned)((nXT + 255) / 256), 256>>>(x, x0, x1);

    // fork: precompute A0 chunks on s3 (needs x splits, W0 splits, actA)
    cudaEventRecord(evFork, 0);
    cudaStreamWaitEvent(s3, evFork, 0);
    for (int k = 0; k < NCHUNK; k++) {
        GArgsH a = {};
        a.p[0] = { x0, x1, W0a, W0b, A0p };
        gemm_f16x3<<<dim3(G / TNC, CH_TILES, 1), 128, SMEM_H, s3>>>(
            a, G, KP, nullptr, actAp, k * CH_TILES);
        cudaEventRecord(evChunk[k], s3);
    }

    // remaining weight splits on main stream
    wsplit2_t<<<(unsigned)((nRW + 255) / 256), 256>>>(R0, R0a, R0b, U, G, U);
    wsplit2_t<<<(unsigned)((nRW + 255) / 256), 256>>>(W1, W1a, W1b, U, G, U);
    wsplit2_t<<<(unsigned)((nRW + 255) / 256), 256>>>(R1, R1a, R1b, U, G, U);

    // t = 0 prolog on s1 (z0(0) == 0; all rows active at t=0 since len >= 1)
    cudaStreamWaitEvent(0, evChunk[0], 0);
    cell0_kernel<<<B, 256>>>(rg0, rb0, kg0, kb0, sg0, sb0, b0, 0);
    cudaEventRecord(evC0[0], 0);

    for (int t = 0; t < T; t++) {
        // --- layer-1 chain on s2: z1a(t), z1b(t) then cell1(t) ---
        cudaStreamWaitEvent(s2, evC0[t], 0);
        {
            GArgsH bargs = {};
            bargs.p[0] = { h0sa, h0sb, W1a, W1b, z1ap };
            bargs.p[1] = { h1sa, h1sb, R1a, R1b, z1bp };
            gemm_f16x3<<<dim3(G / TNC, B / TMC, 2), 128, SMEM_H, s2>>>(
                bargs, G, U, cntp + t, nullptr, 0);
        }
        cudaEventRecord(evGB[t], s2);
        cell1_kernel<<<B, 256, 0, s2>>>(kg1, kb1, rg1, rb1, sg1, sb1, b1, t);
        if (t == T - 1) cudaEventRecord(evC1, s2);

        // --- layer-0 chain on s1: z0(t+1) then cell0(t+1) ---
        if (t + 1 < T) {
            GArgsH aargs = {};
            aargs.p[0] = { h0sa, h0sb, R0a, R0b, z0p };
            gemm_f16x3<<<dim3(G / TNC, B / TMC, 1), 128, SMEM_H>>>(
                aargs, G, U, cntp + (t + 1), nullptr, 0);
            if ((t + 1) % (T / NCHUNK) == 0)
                cudaStreamWaitEvent(0, evChunk[(t + 1) / (T / NCHUNK)], 0);
            cudaStreamWaitEvent(0, evGB[t], 0);   // gemmB(t) has read h0s(t)
            cell0_kernel<<<B, 256>>>(rg0, rb0, kg0, kb0, sg0, sb0, b0, t + 1);
            cudaEventRecord(evC0[t + 1], 0);
        }
    }

    // dense on s1 after final cell1
    cudaStreamWaitEvent(0, evC1, 0);
    dense_kernel<<<B, 256>>>(Wd, bd, out);
}

// round 16
// speedup vs baseline: 1.8878x; 1.0207x over previous
#include <cuda_runtime.h>
#include <cuda_fp16.h>
#include <cstdint>

#define B  1024
#define T  100
#define F  300
#define KP 320     /* F padded to 32-multiple */
#define U  512
#define G  2048    /* 4*U */
#define NC 10
#define EPS 1e-3f

// ---- fp16x3 HMMA GEMM config: fine 64x64 tiles for SM load balance ----
#define TMC 64
#define TNC 64
#define BKC 32
#define LDAH 40                       /* padded fp16 stride (conflict-free) */
#define ROWB (LDAH * 2)               /* 80 B row stride */
#define TERMB (TMC * ROWB)            /* 5120 B per operand term tile */
#define STAGEB (4 * TERMB)            /* A0,A1,B0,B1 = 20480 B */
#define SMEM_H (2 * STAGEB)           /* 40960 B */
#define NTILEA ((B * T) / TMC)        /* 1600 precompute row-tiles */
#define NCHUNK 10                     /* precompute chunks (10 timesteps each) */
#define CH_TILES (NTILEA / NCHUNK)    /* 160 row-tiles per chunk */

// ---------------- device scratch ---------------------------------------------------
// batch-indexed arrays live in PERMUTED row order (sorted by len desc)
// A0 and x-splits live in [t*B + p] row order (tile == single t)
__device__ __align__(16) float g_A0[(size_t)B * T * G];
__device__ __align__(16) __half g_x0[(size_t)B * T * KP], g_x1[(size_t)B * T * KP];
__device__ __align__(16) __half g_W0a[(size_t)G * KP], g_W0b[(size_t)G * KP];
__device__ __align__(16) __half g_R0a[(size_t)G * U],  g_R0b[(size_t)G * U];
__device__ __align__(16) __half g_W1a[(size_t)G * U],  g_W1b[(size_t)G * U];
__device__ __align__(16) __half g_R1a[(size_t)G * U],  g_R1b[(size_t)G * U];
__device__ __align__(16) float g_z0[B * G];
__device__ __align__(16) float g_z1a[2][B * G];   // parity double buffer
__device__ __align__(16) float g_z1b[B * G];
__device__ __align__(16) __half g_h0sa[B * U], g_h0sb[B * U];
__device__ __align__(16) __half g_h1sa[B * U], g_h1sb[B * U];
__device__ __align__(16) float g_c0[B * U], g_c1[B * U], g_out[B * U];
__device__ int g_perm[B];        // permuted p -> original b
__device__ int g_plen[B];        // len of permuted row p (descending)
__device__ int g_cnt[T + 1];     // cnt[t] = #rows with len > t
__device__ int g_actA[NTILEA];   // precompute tile flags

__device__ __forceinline__ float sigmf(float x) { return 1.0f / (1.0f + expf(-x)); }

__device__ __forceinline__ void split2(float v, __half& h0, __half& h1)
{
    h0 = __float2half_rn(v);
    h1 = __float2half_rn(v - __half2float(h0));
}

__device__ __forceinline__ void cp16(uint32_t dst, const void* src) {
    asm volatile("cp.async.cg.shared.global [%0], [%1], 16;" :: "r"(dst), "l"(src));
}
__device__ __forceinline__ void cp_commit() { asm volatile("cp.async.commit_group;"); }
__device__ __forceinline__ void cp_wait0()  { asm volatile("cp.async.wait_group 0;"); }

#define MMA16(acc, a, b) \
    asm volatile( \
        "mma.sync.aligned.m16n8k16.row.col.f32.f16.f16.f32 " \
        "{%0,%1,%2,%3},{%4,%5,%6,%7},{%8,%9},{%0,%1,%2,%3};" \
        : "+f"((acc)[0]), "+f"((acc)[1]), "+f"((acc)[2]), "+f"((acc)[3]) \
        : "r"((a)[0]), "r"((a)[1]), "r"((a)[2]), "r"((a)[3]), \
          "r"((b)[0]), "r"((b)[1]))

#define LDSM4(r, addr) \
    asm volatile("ldmatrix.sync.aligned.m8n8.x4.shared.b16 {%0,%1,%2,%3}, [%4];" \
        : "=r"((r)[0]), "=r"((r)[1]), "=r"((r)[2]), "=r"((r)[3]) : "r"(addr))

// ---------------- fp16x3 HMMA GEMM --------------------------------------------------
// C[M,N] = A[M,K] @ Bt[N,K]^T, fp32 emulated as 2 fp16 terms, 3 pair-MMAs.
// cntp : scalar active-row bound (exit if m0 >= *cntp)     — loop GEMMs
// tilef: per-row-tile flags (exit if !tilef[ytile])        — precompute
// yoff : row-tile index offset (for chunked precompute launches)
struct ProbH { const __half *A0, *A1, *B0, *B1; float* C; };
struct GArgsH { ProbH p[2]; };

__global__ __launch_bounds__(128, 5) void gemm_f16x3(GArgsH ga, int N, int K,
                                                     const int* cntp, const int* tilef,
                                                     int yoff)
{
    const int ytile = blockIdx.y + yoff;
    const int m0 = ytile * TMC;
    if (cntp != nullptr && m0 >= *cntp) return;
    if (tilef != nullptr && tilef[ytile] == 0) return;

    extern __shared__ char smem[];
    const uint32_t sb0 = (uint32_t)__cvta_generic_to_shared(smem);

    const ProbH pr = ga.p[blockIdx.z];
    const int tid  = threadIdx.x;
    const int lane = tid & 31;
    const int wid  = tid >> 5;       // 0..3
    const int wm   = wid >> 1;       // 0..1  (32 rows each)
    const int wn   = wid & 1;        // 0..1  (32 cols each)
    const int n0   = blockIdx.x * TNC;
    const int grp  = lane >> 2;      // 0..7
    const int tg   = lane & 3;       // 0..3

    // per-lane ldmatrix offsets (x4 tile decomposition)
    const int lm = lane >> 3, lr = lane & 7;
    const uint32_t aoff = (uint32_t)((((lm & 1) * 8) + lr) * ROWB + (lm >> 1) * 16);
    const uint32_t boff = (uint32_t)((((lm >> 1) * 8) + lr) * ROWB + (lm & 1) * 16);

    // copy one BK=32 chunk: per term 64 rows x 4 granules(16B) = 256 slots,
    // 128 threads x 2 iterations.
    auto issue = [&](int stage, int k0) {
        const uint32_t sb = sb0 + (uint32_t)stage * STAGEB;
#pragma unroll
        for (int i = 0; i < 2; i++) {
            const int idx = tid + i * 128;        // 0..255
            const int r = idx >> 2, g = idx & 3;  // row, 16B granule
            const uint32_t doff = (uint32_t)(r * ROWB + g * 16);
            const size_t soffA = (size_t)(m0 + r) * K + k0 + g * 8;
            const size_t soffB = (size_t)(n0 + r) * K + k0 + g * 8;
            cp16(sb + 0 * TERMB + doff, pr.A0 + soffA);
            cp16(sb + 1 * TERMB + doff, pr.A1 + soffA);
            cp16(sb + 2 * TERMB + doff, pr.B0 + soffB);
            cp16(sb + 3 * TERMB + doff, pr.B1 + soffB);
        }
        cp_commit();
    };

    float acc[2][4][4];
#pragma unroll
    for (int i = 0; i < 2; i++)
#pragma unroll
        for (int j = 0; j < 4; j++)
#pragma unroll
            for (int k = 0; k < 4; k++) acc[i][j][k] = 0.f;

    const int NIT = K / BKC;
    issue(0, 0);

    for (int it = 0; it < NIT; ++it) {
        cp_wait0();
        __syncthreads();
        if (it + 1 < NIT) issue((it + 1) & 1, (it + 1) * BKC);

        const uint32_t sst = sb0 + (uint32_t)(it & 1) * STAGEB;
        const uint32_t aBase = sst + (uint32_t)((wm * 32) * ROWB) + aoff;
        const uint32_t bBase = sst + 2 * TERMB + (uint32_t)((wn * 32) * ROWB) + boff;

#pragma unroll
        for (int kk = 0; kk < 2; kk++) {
            uint32_t a0f[2][4], a1f[2][4], b0t[2][4], b1t[2][4];
#pragma unroll
            for (int im = 0; im < 2; im++) {
                const uint32_t ab = aBase + (uint32_t)(im * 16 * ROWB + kk * 32);
                LDSM4(a0f[im], ab);
                LDSM4(a1f[im], ab + TERMB);
            }
#pragma unroll
            for (int jp = 0; jp < 2; jp++) {
                const uint32_t bb = bBase + (uint32_t)(jp * 16 * ROWB + kk * 32);
                LDSM4(b0t[jp], bb);
                LDSM4(b1t[jp], bb + TERMB);
            }
#pragma unroll
            for (int im = 0; im < 2; im++)
#pragma unroll
                for (int jn = 0; jn < 4; jn++) {
                    const uint32_t* b0p = &b0t[jn >> 1][(jn & 1) * 2];
                    const uint32_t* b1p = &b1t[jn >> 1][(jn & 1) * 2];
                    MMA16(acc[im][jn], a1f[im], b0p);   // lo*hi
                    MMA16(acc[im][jn], a0f[im], b1p);   // hi*lo
                    MMA16(acc[im][jn], a0f[im], b0p);   // hi*hi
                }
        }
    }

    // epilogue
#pragma unroll
    for (int im = 0; im < 2; im++) {
        const int row0 = m0 + wm * 32 + im * 16 + grp;
#pragma unroll
        for (int jn = 0; jn < 4; jn++) {
            const int col = n0 + wn * 32 + jn * 8 + tg * 2;
            *(float2*)(pr.C + (size_t)row0 * N + col)       = make_float2(acc[im][jn][0], acc[im][jn][1]);
            *(float2*)(pr.C + (size_t)(row0 + 8) * N + col) = make_float2(acc[im][jn][2], acc[im][jn][3]);
        }
    }
}

// ---------------- one-time prep ------------------------------------------------------
__global__ void sort_kernel(const int* __restrict__ mask)
{
    __shared__ int len[B];
    const int b = threadIdx.x;
    int l = 0;
    for (int t = 0; t < T; t++) l += mask[b * T + t];
    len[b] = l;
    __syncthreads();
    int rank = 0;
    for (int j = 0; j < B; j++) {
        const int lj = len[j];
        rank += (lj > l) || (lj == l && j < b);
    }
    g_perm[rank] = b;
    g_plen[rank] = l;
}

__global__ void cnt_kernel()
{
    const int tid = threadIdx.x;   // 1024 threads
    if (tid <= T) {
        int c = 0;
        for (int p = 0; p < B; p++) c += (g_plen[p] > tid);
        g_cnt[tid] = c;
    }
    __syncthreads();
    for (int i = tid; i < NTILEA; i += 1024) {
        const int t  = i >> 4;            // B/TMC = 16 tiles per t
        const int pb = i & 15;
        g_actA[i] = (pb * TMC < g_cnt[t]) ? 1 : 0;
    }
}

__global__ void wsplit2_t(const float* __restrict__ W, __half* __restrict__ t0,
                          __half* __restrict__ t1, int Kd, int N, int Ksrc)
{
    const size_t i = (size_t)blockIdx.x * 256 + threadIdx.x;
    if (i < (size_t)N * Kd) {
        const int n = (int)(i / Kd), k = (int)(i % Kd);
        const float v = (k < Ksrc) ? W[(size_t)k * N + n] : 0.f;
        __half h0, h1;
        split2(v, h0, h1);
        t0[i] = h0; t1[i] = h1;
    }
}

__global__ void xsplit2(const float* __restrict__ x, __half* __restrict__ t0,
                        __half* __restrict__ t1)
{
    const size_t i = (size_t)blockIdx.x * 256 + threadIdx.x;
    if (i < (size_t)B * T * KP) {
        const size_t r = i / KP;       // flat [t*B + p]
        const int c = (int)(i % KP);
        const int t = (int)(r / B), p = (int)(r % B);
        const float v = (c < F) ? x[((size_t)g_perm[p] * T + t) * F + c] : 0.f;
        __half h0, h1;
        split2(v, h0, h1);
        t0[i] = h0; t1[i] = h1;
    }
}

__global__ void init_kernel()
{
    const size_t i = (size_t)blockIdx.x * 256 + threadIdx.x;
    if (i < (size_t)B * G) { g_z0[i] = 0.f; g_z1b[i] = 0.f; }
    if (i < (size_t)B * U) {
        const __half z = __float2half_rn(0.f);
        g_h0sa[i] = z; g_h0sb[i] = z;
        g_h1sa[i] = z; g_h1sb[i] = z;
        g_c0[i] = 0.f; g_c1[i] = 0.f; g_out[i] = 0.f;
    }
}

// ---------------- unified cell body ----------------------------------------------------
// Early-exits when row inactive (t >= plen[b]); surviving blocks write unconditionally.
__device__ void cell_body(int layer, int b, int t,
                          const float* __restrict__ za, const float* __restrict__ zb,
                          const float* __restrict__ gza, const float* __restrict__ bza,
                          const float* __restrict__ gzb, const float* __restrict__ bzb,
                          const float* __restrict__ sg,  const float* __restrict__ sb,
                          const float* __restrict__ bias)
{
    if (t >= g_plen[b]) return;   // uniform per block

    const int tid = threadIdx.x, lane = tid & 31, w = tid >> 5;
    __shared__ float sh1[4][8];
    __shared__ float bc1[4];

    float va[2][4], vb[2][4];
    float s1 = 0.f, p1 = 0.f, s2 = 0.f, p2 = 0.f;
#pragma unroll
    for (int q = 0; q < 2; q++) {
        const int u = tid + q * 256;
#pragma unroll
        for (int gg = 0; gg < 4; gg++) {
            const float x1 = za[gg * U + u];
            const float x2 = zb[gg * U + u];
            va[q][gg] = x1; vb[q][gg] = x2;
            s1 += x1; p1 += x1 * x1; s2 += x2; p2 += x2 * x2;
        }
    }
#pragma unroll
    for (int o = 16; o > 0; o >>= 1) {
        s1 += __shfl_xor_sync(0xffffffffu, s1, o);
        p1 += __shfl_xor_sync(0xffffffffu, p1, o);
        s2 += __shfl_xor_sync(0xffffffffu, s2, o);
        p2 += __shfl_xor_sync(0xffffffffu, p2, o);
    }
    if (lane == 0) { sh1[0][w] = s1; sh1[1][w] = p1; sh1[2][w] = s2; sh1[3][w] = p2; }
    __syncthreads();
    if (tid == 0) {
        float S1 = 0.f, P1 = 0.f, S2 = 0.f, P2 = 0.f;
#pragma unroll
        for (int i = 0; i < 8; i++) { S1 += sh1[0][i]; P1 += sh1[1][i]; S2 += sh1[2][i]; P2 += sh1[3][i]; }
        const float m1 = S1 / (float)G, m2 = S2 / (float)G;
        bc1[0] = m1; bc1[1] = rsqrtf(P1 / (float)G - m1 * m1 + EPS);
        bc1[2] = m2; bc1[3] = rsqrtf(P2 / (float)G - m2 * m2 + EPS);
    }
    __syncthreads();
    const float m1 = bc1[0], r1 = bc1[1], m2 = bc1[2], r2 = bc1[3];

    float* cold = (layer == 0) ? g_c0 : g_c1;
    float cn[2], zo[2];
    float s3 = 0.f, p3 = 0.f;
#pragma unroll
    for (int q = 0; q < 2; q++) {
        const int u = tid + q * 256;
        float zg4[4];
#pragma unroll
        for (int gg = 0; gg < 4; gg++) {
            const int j = gg * U + u;
            zg4[gg] = (va[q][gg] - m1) * r1 * gza[j] + bza[j]
                    + (vb[q][gg] - m2) * r2 * gzb[j] + bzb[j] + bias[j];
        }
        const float c = cold[(size_t)b * U + u];
        const float v = sigmf(zg4[1]) * c + sigmf(zg4[0]) * tanhf(zg4[2]);
        cn[q] = v; zo[q] = zg4[3]; s3 += v; p3 += v * v;
    }
#pragma unroll
    for (int o = 16; o > 0; o >>= 1) {
        s3 += __shfl_xor_sync(0xffffffffu, s3, o);
        p3 += __shfl_xor_sync(0xffffffffu, p3, o);
    }
    __syncthreads();
    if (lane == 0) { sh1[0][w] = s3; sh1[1][w] = p3; }
    __syncthreads();
    if (tid == 0) {
        float S = 0.f, P = 0.f;
#pragma unroll
        for (int i = 0; i < 8; i++) { S += sh1[0][i]; P += sh1[1][i]; }
        const float m = S / (float)U;
        bc1[0] = m;
        bc1[1] = rsqrtf(P / (float)U - m * m + EPS);
    }
    __syncthreads();
    const float mc = bc1[0], rc = bc1[1];
#pragma unroll
    for (int q = 0; q < 2; q++) {
        const int u = tid + q * 256;
        const float cl = (cn[q] - mc) * rc * sg[u] + sb[u];
        const float hn = sigmf(zo[q]) * tanhf(cl);
        __half h0, h1;
        split2(hn, h0, h1);
        if (layer == 0) {
            g_h0sa[(size_t)b * U + u] = h0;
            g_h0sb[(size_t)b * U + u] = h1;
            g_c0  [(size_t)b * U + u] = cl;
        } else {
            g_h1sa[(size_t)b * U + u] = h0;
            g_h1sb[(size_t)b * U + u] = h1;
            g_c1 [(size_t)b * U + u] = cl;
            g_out[(size_t)b * U + u] = hn;
        }
    }
}

__global__ __launch_bounds__(256) void cell0_kernel(
    const float* rg, const float* rb, const float* kg, const float* kb,
    const float* sg, const float* sb, const float* bias, int t)
{
    const int b = blockIdx.x;
    cell_body(0, b, t,
              g_z0 + (size_t)b * G,
              g_A0 + ((size_t)t * B + b) * G,
              rg, rb, kg, kb, sg, sb, bias);
}

__global__ __launch_bounds__(256) void cell1_kernel(
    const float* kg, const float* kb, const float* rg, const float* rb,
    const float* sg, const float* sb, const float* bias, int t)
{
    const int b = blockIdx.x;
    cell_body(1, b, t,
              g_z1b + (size_t)b * G,
              g_z1a[t & 1] + (size_t)b * G,
              rg, rb, kg, kb, sg, sb, bias);
}

// ---------------- dense + softmax (scatter through perm) ------------------------------
__global__ __launch_bounds__(256) void dense_kernel(const float* __restrict__ Wd,
                                                    const float* __restrict__ bd,
                                                    float* __restrict__ out)
{
    const int b = blockIdx.x, tid = threadIdx.x, lane = tid & 31, w = tid >> 5;
    float p[NC];
#pragma unroll
    for (int c = 0; c < NC; c++) p[c] = 0.f;
    for (int u = tid; u < U; u += 256) {
        const float h = g_out[(size_t)b * U + u];
#pragma unroll
        for (int c = 0; c < NC; c++) p[c] += h * Wd[u * NC + c];
    }
    __shared__ float sh[NC][8];
#pragma unroll
    for (int c = 0; c < NC; c++) {
        float v = p[c];
#pragma unroll
        for (int o = 16; o > 0; o >>= 1) v += __shfl_xor_sync(0xffffffffu, v, o);
        if (lane == 0) sh[c][w] = v;
    }
    __syncthreads();
    if (tid == 0) {
        const int ob = g_perm[b];
        float lg[NC];
        float mx = -1e30f;
#pragma unroll
        for (int c = 0; c < NC; c++) {
            float l = bd[c];
#pragma unroll
            for (int i = 0; i < 8; i++) l += sh[c][i];
            lg[c] = l;
            mx = fmaxf(mx, l);
        }
        float sum = 0.f;
#pragma unroll
        for (int c = 0; c < NC; c++) { lg[c] = expf(lg[c] - mx); sum += lg[c]; }
        const float inv = 1.f / sum;
#pragma unroll
        for (int c = 0; c < NC; c++) out[ob * NC + c] = lg[c] * inv;
    }
}

// ---------------- launch ---------------------------------------------------------------
extern "C" void kernel_launch(void* const* d_in, const int* in_sizes, int n_in,
                              void* d_out, int out_size)
{
    const float* x    = (const float*)d_in[0];
    const int*   mask = (const int*)  d_in[1];
    const float* W0   = (const float*)d_in[2];
    const float* R0   = (const float*)d_in[3];
    const float* b0   = (const float*)d_in[4];
    const float* kg0  = (const float*)d_in[5];
    const float* kb0  = (const float*)d_in[6];
    const float* rg0  = (const float*)d_in[7];
    const float* rb0  = (const float*)d_in[8];
    const float* sg0  = (const float*)d_in[9];
    const float* sb0  = (const float*)d_in[10];
    const float* W1   = (const float*)d_in[11];
    const float* R1   = (const float*)d_in[12];
    const float* b1   = (const float*)d_in[13];
    const float* kg1  = (const float*)d_in[14];
    const float* kb1  = (const float*)d_in[15];
    const float* rg1  = (const float*)d_in[16];
    const float* rb1  = (const float*)d_in[17];
    const float* sg1  = (const float*)d_in[18];
    const float* sb1  = (const float*)d_in[19];
    const float* Wd   = (const float*)d_in[20];
    const float* bd   = (const float*)d_in[21];
    float* out = (float*)d_out;

    float *A0p, *z0p, *z1ap, *z1bp;
    __half *x0, *x1, *W0a, *W0b, *R0a, *R0b, *W1a, *W1b, *R1a, *R1b;
    __half *h0sa, *h0sb, *h1sa, *h1sb;
    int *cntp, *actAp;
    cudaGetSymbolAddress((void**)&A0p,  g_A0);
    cudaGetSymbolAddress((void**)&z0p,  g_z0);
    cudaGetSymbolAddress((void**)&z1ap, g_z1a);
    cudaGetSymbolAddress((void**)&z1bp, g_z1b);
    cudaGetSymbolAddress((void**)&x0,   g_x0);
    cudaGetSymbolAddress((void**)&x1,   g_x1);
    cudaGetSymbolAddress((void**)&W0a,  g_W0a);
    cudaGetSymbolAddress((void**)&W0b,  g_W0b);
    cudaGetSymbolAddress((void**)&R0a,  g_R0a);
    cudaGetSymbolAddress((void**)&R0b,  g_R0b);
    cudaGetSymbolAddress((void**)&W1a,  g_W1a);
    cudaGetSymbolAddress((void**)&W1b,  g_W1b);
    cudaGetSymbolAddress((void**)&R1a,  g_R1a);
    cudaGetSymbolAddress((void**)&R1b,  g_R1b);
    cudaGetSymbolAddress((void**)&h0sa, g_h0sa);
    cudaGetSymbolAddress((void**)&h0sb, g_h0sb);
    cudaGetSymbolAddress((void**)&h1sa, g_h1sa);
    cudaGetSymbolAddress((void**)&h1sb, g_h1sb);
    cudaGetSymbolAddress((void**)&cntp, g_cnt);
    cudaGetSymbolAddress((void**)&actAp, g_actA);

    cudaFuncSetAttribute(gemm_f16x3, cudaFuncAttributeMaxDynamicSharedMemorySize, SMEM_H);

    // lazy-init streams + events (handles only; no device memory)
    static cudaStream_t s2 = nullptr, s3 = nullptr;
    static cudaEvent_t evFork = nullptr;
    static cudaEvent_t evChunk[NCHUNK];
    static cudaEvent_t evA[T];      // after gemmA2(t): z1a(t), z0(t+1) ready
    static cudaEvent_t evC1[T];     // after cell1(t)
    if (s2 == nullptr) {
        cudaStreamCreateWithFlags(&s2, cudaStreamNonBlocking);
        cudaStreamCreateWithFlags(&s3, cudaStreamNonBlocking);
        cudaEventCreateWithFlags(&evFork, cudaEventDisableTiming);
        for (int k = 0; k < NCHUNK; k++)
            cudaEventCreateWithFlags(&evChunk[k], cudaEventDisableTiming);
        for (int t = 0; t < T; t++) {
            cudaEventCreateWithFlags(&evA[t], cudaEventDisableTiming);
            cudaEventCreateWithFlags(&evC1[t], cudaEventDisableTiming);
        }
    }

    // one-time prep (main stream s1)
    const size_t nW0 = (size_t)G * KP;
    const size_t nRW = (size_t)G * U;
    const size_t nXT = (size_t)B * T * KP;
    init_kernel<<<(B * G + 255) / 256, 256>>>();
    sort_kernel<<<1, B>>>(mask);
    cnt_kernel<<<1, 1024>>>();
    wsplit2_t<<<(unsigned)((nW0 + 255) / 256), 256>>>(W0, W0a, W0b, KP, G, F);
    xsplit2<<<(unsigned)((nXT + 255) / 256), 256>>>(x, x0, x1);

    // fork: precompute A0 chunks on s3
    cudaEventRecord(evFork, 0);
    cudaStreamWaitEvent(s3, evFork, 0);
    for (int k = 0; k < NCHUNK; k++) {
        GArgsH a = {};
        a.p[0] = { x0, x1, W0a, W0b, A0p };
        gemm_f16x3<<<dim3(G / TNC, CH_TILES, 1), 128, SMEM_H, s3>>>(
            a, G, KP, nullptr, actAp, k * CH_TILES);
        cudaEventRecord(evChunk[k], s3);
    }

    // remaining weight splits on main stream
    wsplit2_t<<<(unsigned)((nRW + 255) / 256), 256>>>(R0, R0a, R0b, U, G, U);
    wsplit2_t<<<(unsigned)((nRW + 255) / 256), 256>>>(W1, W1a, W1b, U, G, U);
    wsplit2_t<<<(unsigned)((nRW + 255) / 256), 256>>>(R1, R1a, R1b, U, G, U);

    // t = 0 prolog on s1 (z0(0) == 0; z1b(0) == 0 since h1s(0)==0)
    cudaStreamWaitEvent(0, evChunk[0], 0);
    cell0_kernel<<<B, 256>>>(rg0, rb0, kg0, kb0, sg0, sb0, b0, 0);

    for (int t = 0; t < T; t++) {
        // --- s1 critical chain: gemmA2(t) = {z1a(t), z0(t+1)} after cell0(t) ---
        if (t >= 2) cudaStreamWaitEvent(0, evC1[t - 2], 0);   // WAR on z1a[t&1]
        {
            GArgsH aargs = {};
            aargs.p[0] = { h0sa, h0sb, W1a, W1b, (float*)((char*)z1ap + (size_t)(t & 1) * B * G * 4) };
            aargs.p[1] = { h0sa, h0sb, R0a, R0b, z0p };
            gemm_f16x3<<<dim3(G / TNC, B / TMC, 2), 128, SMEM_H>>>(
                aargs, G, U, cntp + t, nullptr, 0);
        }
        cudaEventRecord(evA[t], 0);

        if (t + 1 < T) {
            if ((t + 1) % (T / NCHUNK) == 0)
                cudaStreamWaitEvent(0, evChunk[(t + 1) / (T / NCHUNK)], 0);
            cell0_kernel<<<B, 256>>>(rg0, rb0, kg0, kb0, sg0, sb0, b0, t + 1);
        }

        // --- s2 slack chain: cell1(t) after z1a(t); then z1b(t+1) ---
        cudaStreamWaitEvent(s2, evA[t], 0);
        cell1_kernel<<<B, 256, 0, s2>>>(kg1, kb1, rg1, rb1, sg1, sb1, b1, t);
        cudaEventRecord(evC1[t], s2);
        if (t + 1 < T) {
            GArgsH bargs = {};
            bargs.p[0] = { h1sa, h1sb, R1a, R1b, z1bp };
            gemm_f16x3<<<dim3(G / TNC, B / TMC, 1), 128, SMEM_H, s2>>>(
                bargs, G, U, cntp + (t + 1), nullptr, 0);
        }
    }

    // dense on s1 after final cell1
    cudaStreamWaitEvent(0, evC1[T - 1], 0);
    dense_kernel<<<B, 256>>>(Wd, bd, out);
}